// round 7
// baseline (speedup 1.0000x reference)
#include <cuda_runtime.h>
#include <cuda_bf16.h>
#include <cstdint>

// Problem constants
#define B_  2
#define S_  2048
#define D_  1024
#define H_  16
#define DH_ 64
#define BS_ (B_ * S_)        // 4096
#define N3D_ (3 * D_)        // 3072

// ---------------------------------------------------------------------------
// Scratch (allocation-free: __device__ globals)
// ---------------------------------------------------------------------------
__device__ __align__(128) __nv_bfloat16 g_Qhi[B_ * H_ * S_ * DH_]; // scaled 0.125
__device__ __align__(128) __nv_bfloat16 g_Qlo[B_ * H_ * S_ * DH_];
__device__ __align__(128) __nv_bfloat16 g_Khi[B_ * H_ * S_ * DH_];
__device__ __align__(128) __nv_bfloat16 g_Klo[B_ * H_ * S_ * DH_];
__device__ __align__(128) __nv_bfloat16 g_Vhi[B_ * H_ * S_ * DH_];
__device__ __align__(128) __nv_bfloat16 g_Vlo[B_ * H_ * S_ * DH_];

__device__ __align__(128) __nv_bfloat16 g_xhi[BS_ * D_];
__device__ __align__(128) __nv_bfloat16 g_xlo[BS_ * D_];
__device__ __align__(128) __nv_bfloat16 g_WqT_hi[N3D_ * D_];
__device__ __align__(128) __nv_bfloat16 g_WqT_lo[N3D_ * D_];
__device__ __align__(128) __nv_bfloat16 g_WpT_hi[D_ * D_];
__device__ __align__(128) __nv_bfloat16 g_WpT_lo[D_ * D_];
__device__ __align__(128) __nv_bfloat16 g_Ohi[BS_ * D_];
__device__ __align__(128) __nv_bfloat16 g_Olo[BS_ * D_];

// ---------------------------------------------------------------------------
// Base-ISA helpers
// ---------------------------------------------------------------------------
__device__ __forceinline__ uint32_t smem_u32(const void* p) {
    uint32_t a;
    asm("{ .reg .u64 t; cvta.to.shared.u64 t, %1; cvt.u32.u64 %0, t; }"
        : "=r"(a) : "l"(p));
    return a;
}
__device__ __forceinline__ uint32_t swz(uint32_t b) { return b ^ ((b >> 3) & 0x70); }

__device__ __forceinline__ void ldm4(uint32_t& r0, uint32_t& r1, uint32_t& r2,
                                     uint32_t& r3, uint32_t a) {
    asm volatile("ldmatrix.sync.aligned.m8n8.x4.shared.b16 {%0,%1,%2,%3},[%4];"
                 : "=r"(r0), "=r"(r1), "=r"(r2), "=r"(r3) : "r"(a));
}
__device__ __forceinline__ void ldm4t(uint32_t& r0, uint32_t& r1, uint32_t& r2,
                                      uint32_t& r3, uint32_t a) {
    asm volatile("ldmatrix.sync.aligned.m8n8.x4.trans.shared.b16 {%0,%1,%2,%3},[%4];"
                 : "=r"(r0), "=r"(r1), "=r"(r2), "=r"(r3) : "r"(a));
}
__device__ __forceinline__ void mma16816(float* d, const uint32_t* a,
                                         const uint32_t* b) {
    asm volatile(
        "mma.sync.aligned.m16n8k16.row.col.f32.bf16.bf16.f32 "
        "{%0,%1,%2,%3},{%4,%5,%6,%7},{%8,%9},{%0,%1,%2,%3};"
        : "+f"(d[0]), "+f"(d[1]), "+f"(d[2]), "+f"(d[3])
        : "r"(a[0]), "r"(a[1]), "r"(a[2]), "r"(a[3]), "r"(b[0]), "r"(b[1]));
}
__device__ __forceinline__ void cp16(uint32_t dst, const void* src) {
    asm volatile("cp.async.cg.shared.global [%0],[%1],16;" :: "r"(dst), "l"(src));
}
#define CP_COMMIT() asm volatile("cp.async.commit_group;")

__device__ __forceinline__ void split2(float a, float b, uint32_t& hi, uint32_t& lo) {
    __nv_bfloat162 h = __floats2bfloat162_rn(a, b);
    hi = *(uint32_t*)&h;
    __nv_bfloat162 l = __floats2bfloat162_rn(a - __bfloat162float(h.x),
                                             b - __bfloat162float(h.y));
    lo = *(uint32_t*)&l;
}

// ---------------------------------------------------------------------------
// Prep
// ---------------------------------------------------------------------------
__global__ void split_kernel(const float* __restrict__ x, int n)
{
    for (int i = blockIdx.x * blockDim.x + threadIdx.x; i < n;
         i += gridDim.x * blockDim.x) {
        float f = x[i];
        __nv_bfloat16 h = __float2bfloat16(f);
        g_xhi[i] = h;
        g_xlo[i] = __float2bfloat16(f - __bfloat162float(h));
    }
}

template <int MODE>  // 0: W_qkv, 1: W_proj
__global__ void tsplit_kernel(const float* __restrict__ W, int K, int N)
{
    __nv_bfloat16* hi = (MODE == 0) ? g_WqT_hi : g_WpT_hi;
    __nv_bfloat16* lo = (MODE == 0) ? g_WqT_lo : g_WpT_lo;
    __shared__ float t[32][33];
    int n0 = blockIdx.x * 32, k0 = blockIdx.y * 32;
    int tx = threadIdx.x, ty = threadIdx.y;
#pragma unroll
    for (int r = 0; r < 32; r += 8)
        t[ty + r][tx] = W[(size_t)(k0 + ty + r) * N + n0 + tx];
    __syncthreads();
#pragma unroll
    for (int r = 0; r < 32; r += 8) {
        float f = t[tx][ty + r];
        __nv_bfloat16 h = __float2bfloat16(f);
        size_t o = (size_t)(n0 + ty + r) * K + k0 + tx;
        hi[o] = h;
        lo[o] = __float2bfloat16(f - __bfloat162float(h));
    }
}

// ---------------------------------------------------------------------------
// mma.sync bf16 hi/lo GEMM. 128x128 CTA tile, 8 warps (2x4), 64x32 warp tile,
// K-chunk 64, 3-stage cp.async pipeline, ONE sync/iter, frag pipeline,
// PASS-OUTER MMA ordering (independent accumulator chains of 16).
// ---------------------------------------------------------------------------
#define BKC 64
#define ARR_BYTES (128 * BKC * 2)
#define STAGE_BYTES (4 * ARR_BYTES)          // 65536
#define GEMM_DSMEM (3 * STAGE_BYTES)         // 196608

__device__ __forceinline__ void cp_tile(uint32_t sdst,
                                        const __nv_bfloat16* __restrict__ g,
                                        int row0, int k0, int tid)
{
#pragma unroll
    for (int it = 0; it < 4; it++) {
        int idx = tid + it * 256;
        int row = idx >> 3;
        int c   = idx & 7;
        cp16(sdst + swz(row * 128 + c * 16),
             g + (size_t)(row0 + row) * 1024 + k0 + c * 8);
    }
}

struct GFrags {
    uint32_t ahi[4][4], alo[4][4];
    uint32_t bhi[4][2], blo[4][2];
};

__device__ __forceinline__ void gload_frags(
    GFrags& f, uint32_t sAhi, uint32_t sAlo, uint32_t sBhi, uint32_t sBlo,
    int ks, int wm, int wn, int a_row, int a_kb, int b_row, int b_kb)
{
#pragma unroll
    for (int i = 0; i < 4; i++) {
        uint32_t off = swz((wm * 64 + i * 16 + a_row) * 128 + ks * 32 + a_kb);
        ldm4(f.ahi[i][0], f.ahi[i][1], f.ahi[i][2], f.ahi[i][3], sAhi + off);
        ldm4(f.alo[i][0], f.alo[i][1], f.alo[i][2], f.alo[i][3], sAlo + off);
    }
#pragma unroll
    for (int p = 0; p < 2; p++) {
        uint32_t off = swz((wn * 32 + p * 16 + b_row) * 128 + ks * 32 + b_kb);
        ldm4(f.bhi[2 * p][0], f.bhi[2 * p][1], f.bhi[2 * p + 1][0],
             f.bhi[2 * p + 1][1], sBhi + off);
        ldm4(f.blo[2 * p][0], f.blo[2 * p][1], f.blo[2 * p + 1][0],
             f.blo[2 * p + 1][1], sBlo + off);
    }
}

template <int MODE>
__global__ void __launch_bounds__(256) gemm_mma_kernel(
    const float* __restrict__ bias, float* __restrict__ Cout)
{
    constexpr int N = (MODE == 0) ? N3D_ : D_;
    constexpr int nkc = D_ / BKC;   // 16
    extern __shared__ char dsm[];
    const uint32_t sb0 = smem_u32(dsm);

    const int tid = threadIdx.x;
    const int wid = tid >> 5;
    const int lid = tid & 31;
    const int wm = wid >> 2;        // 0..1
    const int wn = wid & 3;         // 0..3
    const int m0 = blockIdx.y * 128;
    const int n0 = blockIdx.x * 128;

    const __nv_bfloat16* Ahi = (MODE == 0) ? g_xhi : g_Ohi;
    const __nv_bfloat16* Alo = (MODE == 0) ? g_xlo : g_Olo;
    const __nv_bfloat16* Bhi = (MODE == 0) ? g_WqT_hi : g_WpT_hi;
    const __nv_bfloat16* Blo = (MODE == 0) ? g_WqT_lo : g_WpT_lo;

    const int a_row = (lid & 7) + ((lid >> 3) & 1) * 8;
    const int a_kb  = (lid >> 4) * 16;
    const int b_row = (lid & 7) + ((lid >> 4) & 1) * 8;
    const int b_kb  = ((lid >> 3) & 1) * 16;

    float acc[4][4][4];
#pragma unroll
    for (int i = 0; i < 4; i++)
#pragma unroll
        for (int j = 0; j < 4; j++)
#pragma unroll
            for (int r = 0; r < 4; r++) acc[i][j][r] = 0.f;

    // prologue: stages 0,1
#pragma unroll
    for (int s = 0; s < 2; s++) {
        uint32_t sb = sb0 + s * STAGE_BYTES;
        cp_tile(sb + 0 * ARR_BYTES, Ahi, m0, s * BKC, tid);
        cp_tile(sb + 1 * ARR_BYTES, Alo, m0, s * BKC, tid);
        cp_tile(sb + 2 * ARR_BYTES, Bhi, n0, s * BKC, tid);
        cp_tile(sb + 3 * ARR_BYTES, Blo, n0, s * BKC, tid);
        CP_COMMIT();
    }

    GFrags fr[2];
    int bufc = 0;   // kc % 3
    int bufp = 2;   // (kc+2) % 3

    for (int kc = 0; kc < nkc; kc++) {
        if (kc + 1 < nkc) { asm volatile("cp.async.wait_group 1;"); }
        else              { asm volatile("cp.async.wait_group 0;"); }
        __syncthreads();

        if (kc + 2 < nkc) {
            uint32_t sb = sb0 + bufp * STAGE_BYTES;
            const int k0 = (kc + 2) * BKC;
            cp_tile(sb + 0 * ARR_BYTES, Ahi, m0, k0, tid);
            cp_tile(sb + 1 * ARR_BYTES, Alo, m0, k0, tid);
            cp_tile(sb + 2 * ARR_BYTES, Bhi, n0, k0, tid);
            cp_tile(sb + 3 * ARR_BYTES, Blo, n0, k0, tid);
            CP_COMMIT();
        }

        const uint32_t sb = sb0 + bufc * STAGE_BYTES;
        const uint32_t sAhi = sb + 0 * ARR_BYTES;
        const uint32_t sAlo = sb + 1 * ARR_BYTES;
        const uint32_t sBhi = sb + 2 * ARR_BYTES;
        const uint32_t sBlo = sb + 3 * ARR_BYTES;

        gload_frags(fr[0], sAhi, sAlo, sBhi, sBlo, 0, wm, wn, a_row, a_kb, b_row, b_kb);
#pragma unroll
        for (int ks = 0; ks < 4; ks++) {
            const int cur = ks & 1;
            if (ks < 3)
                gload_frags(fr[cur ^ 1], sAhi, sAlo, sBhi, sBlo, ks + 1,
                            wm, wn, a_row, a_kb, b_row, b_kb);
            GFrags& f = fr[cur];
            // pass-outer: 16 independent accumulators per pass
#pragma unroll
            for (int i = 0; i < 4; i++)
#pragma unroll
                for (int j = 0; j < 4; j++)
                    mma16816(acc[i][j], f.ahi[i], f.bhi[j]);
#pragma unroll
            for (int i = 0; i < 4; i++)
#pragma unroll
                for (int j = 0; j < 4; j++)
                    mma16816(acc[i][j], f.ahi[i], f.blo[j]);
#pragma unroll
            for (int i = 0; i < 4; i++)
#pragma unroll
                for (int j = 0; j < 4; j++)
                    mma16816(acc[i][j], f.alo[i], f.bhi[j]);
        }
        bufc = (bufc == 2) ? 0 : bufc + 1;
        bufp = (bufp == 2) ? 0 : bufp + 1;
    }

#pragma unroll
    for (int i = 0; i < 4; i++) {
#pragma unroll
        for (int j = 0; j < 4; j++) {
            const int n = n0 + wn * 32 + j * 8 + (lid & 3) * 2;
            const float b0 = __ldg(&bias[n]);
            const float b1 = __ldg(&bias[n + 1]);
#pragma unroll
            for (int rr = 0; rr < 2; rr++) {
                const int m = m0 + wm * 64 + i * 16 + (lid >> 2) + rr * 8;
                float v0 = acc[i][j][rr * 2 + 0] + b0;
                float v1 = acc[i][j][rr * 2 + 1] + b1;
                if constexpr (MODE == 0) {
                    const int b = m >> 11, s = m & 2047;
                    const int rem = n & 1023, h = rem >> 6, d = rem & 63;
                    const size_t o = (((size_t)(b * H_ + h) << 11) + s) * DH_ + d;
                    const int which = n0 >> 10;
                    if (which == 0) { v0 *= 0.125f; v1 *= 0.125f; }
                    uint32_t hp, lp;
                    split2(v0, v1, hp, lp);
                    if (which == 0) {
                        *(uint32_t*)(g_Qhi + o) = hp; *(uint32_t*)(g_Qlo + o) = lp;
                    } else if (which == 1) {
                        *(uint32_t*)(g_Khi + o) = hp; *(uint32_t*)(g_Klo + o) = lp;
                    } else {
                        *(uint32_t*)(g_Vhi + o) = hp; *(uint32_t*)(g_Vlo + o) = lp;
                    }
                } else {
                    *(float2*)(Cout + (size_t)m * N + n) = make_float2(v0, v1);
                }
            }
        }
    }
}

// ---------------------------------------------------------------------------
// Flash attention, mma.sync bf16 hi/lo, causal.
// BM=128, BN=64, 8 warps * 16 rows, 3-stage pipeline, ONE sync per tile,
// PASS-OUTER MMA ordering, heavy-first q-tile scheduling.
// ---------------------------------------------------------------------------
#define FBM 128
#define FBN 64
#define FK_BYTES (FBN * 128)            // 8192
#define FSTAGE   (4 * FK_BYTES)          // 32768
#define FLASH_DSMEM (3 * FSTAGE)         // 98304

__device__ __forceinline__ void cp_ftile(uint32_t sdst,
                                         const __nv_bfloat16* __restrict__ g,
                                         int tid)
{
#pragma unroll
    for (int it = 0; it < 2; it++) {
        int idx = tid + it * 256;
        int row = idx >> 3;
        int c   = idx & 7;
        cp16(sdst + swz(row * 128 + c * 16), g + (size_t)row * 64 + c * 8);
    }
}

__global__ void __launch_bounds__(256) flash_mma_kernel()
{
    extern __shared__ char fsm[];
    const uint32_t sStage = smem_u32(fsm);

    const int tid = threadIdx.x;
    const int wid = tid >> 5;
    const int lid = tid & 31;
    const int qt = gridDim.x - 1 - blockIdx.x;   // heavy tiles first
    const int bh = blockIdx.y;
    const int q0 = qt * FBM;
    const int nkt = 2 * qt + 2;

    const __nv_bfloat16* Qhig = g_Qhi + ((size_t)bh * S_ + q0) * DH_;
    const __nv_bfloat16* Qlog = g_Qlo + ((size_t)bh * S_ + q0) * DH_;
    const __nv_bfloat16* Khig = g_Khi + (size_t)bh * S_ * DH_;
    const __nv_bfloat16* Klog = g_Klo + (size_t)bh * S_ * DH_;
    const __nv_bfloat16* Vhig = g_Vhi + (size_t)bh * S_ * DH_;
    const __nv_bfloat16* Vlog = g_Vlo + (size_t)bh * S_ * DH_;

    // ---- stage Q through stage-0 buffer: hi at +0, lo at +16KB ----
#pragma unroll
    for (int it = 0; it < 4; it++) {
        int idx = tid + it * 256;
        int row = idx >> 3;
        int c   = idx & 7;
        cp16(sStage + swz(row * 128 + c * 16),         Qhig + (size_t)row * 64 + c * 8);
        cp16(sStage + 16384 + swz(row * 128 + c * 16), Qlog + (size_t)row * 64 + c * 8);
    }
    CP_COMMIT();
    asm volatile("cp.async.wait_group 0;");
    __syncthreads();

    const int a_row = (lid & 7) + ((lid >> 3) & 1) * 8;
    const int a_kb  = (lid >> 4) * 16;
    uint32_t qhi[4][4], qlo[4][4];
#pragma unroll
    for (int ks = 0; ks < 4; ks++) {
        uint32_t off = swz((wid * 16 + a_row) * 128 + ks * 32 + a_kb);
        ldm4(qhi[ks][0], qhi[ks][1], qhi[ks][2], qhi[ks][3], sStage + off);
        ldm4(qlo[ks][0], qlo[ks][1], qlo[ks][2], qlo[ks][3], sStage + 16384 + off);
    }
    __syncthreads();   // frags extracted; buffers reusable for K/V

    // prefetch kt=0 -> buf0, kt=1 -> buf1
#pragma unroll
    for (int s = 0; s < 2; s++) {
        uint32_t sb = sStage + s * FSTAGE;
        const size_t koff = (size_t)s * FBN * DH_;
        cp_ftile(sb + 0 * FK_BYTES, Khig + koff, tid);
        cp_ftile(sb + 1 * FK_BYTES, Klog + koff, tid);
        cp_ftile(sb + 2 * FK_BYTES, Vhig + koff, tid);
        cp_ftile(sb + 3 * FK_BYTES, Vlog + koff, tid);
        CP_COMMIT();
    }

    const int b_row = (lid & 7) + ((lid >> 4) & 1) * 8;
    const int b_kb  = ((lid >> 3) & 1) * 16;
    const int v_row = (lid & 7) + ((lid >> 3) & 1) * 8;
    const int v_cb  = ((lid >> 4) & 1) * 16;

    float m_i[2] = {-1e30f, -1e30f};
    float l_i[2] = {0.f, 0.f};
    float out[8][4];
#pragma unroll
    for (int nn = 0; nn < 8; nn++)
#pragma unroll
        for (int r = 0; r < 4; r++) out[nn][r] = 0.f;

    int bufc = 0;   // kt % 3
    int bufp = 2;   // (kt+2) % 3
    for (int kt = 0; kt < nkt; kt++) {
        if (kt + 1 < nkt) { asm volatile("cp.async.wait_group 1;"); }
        else              { asm volatile("cp.async.wait_group 0;"); }
        __syncthreads();

        if (kt + 2 < nkt) {
            uint32_t sb2 = sStage + bufp * FSTAGE;
            const size_t koff = (size_t)(kt + 2) * FBN * DH_;
            cp_ftile(sb2 + 0 * FK_BYTES, Khig + koff, tid);
            cp_ftile(sb2 + 1 * FK_BYTES, Klog + koff, tid);
            cp_ftile(sb2 + 2 * FK_BYTES, Vhig + koff, tid);
            cp_ftile(sb2 + 3 * FK_BYTES, Vlog + koff, tid);
            CP_COMMIT();
        }

        const uint32_t sb = sStage + bufc * FSTAGE;
        const uint32_t sKhi = sb + 0 * FK_BYTES;
        const uint32_t sKlo = sb + 1 * FK_BYTES;
        const uint32_t sVhi = sb + 2 * FK_BYTES;
        const uint32_t sVlo = sb + 3 * FK_BYTES;

        float sc[8][4];
#pragma unroll
        for (int j = 0; j < 8; j++)
#pragma unroll
            for (int r = 0; r < 4; r++) sc[j][r] = 0.f;

        // QK^T: per ks, load all K frags, then pass-outer over 8 accumulators
#pragma unroll
        for (int ks = 0; ks < 4; ks++) {
            uint32_t kh[4][4], kl[4][4];
#pragma unroll
            for (int jp = 0; jp < 4; jp++) {
                uint32_t off = swz((jp * 16 + b_row) * 128 + ks * 32 + b_kb);
                ldm4(kh[jp][0], kh[jp][1], kh[jp][2], kh[jp][3], sKhi + off);
                ldm4(kl[jp][0], kl[jp][1], kl[jp][2], kl[jp][3], sKlo + off);
            }
#pragma unroll
            for (int jp = 0; jp < 4; jp++) {
                mma16816(sc[2 * jp],     qhi[ks], &kh[jp][0]);
                mma16816(sc[2 * jp + 1], qhi[ks], &kh[jp][2]);
            }
#pragma unroll
            for (int jp = 0; jp < 4; jp++) {
                mma16816(sc[2 * jp],     qhi[ks], &kl[jp][0]);
                mma16816(sc[2 * jp + 1], qhi[ks], &kl[jp][2]);
            }
#pragma unroll
            for (int jp = 0; jp < 4; jp++) {
                mma16816(sc[2 * jp],     qlo[ks], &kh[jp][0]);
                mma16816(sc[2 * jp + 1], qlo[ks], &kh[jp][2]);
            }
        }

        if (kt >= nkt - 2) {
            const int k0g = kt * FBN;
            const int rbase = q0 + wid * 16 + (lid >> 2);
#pragma unroll
            for (int j = 0; j < 8; j++) {
                const int cbase = k0g + j * 8 + 2 * (lid & 3);
#pragma unroll
                for (int rr = 0; rr < 2; rr++) {
                    const int row = rbase + rr * 8;
                    if (cbase > row)     sc[j][2 * rr]     = -1e30f;
                    if (cbase + 1 > row) sc[j][2 * rr + 1] = -1e30f;
                }
            }
        }

        float alpha[2];
#pragma unroll
        for (int rr = 0; rr < 2; rr++) {
            float tm = -1e30f;
#pragma unroll
            for (int j = 0; j < 8; j++)
                tm = fmaxf(tm, fmaxf(sc[j][2 * rr], sc[j][2 * rr + 1]));
            tm = fmaxf(tm, __shfl_xor_sync(0xffffffffu, tm, 1));
            tm = fmaxf(tm, __shfl_xor_sync(0xffffffffu, tm, 2));
            const float mn = fmaxf(m_i[rr], tm);
            alpha[rr] = __expf(m_i[rr] - mn);
            m_i[rr] = mn;
            float rs = 0.f;
#pragma unroll
            for (int j = 0; j < 8; j++) {
                float p0 = __expf(sc[j][2 * rr]     - mn);
                float p1 = __expf(sc[j][2 * rr + 1] - mn);
                sc[j][2 * rr] = p0; sc[j][2 * rr + 1] = p1;
                rs += p0 + p1;
            }
            rs += __shfl_xor_sync(0xffffffffu, rs, 1);
            rs += __shfl_xor_sync(0xffffffffu, rs, 2);
            l_i[rr] = l_i[rr] * alpha[rr] + rs;
        }
#pragma unroll
        for (int nn = 0; nn < 8; nn++) {
            out[nn][0] *= alpha[0]; out[nn][1] *= alpha[0];
            out[nn][2] *= alpha[1]; out[nn][3] *= alpha[1];
        }

        // PV: per kk, load all V frags, then pass-outer over 8 accumulators
#pragma unroll
        for (int kk = 0; kk < 4; kk++) {
            uint32_t phi[4], plo[4];
            split2(sc[2 * kk][0],     sc[2 * kk][1],     phi[0], plo[0]);
            split2(sc[2 * kk][2],     sc[2 * kk][3],     phi[1], plo[1]);
            split2(sc[2 * kk + 1][0], sc[2 * kk + 1][1], phi[2], plo[2]);
            split2(sc[2 * kk + 1][2], sc[2 * kk + 1][3], phi[3], plo[3]);
            uint32_t vh[4][4], vl[4][4];
#pragma unroll
            for (int np = 0; np < 4; np++) {
                uint32_t off = swz((kk * 16 + v_row) * 128 + np * 32 + v_cb);
                ldm4t(vh[np][0], vh[np][1], vh[np][2], vh[np][3], sVhi + off);
                ldm4t(vl[np][0], vl[np][1], vl[np][2], vl[np][3], sVlo + off);
            }
#pragma unroll
            for (int np = 0; np < 4; np++) {
                mma16816(out[2 * np],     phi, &vh[np][0]);
                mma16816(out[2 * np + 1], phi, &vh[np][2]);
            }
#pragma unroll
            for (int np = 0; np < 4; np++) {
                mma16816(out[2 * np],     phi, &vl[np][0]);
                mma16816(out[2 * np + 1], phi, &vl[np][2]);
            }
#pragma unroll
            for (int np = 0; np < 4; np++) {
                mma16816(out[2 * np],     plo, &vh[np][0]);
                mma16816(out[2 * np + 1], plo, &vh[np][2]);
            }
        }

        bufc = (bufc == 2) ? 0 : bufc + 1;
        bufp = (bufp == 2) ? 0 : bufp + 1;
    }

    const int b = bh >> 4;
    const int h = bh & 15;
    const float inv0 = 1.0f / l_i[0];
    const float inv1 = 1.0f / l_i[1];
#pragma unroll
    for (int nn = 0; nn < 8; nn++) {
        const int col = h * 64 + nn * 8 + 2 * (lid & 3);
#pragma unroll
        for (int rr = 0; rr < 2; rr++) {
            const int row = q0 + wid * 16 + (lid >> 2) + rr * 8;
            const float inv = rr ? inv1 : inv0;
            uint32_t hp, lp;
            split2(out[nn][2 * rr] * inv, out[nn][2 * rr + 1] * inv, hp, lp);
            const size_t o = ((size_t)b * S_ + row) * D_ + col;
            *(uint32_t*)(g_Ohi + o) = hp;
            *(uint32_t*)(g_Olo + o) = lp;
        }
    }
}

// ---------------------------------------------------------------------------
// Launch
// ---------------------------------------------------------------------------
extern "C" void kernel_launch(void* const* d_in, const int* in_sizes, int n_in,
                              void* d_out, int out_size)
{
    const float* x     = (const float*)d_in[0];
    const float* Wqkv  = (const float*)d_in[1];
    const float* bqkv  = (const float*)d_in[2];
    const float* Wproj = (const float*)d_in[3];
    const float* bproj = (const float*)d_in[4];
    float* out = (float*)d_out;

    cudaFuncSetAttribute(gemm_mma_kernel<0>,
                         cudaFuncAttributeMaxDynamicSharedMemorySize, GEMM_DSMEM);
    cudaFuncSetAttribute(gemm_mma_kernel<1>,
                         cudaFuncAttributeMaxDynamicSharedMemorySize, GEMM_DSMEM);
    cudaFuncSetAttribute(flash_mma_kernel,
                         cudaFuncAttributeMaxDynamicSharedMemorySize, FLASH_DSMEM);

    split_kernel<<<4096, 256>>>(x, BS_ * D_);
    tsplit_kernel<0><<<dim3(N3D_ / 32, D_ / 32), dim3(32, 8)>>>(Wqkv, D_, N3D_);
    tsplit_kernel<1><<<dim3(D_ / 32, D_ / 32), dim3(32, 8)>>>(Wproj, D_, D_);

    gemm_mma_kernel<0><<<dim3(N3D_ / 128, BS_ / 128), 256, GEMM_DSMEM>>>(bqkv, nullptr);

    flash_mma_kernel<<<dim3(S_ / FBM, B_ * H_), 256, FLASH_DSMEM>>>();

    gemm_mma_kernel<1><<<dim3(D_ / 128, BS_ / 128), 256, GEMM_DSMEM>>>(bproj, out);
}

// round 8
// speedup vs baseline: 1.0537x; 1.0537x over previous
#include <cuda_runtime.h>
#include <cuda_bf16.h>
#include <cstdint>

// Problem constants
#define B_  2
#define S_  2048
#define D_  1024
#define H_  16
#define DH_ 64
#define BS_ (B_ * S_)        // 4096
#define N3D_ (3 * D_)        // 3072

// ---------------------------------------------------------------------------
// Scratch (allocation-free: __device__ globals)
// ---------------------------------------------------------------------------
__device__ __align__(128) __nv_bfloat16 g_Qhi[B_ * H_ * S_ * DH_]; // scaled 0.125
__device__ __align__(128) __nv_bfloat16 g_Qlo[B_ * H_ * S_ * DH_];
__device__ __align__(128) __nv_bfloat16 g_Khi[B_ * H_ * S_ * DH_];
__device__ __align__(128) __nv_bfloat16 g_Klo[B_ * H_ * S_ * DH_];
__device__ __align__(128) __nv_bfloat16 g_Vhi[B_ * H_ * S_ * DH_];
__device__ __align__(128) __nv_bfloat16 g_Vlo[B_ * H_ * S_ * DH_];

__device__ __align__(128) __nv_bfloat16 g_xhi[BS_ * D_];
__device__ __align__(128) __nv_bfloat16 g_xlo[BS_ * D_];
__device__ __align__(128) __nv_bfloat16 g_WqT_hi[N3D_ * D_];
__device__ __align__(128) __nv_bfloat16 g_WqT_lo[N3D_ * D_];
__device__ __align__(128) __nv_bfloat16 g_WpT_hi[D_ * D_];
__device__ __align__(128) __nv_bfloat16 g_WpT_lo[D_ * D_];
__device__ __align__(128) __nv_bfloat16 g_Ohi[BS_ * D_];
__device__ __align__(128) __nv_bfloat16 g_Olo[BS_ * D_];

// ---------------------------------------------------------------------------
// Base-ISA helpers
// ---------------------------------------------------------------------------
__device__ __forceinline__ uint32_t smem_u32(const void* p) {
    uint32_t a;
    asm("{ .reg .u64 t; cvta.to.shared.u64 t, %1; cvt.u32.u64 %0, t; }"
        : "=r"(a) : "l"(p));
    return a;
}
__device__ __forceinline__ uint32_t swz(uint32_t b) { return b ^ ((b >> 3) & 0x70); }

__device__ __forceinline__ void ldm4(uint32_t& r0, uint32_t& r1, uint32_t& r2,
                                     uint32_t& r3, uint32_t a) {
    asm volatile("ldmatrix.sync.aligned.m8n8.x4.shared.b16 {%0,%1,%2,%3},[%4];"
                 : "=r"(r0), "=r"(r1), "=r"(r2), "=r"(r3) : "r"(a));
}
__device__ __forceinline__ void ldm4t(uint32_t& r0, uint32_t& r1, uint32_t& r2,
                                      uint32_t& r3, uint32_t a) {
    asm volatile("ldmatrix.sync.aligned.m8n8.x4.trans.shared.b16 {%0,%1,%2,%3},[%4];"
                 : "=r"(r0), "=r"(r1), "=r"(r2), "=r"(r3) : "r"(a));
}
__device__ __forceinline__ void mma16816(float* d, const uint32_t* a,
                                         const uint32_t* b) {
    asm volatile(
        "mma.sync.aligned.m16n8k16.row.col.f32.bf16.bf16.f32 "
        "{%0,%1,%2,%3},{%4,%5,%6,%7},{%8,%9},{%0,%1,%2,%3};"
        : "+f"(d[0]), "+f"(d[1]), "+f"(d[2]), "+f"(d[3])
        : "r"(a[0]), "r"(a[1]), "r"(a[2]), "r"(a[3]), "r"(b[0]), "r"(b[1]));
}
__device__ __forceinline__ void cp16(uint32_t dst, const void* src) {
    asm volatile("cp.async.cg.shared.global [%0],[%1],16;" :: "r"(dst), "l"(src));
}
#define CP_COMMIT() asm volatile("cp.async.commit_group;")

__device__ __forceinline__ void split2(float a, float b, uint32_t& hi, uint32_t& lo) {
    __nv_bfloat162 h = __floats2bfloat162_rn(a, b);
    hi = *(uint32_t*)&h;
    __nv_bfloat162 l = __floats2bfloat162_rn(a - __bfloat162float(h.x),
                                             b - __bfloat162float(h.y));
    lo = *(uint32_t*)&l;
}

// ---------------------------------------------------------------------------
// Prep
// ---------------------------------------------------------------------------
__global__ void split_kernel(const float* __restrict__ x, int n)
{
    for (int i = blockIdx.x * blockDim.x + threadIdx.x; i < n;
         i += gridDim.x * blockDim.x) {
        float f = x[i];
        __nv_bfloat16 h = __float2bfloat16(f);
        g_xhi[i] = h;
        g_xlo[i] = __float2bfloat16(f - __bfloat162float(h));
    }
}

template <int MODE>  // 0: W_qkv, 1: W_proj
__global__ void tsplit_kernel(const float* __restrict__ W, int K, int N)
{
    __nv_bfloat16* hi = (MODE == 0) ? g_WqT_hi : g_WpT_hi;
    __nv_bfloat16* lo = (MODE == 0) ? g_WqT_lo : g_WpT_lo;
    __shared__ float t[32][33];
    int n0 = blockIdx.x * 32, k0 = blockIdx.y * 32;
    int tx = threadIdx.x, ty = threadIdx.y;
#pragma unroll
    for (int r = 0; r < 32; r += 8)
        t[ty + r][tx] = W[(size_t)(k0 + ty + r) * N + n0 + tx];
    __syncthreads();
#pragma unroll
    for (int r = 0; r < 32; r += 8) {
        float f = t[tx][ty + r];
        __nv_bfloat16 h = __float2bfloat16(f);
        size_t o = (size_t)(n0 + ty + r) * K + k0 + tx;
        hi[o] = h;
        lo[o] = __float2bfloat16(f - __bfloat162float(h));
    }
}

// ---------------------------------------------------------------------------
// mma.sync bf16 hi/lo GEMM. 256x128 CTA tile, 8 warps (4x2), 64x64 warp
// tile (LDSM:MMA ratio 6), K-chunk 64, 2-stage cp.async double buffer.
// ---------------------------------------------------------------------------
#define BKC 64
#define A_BYTES (256 * BKC * 2)              // 32768 per A array
#define Bn_BYTES (128 * BKC * 2)             // 16384 per B array
#define STAGE_BYTES (2 * A_BYTES + 2 * Bn_BYTES)   // 98304
#define GEMM_DSMEM (2 * STAGE_BYTES)               // 196608

template <int ROWS>
__device__ __forceinline__ void cp_tileR(uint32_t sdst,
                                         const __nv_bfloat16* __restrict__ g,
                                         int row0, int k0, int tid)
{
#pragma unroll
    for (int it = 0; it < ROWS / 32; it++) {
        int idx = tid + it * 256;
        int row = idx >> 3;
        int c   = idx & 7;
        cp16(sdst + swz(row * 128 + c * 16),
             g + (size_t)(row0 + row) * 1024 + k0 + c * 8);
    }
}

template <int MODE>
__global__ void __launch_bounds__(256) gemm_mma_kernel(
    const float* __restrict__ bias, float* __restrict__ Cout)
{
    constexpr int N = (MODE == 0) ? N3D_ : D_;
    constexpr int nkc = D_ / BKC;   // 16
    extern __shared__ char dsm[];
    const uint32_t sb0 = smem_u32(dsm);

    const int tid = threadIdx.x;
    const int wid = tid >> 5;
    const int lid = tid & 31;
    const int wm = wid >> 1;        // 0..3  (64-row band)
    const int wn = wid & 1;         // 0..1  (64-col band)
    const int m0 = blockIdx.y * 256;
    const int n0 = blockIdx.x * 128;

    const __nv_bfloat16* Ahi = (MODE == 0) ? g_xhi : g_Ohi;
    const __nv_bfloat16* Alo = (MODE == 0) ? g_xlo : g_Olo;
    const __nv_bfloat16* Bhi = (MODE == 0) ? g_WqT_hi : g_WpT_hi;
    const __nv_bfloat16* Blo = (MODE == 0) ? g_WqT_lo : g_WpT_lo;

    const int a_row = (lid & 7) + ((lid >> 3) & 1) * 8;
    const int a_kb  = (lid >> 4) * 16;
    const int b_row = (lid & 7) + ((lid >> 4) & 1) * 8;
    const int b_kb  = ((lid >> 3) & 1) * 16;

    float acc[4][8][4];
#pragma unroll
    for (int i = 0; i < 4; i++)
#pragma unroll
        for (int j = 0; j < 8; j++)
#pragma unroll
            for (int r = 0; r < 4; r++) acc[i][j][r] = 0.f;

    // prologue: stage 0
    {
        cp_tileR<256>(sb0 + 0,                       Ahi, m0, 0, tid);
        cp_tileR<256>(sb0 + A_BYTES,                 Alo, m0, 0, tid);
        cp_tileR<128>(sb0 + 2 * A_BYTES,             Bhi, n0, 0, tid);
        cp_tileR<128>(sb0 + 2 * A_BYTES + Bn_BYTES,  Blo, n0, 0, tid);
        CP_COMMIT();
    }

    for (int kc = 0; kc < nkc; kc++) {
        if (kc + 1 < nkc) {
            uint32_t sb = sb0 + ((kc + 1) & 1) * STAGE_BYTES;
            const int k0 = (kc + 1) * BKC;
            cp_tileR<256>(sb + 0,                      Ahi, m0, k0, tid);
            cp_tileR<256>(sb + A_BYTES,                Alo, m0, k0, tid);
            cp_tileR<128>(sb + 2 * A_BYTES,            Bhi, n0, k0, tid);
            cp_tileR<128>(sb + 2 * A_BYTES + Bn_BYTES, Blo, n0, k0, tid);
            CP_COMMIT();
            asm volatile("cp.async.wait_group 1;");
        } else {
            asm volatile("cp.async.wait_group 0;");
        }
        __syncthreads();

        const uint32_t sb = sb0 + (kc & 1) * STAGE_BYTES;
        const uint32_t sAhi = sb;
        const uint32_t sAlo = sb + A_BYTES;
        const uint32_t sBhi = sb + 2 * A_BYTES;
        const uint32_t sBlo = sb + 2 * A_BYTES + Bn_BYTES;

#pragma unroll
        for (int ks = 0; ks < 4; ks++) {
            uint32_t ahi[4][4], alo[4][4], bhi[8][2], blo[8][2];
#pragma unroll
            for (int i = 0; i < 4; i++) {
                uint32_t off = swz((wm * 64 + i * 16 + a_row) * 128 + ks * 32 + a_kb);
                ldm4(ahi[i][0], ahi[i][1], ahi[i][2], ahi[i][3], sAhi + off);
                ldm4(alo[i][0], alo[i][1], alo[i][2], alo[i][3], sAlo + off);
            }
#pragma unroll
            for (int p = 0; p < 4; p++) {
                uint32_t off = swz((wn * 64 + p * 16 + b_row) * 128 + ks * 32 + b_kb);
                ldm4(bhi[2 * p][0], bhi[2 * p][1], bhi[2 * p + 1][0],
                     bhi[2 * p + 1][1], sBhi + off);
                ldm4(blo[2 * p][0], blo[2 * p][1], blo[2 * p + 1][0],
                     blo[2 * p + 1][1], sBlo + off);
            }
#pragma unroll
            for (int i = 0; i < 4; i++)
#pragma unroll
                for (int j = 0; j < 8; j++) {
                    mma16816(acc[i][j], ahi[i], bhi[j]);
                    mma16816(acc[i][j], ahi[i], blo[j]);
                    mma16816(acc[i][j], alo[i], bhi[j]);
                }
        }
        __syncthreads();
    }

#pragma unroll
    for (int i = 0; i < 4; i++) {
#pragma unroll
        for (int j = 0; j < 8; j++) {
            const int n = n0 + wn * 64 + j * 8 + (lid & 3) * 2;
            const float b0 = __ldg(&bias[n]);
            const float b1 = __ldg(&bias[n + 1]);
#pragma unroll
            for (int rr = 0; rr < 2; rr++) {
                const int m = m0 + wm * 64 + i * 16 + (lid >> 2) + rr * 8;
                float v0 = acc[i][j][rr * 2 + 0] + b0;
                float v1 = acc[i][j][rr * 2 + 1] + b1;
                if constexpr (MODE == 0) {
                    const int b = m >> 11, s = m & 2047;
                    const int rem = n & 1023, h = rem >> 6, d = rem & 63;
                    const size_t o = (((size_t)(b * H_ + h) << 11) + s) * DH_ + d;
                    const int which = n0 >> 10;
                    if (which == 0) { v0 *= 0.125f; v1 *= 0.125f; }
                    uint32_t hp, lp;
                    split2(v0, v1, hp, lp);
                    if (which == 0) {
                        *(uint32_t*)(g_Qhi + o) = hp; *(uint32_t*)(g_Qlo + o) = lp;
                    } else if (which == 1) {
                        *(uint32_t*)(g_Khi + o) = hp; *(uint32_t*)(g_Klo + o) = lp;
                    } else {
                        *(uint32_t*)(g_Vhi + o) = hp; *(uint32_t*)(g_Vlo + o) = lp;
                    }
                } else {
                    *(float2*)(Cout + (size_t)m * N + n) = make_float2(v0, v1);
                }
            }
        }
    }
}

// ---------------------------------------------------------------------------
// Flash attention (round-6 version, verbatim): mma.sync bf16 hi/lo, causal,
// BM=128, BN=64, 8 warps * 16 rows, 3-stage pipeline, ONE sync per tile.
// ---------------------------------------------------------------------------
#define FBM 128
#define FBN 64
#define FK_BYTES (FBN * 128)            // 8192
#define FSTAGE   (4 * FK_BYTES)          // 32768
#define FLASH_DSMEM (3 * FSTAGE)         // 98304

__device__ __forceinline__ void cp_ftile(uint32_t sdst,
                                         const __nv_bfloat16* __restrict__ g,
                                         int tid)
{
#pragma unroll
    for (int it = 0; it < 2; it++) {
        int idx = tid + it * 256;
        int row = idx >> 3;
        int c   = idx & 7;
        cp16(sdst + swz(row * 128 + c * 16), g + (size_t)row * 64 + c * 8);
    }
}

__global__ void __launch_bounds__(256) flash_mma_kernel()
{
    extern __shared__ char fsm[];
    const uint32_t sStage = smem_u32(fsm);

    const int tid = threadIdx.x;
    const int wid = tid >> 5;
    const int lid = tid & 31;
    const int qt = blockIdx.x;
    const int bh = blockIdx.y;
    const int q0 = qt * FBM;
    const int nkt = 2 * qt + 2;

    const __nv_bfloat16* Qhig = g_Qhi + ((size_t)bh * S_ + q0) * DH_;
    const __nv_bfloat16* Qlog = g_Qlo + ((size_t)bh * S_ + q0) * DH_;
    const __nv_bfloat16* Khig = g_Khi + (size_t)bh * S_ * DH_;
    const __nv_bfloat16* Klog = g_Klo + (size_t)bh * S_ * DH_;
    const __nv_bfloat16* Vhig = g_Vhi + (size_t)bh * S_ * DH_;
    const __nv_bfloat16* Vlog = g_Vlo + (size_t)bh * S_ * DH_;

    // ---- stage Q through stage-0 buffer: hi at +0, lo at +16KB ----
#pragma unroll
    for (int it = 0; it < 4; it++) {
        int idx = tid + it * 256;
        int row = idx >> 3;
        int c   = idx & 7;
        cp16(sStage + swz(row * 128 + c * 16),         Qhig + (size_t)row * 64 + c * 8);
        cp16(sStage + 16384 + swz(row * 128 + c * 16), Qlog + (size_t)row * 64 + c * 8);
    }
    CP_COMMIT();
    asm volatile("cp.async.wait_group 0;");
    __syncthreads();

    const int a_row = (lid & 7) + ((lid >> 3) & 1) * 8;
    const int a_kb  = (lid >> 4) * 16;
    uint32_t qhi[4][4], qlo[4][4];
#pragma unroll
    for (int ks = 0; ks < 4; ks++) {
        uint32_t off = swz((wid * 16 + a_row) * 128 + ks * 32 + a_kb);
        ldm4(qhi[ks][0], qhi[ks][1], qhi[ks][2], qhi[ks][3], sStage + off);
        ldm4(qlo[ks][0], qlo[ks][1], qlo[ks][2], qlo[ks][3], sStage + 16384 + off);
    }
    __syncthreads();   // frags extracted; buffers reusable for K/V

    // prefetch kt=0 -> buf0, kt=1 -> buf1
#pragma unroll
    for (int s = 0; s < 2; s++) {
        uint32_t sb = sStage + s * FSTAGE;
        const size_t koff = (size_t)s * FBN * DH_;
        cp_ftile(sb + 0 * FK_BYTES, Khig + koff, tid);
        cp_ftile(sb + 1 * FK_BYTES, Klog + koff, tid);
        cp_ftile(sb + 2 * FK_BYTES, Vhig + koff, tid);
        cp_ftile(sb + 3 * FK_BYTES, Vlog + koff, tid);
        CP_COMMIT();
    }

    const int b_row = (lid & 7) + ((lid >> 4) & 1) * 8;
    const int b_kb  = ((lid >> 3) & 1) * 16;
    const int v_row = (lid & 7) + ((lid >> 3) & 1) * 8;
    const int v_cb  = ((lid >> 4) & 1) * 16;

    float m_i[2] = {-1e30f, -1e30f};
    float l_i[2] = {0.f, 0.f};
    float out[8][4];
#pragma unroll
    for (int nn = 0; nn < 8; nn++)
#pragma unroll
        for (int r = 0; r < 4; r++) out[nn][r] = 0.f;

    int bufc = 0;   // kt % 3
    int bufp = 2;   // (kt+2) % 3
    for (int kt = 0; kt < nkt; kt++) {
        if (kt + 1 < nkt) { asm volatile("cp.async.wait_group 1;"); }
        else              { asm volatile("cp.async.wait_group 0;"); }
        __syncthreads();   // stage kt ready; all warps done with stage kt-1

        if (kt + 2 < nkt) {
            uint32_t sb2 = sStage + bufp * FSTAGE;
            const size_t koff = (size_t)(kt + 2) * FBN * DH_;
            cp_ftile(sb2 + 0 * FK_BYTES, Khig + koff, tid);
            cp_ftile(sb2 + 1 * FK_BYTES, Klog + koff, tid);
            cp_ftile(sb2 + 2 * FK_BYTES, Vhig + koff, tid);
            cp_ftile(sb2 + 3 * FK_BYTES, Vlog + koff, tid);
            CP_COMMIT();
        }

        const uint32_t sb = sStage + bufc * FSTAGE;
        const uint32_t sKhi = sb + 0 * FK_BYTES;
        const uint32_t sKlo = sb + 1 * FK_BYTES;
        const uint32_t sVhi = sb + 2 * FK_BYTES;
        const uint32_t sVlo = sb + 3 * FK_BYTES;

        float sc[8][4];
#pragma unroll
        for (int j = 0; j < 8; j++)
#pragma unroll
            for (int r = 0; r < 4; r++) sc[j][r] = 0.f;

#pragma unroll
        for (int jp = 0; jp < 4; jp++) {
#pragma unroll
            for (int ks = 0; ks < 4; ks++) {
                uint32_t off = swz((jp * 16 + b_row) * 128 + ks * 32 + b_kb);
                uint32_t kh[4], kl[4];
                ldm4(kh[0], kh[1], kh[2], kh[3], sKhi + off);
                ldm4(kl[0], kl[1], kl[2], kl[3], sKlo + off);
                uint32_t bh0[2] = {kh[0], kh[1]}, bh1[2] = {kh[2], kh[3]};
                uint32_t bl0[2] = {kl[0], kl[1]}, bl1[2] = {kl[2], kl[3]};
                mma16816(sc[2 * jp],     qhi[ks], bh0);
                mma16816(sc[2 * jp],     qhi[ks], bl0);
                mma16816(sc[2 * jp],     qlo[ks], bh0);
                mma16816(sc[2 * jp + 1], qhi[ks], bh1);
                mma16816(sc[2 * jp + 1], qhi[ks], bl1);
                mma16816(sc[2 * jp + 1], qlo[ks], bh1);
            }
        }

        if (kt >= nkt - 2) {
            const int k0g = kt * FBN;
            const int rbase = q0 + wid * 16 + (lid >> 2);
#pragma unroll
            for (int j = 0; j < 8; j++) {
                const int cbase = k0g + j * 8 + 2 * (lid & 3);
#pragma unroll
                for (int rr = 0; rr < 2; rr++) {
                    const int row = rbase + rr * 8;
                    if (cbase > row)     sc[j][2 * rr]     = -1e30f;
                    if (cbase + 1 > row) sc[j][2 * rr + 1] = -1e30f;
                }
            }
        }

        float alpha[2];
#pragma unroll
        for (int rr = 0; rr < 2; rr++) {
            float tm = -1e30f;
#pragma unroll
            for (int j = 0; j < 8; j++)
                tm = fmaxf(tm, fmaxf(sc[j][2 * rr], sc[j][2 * rr + 1]));
            tm = fmaxf(tm, __shfl_xor_sync(0xffffffffu, tm, 1));
            tm = fmaxf(tm, __shfl_xor_sync(0xffffffffu, tm, 2));
            const float mn = fmaxf(m_i[rr], tm);
            alpha[rr] = __expf(m_i[rr] - mn);
            m_i[rr] = mn;
            float rs = 0.f;
#pragma unroll
            for (int j = 0; j < 8; j++) {
                float p0 = __expf(sc[j][2 * rr]     - mn);
                float p1 = __expf(sc[j][2 * rr + 1] - mn);
                sc[j][2 * rr] = p0; sc[j][2 * rr + 1] = p1;
                rs += p0 + p1;
            }
            rs += __shfl_xor_sync(0xffffffffu, rs, 1);
            rs += __shfl_xor_sync(0xffffffffu, rs, 2);
            l_i[rr] = l_i[rr] * alpha[rr] + rs;
        }
#pragma unroll
        for (int nn = 0; nn < 8; nn++) {
            out[nn][0] *= alpha[0]; out[nn][1] *= alpha[0];
            out[nn][2] *= alpha[1]; out[nn][3] *= alpha[1];
        }

#pragma unroll
        for (int kk = 0; kk < 4; kk++) {
            uint32_t phi[4], plo[4];
            split2(sc[2 * kk][0],     sc[2 * kk][1],     phi[0], plo[0]);
            split2(sc[2 * kk][2],     sc[2 * kk][3],     phi[1], plo[1]);
            split2(sc[2 * kk + 1][0], sc[2 * kk + 1][1], phi[2], plo[2]);
            split2(sc[2 * kk + 1][2], sc[2 * kk + 1][3], phi[3], plo[3]);
#pragma unroll
            for (int np = 0; np < 4; np++) {
                uint32_t off = swz((kk * 16 + v_row) * 128 + np * 32 + v_cb);
                uint32_t vh[4], vl[4];
                ldm4t(vh[0], vh[1], vh[2], vh[3], sVhi + off);
                ldm4t(vl[0], vl[1], vl[2], vl[3], sVlo + off);
                uint32_t bh0[2] = {vh[0], vh[1]}, bh1[2] = {vh[2], vh[3]};
                uint32_t bl0[2] = {vl[0], vl[1]}, bl1[2] = {vl[2], vl[3]};
                mma16816(out[2 * np],     phi, bh0);
                mma16816(out[2 * np],     phi, bl0);
                mma16816(out[2 * np],     plo, bh0);
                mma16816(out[2 * np + 1], phi, bh1);
                mma16816(out[2 * np + 1], phi, bl1);
                mma16816(out[2 * np + 1], plo, bh1);
            }
        }

        bufc = (bufc == 2) ? 0 : bufc + 1;
        bufp = (bufp == 2) ? 0 : bufp + 1;
    }

    const int b = bh >> 4;
    const int h = bh & 15;
    const float inv0 = 1.0f / l_i[0];
    const float inv1 = 1.0f / l_i[1];
#pragma unroll
    for (int nn = 0; nn < 8; nn++) {
        const int col = h * 64 + nn * 8 + 2 * (lid & 3);
#pragma unroll
        for (int rr = 0; rr < 2; rr++) {
            const int row = q0 + wid * 16 + (lid >> 2) + rr * 8;
            const float inv = rr ? inv1 : inv0;
            uint32_t hp, lp;
            split2(out[nn][2 * rr] * inv, out[nn][2 * rr + 1] * inv, hp, lp);
            const size_t o = ((size_t)b * S_ + row) * D_ + col;
            *(uint32_t*)(g_Ohi + o) = hp;
            *(uint32_t*)(g_Olo + o) = lp;
        }
    }
}

// ---------------------------------------------------------------------------
// Launch
// ---------------------------------------------------------------------------
extern "C" void kernel_launch(void* const* d_in, const int* in_sizes, int n_in,
                              void* d_out, int out_size)
{
    const float* x     = (const float*)d_in[0];
    const float* Wqkv  = (const float*)d_in[1];
    const float* bqkv  = (const float*)d_in[2];
    const float* Wproj = (const float*)d_in[3];
    const float* bproj = (const float*)d_in[4];
    float* out = (float*)d_out;

    cudaFuncSetAttribute(gemm_mma_kernel<0>,
                         cudaFuncAttributeMaxDynamicSharedMemorySize, GEMM_DSMEM);
    cudaFuncSetAttribute(gemm_mma_kernel<1>,
                         cudaFuncAttributeMaxDynamicSharedMemorySize, GEMM_DSMEM);
    cudaFuncSetAttribute(flash_mma_kernel,
                         cudaFuncAttributeMaxDynamicSharedMemorySize, FLASH_DSMEM);

    split_kernel<<<4096, 256>>>(x, BS_ * D_);
    tsplit_kernel<0><<<dim3(N3D_ / 32, D_ / 32), dim3(32, 8)>>>(Wqkv, D_, N3D_);
    tsplit_kernel<1><<<dim3(D_ / 32, D_ / 32), dim3(32, 8)>>>(Wproj, D_, D_);

    gemm_mma_kernel<0><<<dim3(N3D_ / 128, BS_ / 256), 256, GEMM_DSMEM>>>(bqkv, nullptr);

    flash_mma_kernel<<<dim3(S_ / FBM, B_ * H_), 256, FLASH_DSMEM>>>();

    gemm_mma_kernel<1><<<dim3(D_ / 128, BS_ / 256), 256, GEMM_DSMEM>>>(bproj, out);
}

// round 9
// speedup vs baseline: 1.3022x; 1.2358x over previous
#include <cuda_runtime.h>
#include <cuda_bf16.h>
#include <cuda_fp16.h>
#include <cstdint>

// Problem constants
#define B_  2
#define S_  2048
#define D_  1024
#define H_  16
#define DH_ 64
#define BS_ (B_ * S_)        // 4096
#define N3D_ (3 * D_)        // 3072

// ---------------------------------------------------------------------------
// Scratch (allocation-free: __device__ globals)
// ---------------------------------------------------------------------------
__device__ __align__(128) __half g_Qh[B_ * H_ * S_ * DH_];  // scaled 0.125
__device__ __align__(128) __half g_Kh[B_ * H_ * S_ * DH_];
__device__ __align__(128) __half g_Vh[B_ * H_ * S_ * DH_];

__device__ __align__(128) __nv_bfloat16 g_xhi[BS_ * D_];
__device__ __align__(128) __nv_bfloat16 g_xlo[BS_ * D_];
__device__ __align__(128) __nv_bfloat16 g_WqT_hi[N3D_ * D_];
__device__ __align__(128) __nv_bfloat16 g_WqT_lo[N3D_ * D_];
__device__ __align__(128) __nv_bfloat16 g_WpT_hi[D_ * D_];
__device__ __align__(128) __nv_bfloat16 g_WpT_lo[D_ * D_];
__device__ __align__(128) __nv_bfloat16 g_Ohi[BS_ * D_];
__device__ __align__(128) __nv_bfloat16 g_Olo[BS_ * D_];

// ---------------------------------------------------------------------------
// Base-ISA helpers
// ---------------------------------------------------------------------------
__device__ __forceinline__ uint32_t smem_u32(const void* p) {
    uint32_t a;
    asm("{ .reg .u64 t; cvta.to.shared.u64 t, %1; cvt.u32.u64 %0, t; }"
        : "=r"(a) : "l"(p));
    return a;
}
__device__ __forceinline__ uint32_t swz(uint32_t b) { return b ^ ((b >> 3) & 0x70); }

__device__ __forceinline__ void ldm4(uint32_t& r0, uint32_t& r1, uint32_t& r2,
                                     uint32_t& r3, uint32_t a) {
    asm volatile("ldmatrix.sync.aligned.m8n8.x4.shared.b16 {%0,%1,%2,%3},[%4];"
                 : "=r"(r0), "=r"(r1), "=r"(r2), "=r"(r3) : "r"(a));
}
__device__ __forceinline__ void ldm4t(uint32_t& r0, uint32_t& r1, uint32_t& r2,
                                      uint32_t& r3, uint32_t a) {
    asm volatile("ldmatrix.sync.aligned.m8n8.x4.trans.shared.b16 {%0,%1,%2,%3},[%4];"
                 : "=r"(r0), "=r"(r1), "=r"(r2), "=r"(r3) : "r"(a));
}
__device__ __forceinline__ void mma16816(float* d, const uint32_t* a,
                                         const uint32_t* b) {
    asm volatile(
        "mma.sync.aligned.m16n8k16.row.col.f32.bf16.bf16.f32 "
        "{%0,%1,%2,%3},{%4,%5,%6,%7},{%8,%9},{%0,%1,%2,%3};"
        : "+f"(d[0]), "+f"(d[1]), "+f"(d[2]), "+f"(d[3])
        : "r"(a[0]), "r"(a[1]), "r"(a[2]), "r"(a[3]), "r"(b[0]), "r"(b[1]));
}
__device__ __forceinline__ void mma16816h(float* d, const uint32_t* a,
                                          const uint32_t* b) {
    asm volatile(
        "mma.sync.aligned.m16n8k16.row.col.f32.f16.f16.f32 "
        "{%0,%1,%2,%3},{%4,%5,%6,%7},{%8,%9},{%0,%1,%2,%3};"
        : "+f"(d[0]), "+f"(d[1]), "+f"(d[2]), "+f"(d[3])
        : "r"(a[0]), "r"(a[1]), "r"(a[2]), "r"(a[3]), "r"(b[0]), "r"(b[1]));
}
__device__ __forceinline__ void cp16(uint32_t dst, const void* src) {
    asm volatile("cp.async.cg.shared.global [%0],[%1],16;" :: "r"(dst), "l"(src));
}
#define CP_COMMIT() asm volatile("cp.async.commit_group;")

__device__ __forceinline__ void split2(float a, float b, uint32_t& hi, uint32_t& lo) {
    __nv_bfloat162 h = __floats2bfloat162_rn(a, b);
    hi = *(uint32_t*)&h;
    __nv_bfloat162 l = __floats2bfloat162_rn(a - __bfloat162float(h.x),
                                             b - __bfloat162float(h.y));
    lo = *(uint32_t*)&l;
}
__device__ __forceinline__ uint32_t packh2(float a, float b) {
    __half2 h = __floats2half2_rn(a, b);
    return *(uint32_t*)&h;
}

// ---------------------------------------------------------------------------
// Prep
// ---------------------------------------------------------------------------
__global__ void split_kernel(const float* __restrict__ x, int n)
{
    for (int i = blockIdx.x * blockDim.x + threadIdx.x; i < n;
         i += gridDim.x * blockDim.x) {
        float f = x[i];
        __nv_bfloat16 h = __float2bfloat16(f);
        g_xhi[i] = h;
        g_xlo[i] = __float2bfloat16(f - __bfloat162float(h));
    }
}

template <int MODE>  // 0: W_qkv, 1: W_proj
__global__ void tsplit_kernel(const float* __restrict__ W, int K, int N)
{
    __nv_bfloat16* hi = (MODE == 0) ? g_WqT_hi : g_WpT_hi;
    __nv_bfloat16* lo = (MODE == 0) ? g_WqT_lo : g_WpT_lo;
    __shared__ float t[32][33];
    int n0 = blockIdx.x * 32, k0 = blockIdx.y * 32;
    int tx = threadIdx.x, ty = threadIdx.y;
#pragma unroll
    for (int r = 0; r < 32; r += 8)
        t[ty + r][tx] = W[(size_t)(k0 + ty + r) * N + n0 + tx];
    __syncthreads();
#pragma unroll
    for (int r = 0; r < 32; r += 8) {
        float f = t[tx][ty + r];
        __nv_bfloat16 h = __float2bfloat16(f);
        size_t o = (size_t)(n0 + ty + r) * K + k0 + tx;
        hi[o] = h;
        lo[o] = __float2bfloat16(f - __bfloat162float(h));
    }
}

// ---------------------------------------------------------------------------
// mma.sync bf16 hi/lo GEMM (round-8 best). 256x128 CTA tile, 8 warps (4x2),
// 64x64 warp tile, K-chunk 64, 2-stage cp.async double buffer.
// MODE 0: QKV -> q/k/v fp16 (Q scaled).  MODE 1: proj -> fp32 out.
// ---------------------------------------------------------------------------
#define BKC 64
#define A_BYTES (256 * BKC * 2)
#define Bn_BYTES (128 * BKC * 2)
#define STAGE_BYTES (2 * A_BYTES + 2 * Bn_BYTES)   // 98304
#define GEMM_DSMEM (2 * STAGE_BYTES)               // 196608

template <int ROWS>
__device__ __forceinline__ void cp_tileR(uint32_t sdst,
                                         const __nv_bfloat16* __restrict__ g,
                                         int row0, int k0, int tid)
{
#pragma unroll
    for (int it = 0; it < ROWS / 32; it++) {
        int idx = tid + it * 256;
        int row = idx >> 3;
        int c   = idx & 7;
        cp16(sdst + swz(row * 128 + c * 16),
             g + (size_t)(row0 + row) * 1024 + k0 + c * 8);
    }
}

template <int MODE>
__global__ void __launch_bounds__(256) gemm_mma_kernel(
    const float* __restrict__ bias, float* __restrict__ Cout)
{
    constexpr int N = (MODE == 0) ? N3D_ : D_;
    constexpr int nkc = D_ / BKC;   // 16
    extern __shared__ char dsm[];
    const uint32_t sb0 = smem_u32(dsm);

    const int tid = threadIdx.x;
    const int wid = tid >> 5;
    const int lid = tid & 31;
    const int wm = wid >> 1;
    const int wn = wid & 1;
    const int m0 = blockIdx.y * 256;
    const int n0 = blockIdx.x * 128;

    const __nv_bfloat16* Ahi = (MODE == 0) ? g_xhi : g_Ohi;
    const __nv_bfloat16* Alo = (MODE == 0) ? g_xlo : g_Olo;
    const __nv_bfloat16* Bhi = (MODE == 0) ? g_WqT_hi : g_WpT_hi;
    const __nv_bfloat16* Blo = (MODE == 0) ? g_WqT_lo : g_WpT_lo;

    const int a_row = (lid & 7) + ((lid >> 3) & 1) * 8;
    const int a_kb  = (lid >> 4) * 16;
    const int b_row = (lid & 7) + ((lid >> 4) & 1) * 8;
    const int b_kb  = ((lid >> 3) & 1) * 16;

    float acc[4][8][4];
#pragma unroll
    for (int i = 0; i < 4; i++)
#pragma unroll
        for (int j = 0; j < 8; j++)
#pragma unroll
            for (int r = 0; r < 4; r++) acc[i][j][r] = 0.f;

    {
        cp_tileR<256>(sb0 + 0,                       Ahi, m0, 0, tid);
        cp_tileR<256>(sb0 + A_BYTES,                 Alo, m0, 0, tid);
        cp_tileR<128>(sb0 + 2 * A_BYTES,             Bhi, n0, 0, tid);
        cp_tileR<128>(sb0 + 2 * A_BYTES + Bn_BYTES,  Blo, n0, 0, tid);
        CP_COMMIT();
    }

    for (int kc = 0; kc < nkc; kc++) {
        if (kc + 1 < nkc) {
            uint32_t sb = sb0 + ((kc + 1) & 1) * STAGE_BYTES;
            const int k0 = (kc + 1) * BKC;
            cp_tileR<256>(sb + 0,                      Ahi, m0, k0, tid);
            cp_tileR<256>(sb + A_BYTES,                Alo, m0, k0, tid);
            cp_tileR<128>(sb + 2 * A_BYTES,            Bhi, n0, k0, tid);
            cp_tileR<128>(sb + 2 * A_BYTES + Bn_BYTES, Blo, n0, k0, tid);
            CP_COMMIT();
            asm volatile("cp.async.wait_group 1;");
        } else {
            asm volatile("cp.async.wait_group 0;");
        }
        __syncthreads();

        const uint32_t sb = sb0 + (kc & 1) * STAGE_BYTES;
        const uint32_t sAhi = sb;
        const uint32_t sAlo = sb + A_BYTES;
        const uint32_t sBhi = sb + 2 * A_BYTES;
        const uint32_t sBlo = sb + 2 * A_BYTES + Bn_BYTES;

#pragma unroll
        for (int ks = 0; ks < 4; ks++) {
            uint32_t ahi[4][4], alo[4][4], bhi[8][2], blo[8][2];
#pragma unroll
            for (int i = 0; i < 4; i++) {
                uint32_t off = swz((wm * 64 + i * 16 + a_row) * 128 + ks * 32 + a_kb);
                ldm4(ahi[i][0], ahi[i][1], ahi[i][2], ahi[i][3], sAhi + off);
                ldm4(alo[i][0], alo[i][1], alo[i][2], alo[i][3], sAlo + off);
            }
#pragma unroll
            for (int p = 0; p < 4; p++) {
                uint32_t off = swz((wn * 64 + p * 16 + b_row) * 128 + ks * 32 + b_kb);
                ldm4(bhi[2 * p][0], bhi[2 * p][1], bhi[2 * p + 1][0],
                     bhi[2 * p + 1][1], sBhi + off);
                ldm4(blo[2 * p][0], blo[2 * p][1], blo[2 * p + 1][0],
                     blo[2 * p + 1][1], sBlo + off);
            }
#pragma unroll
            for (int i = 0; i < 4; i++)
#pragma unroll
                for (int j = 0; j < 8; j++) {
                    mma16816(acc[i][j], ahi[i], bhi[j]);
                    mma16816(acc[i][j], ahi[i], blo[j]);
                    mma16816(acc[i][j], alo[i], bhi[j]);
                }
        }
        __syncthreads();
    }

#pragma unroll
    for (int i = 0; i < 4; i++) {
#pragma unroll
        for (int j = 0; j < 8; j++) {
            const int n = n0 + wn * 64 + j * 8 + (lid & 3) * 2;
            const float b0 = __ldg(&bias[n]);
            const float b1 = __ldg(&bias[n + 1]);
#pragma unroll
            for (int rr = 0; rr < 2; rr++) {
                const int m = m0 + wm * 64 + i * 16 + (lid >> 2) + rr * 8;
                float v0 = acc[i][j][rr * 2 + 0] + b0;
                float v1 = acc[i][j][rr * 2 + 1] + b1;
                if constexpr (MODE == 0) {
                    const int b = m >> 11, s = m & 2047;
                    const int rem = n & 1023, h = rem >> 6, d = rem & 63;
                    const size_t o = (((size_t)(b * H_ + h) << 11) + s) * DH_ + d;
                    const int which = n0 >> 10;
                    if (which == 0) { v0 *= 0.125f; v1 *= 0.125f; }
                    const uint32_t hp = packh2(v0, v1);
                    if (which == 0)      *(uint32_t*)(g_Qh + o) = hp;
                    else if (which == 1) *(uint32_t*)(g_Kh + o) = hp;
                    else                 *(uint32_t*)(g_Vh + o) = hp;
                } else {
                    *(float2*)(Cout + (size_t)m * N + n) = make_float2(v0, v1);
                }
            }
        }
    }
}

// ---------------------------------------------------------------------------
// Flash attention, fp16 SINGLE-PASS mma.sync, causal.
// BM=128, BN=64, 8 warps * 16 rows, 3-stage pipeline (16KB/stage = 48KB),
// ONE sync per tile. Q staged through stage 0.
// ---------------------------------------------------------------------------
#define FBM 128
#define FBN 64
#define FK_BYTES (FBN * 128)            // 8192 (64 rows x 128B fp16)
#define FSTAGE   (2 * FK_BYTES)          // 16384 (K + V)
#define FLASH_DSMEM (3 * FSTAGE)         // 49152

__device__ __forceinline__ void cp_ftile(uint32_t sdst,
                                         const __half* __restrict__ g,
                                         int tid)
{
#pragma unroll
    for (int it = 0; it < 2; it++) {
        int idx = tid + it * 256;
        int row = idx >> 3;
        int c   = idx & 7;
        cp16(sdst + swz(row * 128 + c * 16), g + (size_t)row * 64 + c * 8);
    }
}

__global__ void __launch_bounds__(256) flash_mma_kernel()
{
    extern __shared__ char fsm[];
    const uint32_t sStage = smem_u32(fsm);

    const int tid = threadIdx.x;
    const int wid = tid >> 5;
    const int lid = tid & 31;
    const int qt = blockIdx.x;
    const int bh = blockIdx.y;
    const int q0 = qt * FBM;
    const int nkt = 2 * qt + 2;

    const __half* Qg = g_Qh + ((size_t)bh * S_ + q0) * DH_;
    const __half* Kg = g_Kh + (size_t)bh * S_ * DH_;
    const __half* Vg = g_Vh + (size_t)bh * S_ * DH_;

    // ---- stage Q (128x64 fp16 = 16KB) through stage-0 buffer ----
#pragma unroll
    for (int it = 0; it < 4; it++) {
        int idx = tid + it * 256;
        int row = idx >> 3;
        int c   = idx & 7;
        cp16(sStage + swz(row * 128 + c * 16), Qg + (size_t)row * 64 + c * 8);
    }
    CP_COMMIT();
    asm volatile("cp.async.wait_group 0;");
    __syncthreads();

    const int a_row = (lid & 7) + ((lid >> 3) & 1) * 8;
    const int a_kb  = (lid >> 4) * 16;
    uint32_t qh[4][4];
#pragma unroll
    for (int ks = 0; ks < 4; ks++) {
        uint32_t off = swz((wid * 16 + a_row) * 128 + ks * 32 + a_kb);
        ldm4(qh[ks][0], qh[ks][1], qh[ks][2], qh[ks][3], sStage + off);
    }
    __syncthreads();   // Q frags extracted; buffers reusable for K/V

    // prefetch kt=0 -> buf0, kt=1 -> buf1
#pragma unroll
    for (int s = 0; s < 2; s++) {
        uint32_t sb = sStage + s * FSTAGE;
        const size_t koff = (size_t)s * FBN * DH_;
        cp_ftile(sb + 0,        Kg + koff, tid);
        cp_ftile(sb + FK_BYTES, Vg + koff, tid);
        CP_COMMIT();
    }

    const int b_row = (lid & 7) + ((lid >> 4) & 1) * 8;
    const int b_kb  = ((lid >> 3) & 1) * 16;
    const int v_row = (lid & 7) + ((lid >> 3) & 1) * 8;
    const int v_cb  = ((lid >> 4) & 1) * 16;

    float m_i[2] = {-1e30f, -1e30f};
    float l_i[2] = {0.f, 0.f};
    float out[8][4];
#pragma unroll
    for (int nn = 0; nn < 8; nn++)
#pragma unroll
        for (int r = 0; r < 4; r++) out[nn][r] = 0.f;

    int bufc = 0;   // kt % 3
    int bufp = 2;   // (kt+2) % 3
    for (int kt = 0; kt < nkt; kt++) {
        if (kt + 1 < nkt) { asm volatile("cp.async.wait_group 1;"); }
        else              { asm volatile("cp.async.wait_group 0;"); }
        __syncthreads();

        if (kt + 2 < nkt) {
            uint32_t sb2 = sStage + bufp * FSTAGE;
            const size_t koff = (size_t)(kt + 2) * FBN * DH_;
            cp_ftile(sb2 + 0,        Kg + koff, tid);
            cp_ftile(sb2 + FK_BYTES, Vg + koff, tid);
            CP_COMMIT();
        }

        const uint32_t sb = sStage + bufc * FSTAGE;
        const uint32_t sK = sb;
        const uint32_t sV = sb + FK_BYTES;

        float sc[8][4];
#pragma unroll
        for (int j = 0; j < 8; j++)
#pragma unroll
            for (int r = 0; r < 4; r++) sc[j][r] = 0.f;

        // QK^T: single fp16 pass
#pragma unroll
        for (int jp = 0; jp < 4; jp++) {
#pragma unroll
            for (int ks = 0; ks < 4; ks++) {
                uint32_t off = swz((jp * 16 + b_row) * 128 + ks * 32 + b_kb);
                uint32_t kh[4];
                ldm4(kh[0], kh[1], kh[2], kh[3], sK + off);
                mma16816h(sc[2 * jp],     qh[ks], &kh[0]);
                mma16816h(sc[2 * jp + 1], qh[ks], &kh[2]);
            }
        }

        if (kt >= nkt - 2) {
            const int k0g = kt * FBN;
            const int rbase = q0 + wid * 16 + (lid >> 2);
#pragma unroll
            for (int j = 0; j < 8; j++) {
                const int cbase = k0g + j * 8 + 2 * (lid & 3);
#pragma unroll
                for (int rr = 0; rr < 2; rr++) {
                    const int row = rbase + rr * 8;
                    if (cbase > row)     sc[j][2 * rr]     = -1e30f;
                    if (cbase + 1 > row) sc[j][2 * rr + 1] = -1e30f;
                }
            }
        }

        float alpha[2];
#pragma unroll
        for (int rr = 0; rr < 2; rr++) {
            float tm = -1e30f;
#pragma unroll
            for (int j = 0; j < 8; j++)
                tm = fmaxf(tm, fmaxf(sc[j][2 * rr], sc[j][2 * rr + 1]));
            tm = fmaxf(tm, __shfl_xor_sync(0xffffffffu, tm, 1));
            tm = fmaxf(tm, __shfl_xor_sync(0xffffffffu, tm, 2));
            const float mn = fmaxf(m_i[rr], tm);
            alpha[rr] = __expf(m_i[rr] - mn);
            m_i[rr] = mn;
            float rs = 0.f;
#pragma unroll
            for (int j = 0; j < 8; j++) {
                float p0 = __expf(sc[j][2 * rr]     - mn);
                float p1 = __expf(sc[j][2 * rr + 1] - mn);
                sc[j][2 * rr] = p0; sc[j][2 * rr + 1] = p1;
                rs += p0 + p1;
            }
            rs += __shfl_xor_sync(0xffffffffu, rs, 1);
            rs += __shfl_xor_sync(0xffffffffu, rs, 2);
            l_i[rr] = l_i[rr] * alpha[rr] + rs;
        }
#pragma unroll
        for (int nn = 0; nn < 8; nn++) {
            out[nn][0] *= alpha[0]; out[nn][1] *= alpha[0];
            out[nn][2] *= alpha[1]; out[nn][3] *= alpha[1];
        }

        // PV: single fp16 pass
#pragma unroll
        for (int kk = 0; kk < 4; kk++) {
            uint32_t ph[4];
            ph[0] = packh2(sc[2 * kk][0],     sc[2 * kk][1]);
            ph[1] = packh2(sc[2 * kk][2],     sc[2 * kk][3]);
            ph[2] = packh2(sc[2 * kk + 1][0], sc[2 * kk + 1][1]);
            ph[3] = packh2(sc[2 * kk + 1][2], sc[2 * kk + 1][3]);
#pragma unroll
            for (int np = 0; np < 4; np++) {
                uint32_t off = swz((kk * 16 + v_row) * 128 + np * 32 + v_cb);
                uint32_t vh[4];
                ldm4t(vh[0], vh[1], vh[2], vh[3], sV + off);
                mma16816h(out[2 * np],     ph, &vh[0]);
                mma16816h(out[2 * np + 1], ph, &vh[2]);
            }
        }

        bufc = (bufc == 2) ? 0 : bufc + 1;
        bufp = (bufp == 2) ? 0 : bufp + 1;
    }

    // epilogue: O = out / l, bf16 hi/lo for the accurate proj GEMM
    const int b = bh >> 4;
    const int h = bh & 15;
    const float inv0 = 1.0f / l_i[0];
    const float inv1 = 1.0f / l_i[1];
#pragma unroll
    for (int nn = 0; nn < 8; nn++) {
        const int col = h * 64 + nn * 8 + 2 * (lid & 3);
#pragma unroll
        for (int rr = 0; rr < 2; rr++) {
            const int row = q0 + wid * 16 + (lid >> 2) + rr * 8;
            const float inv = rr ? inv1 : inv0;
            uint32_t hp, lp;
            split2(out[nn][2 * rr] * inv, out[nn][2 * rr + 1] * inv, hp, lp);
            const size_t o = ((size_t)b * S_ + row) * D_ + col;
            *(uint32_t*)(g_Ohi + o) = hp;
            *(uint32_t*)(g_Olo + o) = lp;
        }
    }
}

// ---------------------------------------------------------------------------
// Launch
// ---------------------------------------------------------------------------
extern "C" void kernel_launch(void* const* d_in, const int* in_sizes, int n_in,
                              void* d_out, int out_size)
{
    const float* x     = (const float*)d_in[0];
    const float* Wqkv  = (const float*)d_in[1];
    const float* bqkv  = (const float*)d_in[2];
    const float* Wproj = (const float*)d_in[3];
    const float* bproj = (const float*)d_in[4];
    float* out = (float*)d_out;

    cudaFuncSetAttribute(gemm_mma_kernel<0>,
                         cudaFuncAttributeMaxDynamicSharedMemorySize, GEMM_DSMEM);
    cudaFuncSetAttribute(gemm_mma_kernel<1>,
                         cudaFuncAttributeMaxDynamicSharedMemorySize, GEMM_DSMEM);
    cudaFuncSetAttribute(flash_mma_kernel,
                         cudaFuncAttributeMaxDynamicSharedMemorySize, FLASH_DSMEM);

    split_kernel<<<4096, 256>>>(x, BS_ * D_);
    tsplit_kernel<0><<<dim3(N3D_ / 32, D_ / 32), dim3(32, 8)>>>(Wqkv, D_, N3D_);
    tsplit_kernel<1><<<dim3(D_ / 32, D_ / 32), dim3(32, 8)>>>(Wproj, D_, D_);

    gemm_mma_kernel<0><<<dim3(N3D_ / 128, BS_ / 256), 256, GEMM_DSMEM>>>(bqkv, nullptr);

    flash_mma_kernel<<<dim3(S_ / FBM, B_ * H_), 256, FLASH_DSMEM>>>();

    gemm_mma_kernel<1><<<dim3(D_ / 128, BS_ / 256), 256, GEMM_DSMEM>>>(bproj, out);
}

// round 10
// speedup vs baseline: 1.8212x; 1.3986x over previous
#include <cuda_runtime.h>
#include <cuda_bf16.h>
#include <cuda_fp16.h>
#include <cstdint>

// Problem constants
#define B_  2
#define S_  2048
#define D_  1024
#define H_  16
#define DH_ 64
#define BS_ (B_ * S_)        // 4096
#define N3D_ (3 * D_)        // 3072

// ---------------------------------------------------------------------------
// Scratch (allocation-free: __device__ globals)
// ---------------------------------------------------------------------------
__device__ __align__(128) __half g_Qh[B_ * H_ * S_ * DH_];  // scaled 0.125
__device__ __align__(128) __half g_Kh[B_ * H_ * S_ * DH_];
__device__ __align__(128) __half g_Vh[B_ * H_ * S_ * DH_];

__device__ __align__(128) __half g_xh[BS_ * D_];            // x fp16 [4096,1024]
__device__ __align__(128) __half g_WqTh[N3D_ * D_];         // W_qkv^T fp16 [3072,1024]
__device__ __align__(128) __nv_bfloat16 g_WpT_hi[D_ * D_];  // W_proj^T bf16 hi/lo
__device__ __align__(128) __nv_bfloat16 g_WpT_lo[D_ * D_];
__device__ __align__(128) __nv_bfloat16 g_Ohi[BS_ * D_];    // attention out hi/lo
__device__ __align__(128) __nv_bfloat16 g_Olo[BS_ * D_];

// ---------------------------------------------------------------------------
// Base-ISA helpers
// ---------------------------------------------------------------------------
__device__ __forceinline__ uint32_t smem_u32(const void* p) {
    uint32_t a;
    asm("{ .reg .u64 t; cvta.to.shared.u64 t, %1; cvt.u32.u64 %0, t; }"
        : "=r"(a) : "l"(p));
    return a;
}
__device__ __forceinline__ uint32_t swz(uint32_t b) { return b ^ ((b >> 3) & 0x70); }

__device__ __forceinline__ void ldm4(uint32_t& r0, uint32_t& r1, uint32_t& r2,
                                     uint32_t& r3, uint32_t a) {
    asm volatile("ldmatrix.sync.aligned.m8n8.x4.shared.b16 {%0,%1,%2,%3},[%4];"
                 : "=r"(r0), "=r"(r1), "=r"(r2), "=r"(r3) : "r"(a));
}
__device__ __forceinline__ void ldm4t(uint32_t& r0, uint32_t& r1, uint32_t& r2,
                                      uint32_t& r3, uint32_t a) {
    asm volatile("ldmatrix.sync.aligned.m8n8.x4.trans.shared.b16 {%0,%1,%2,%3},[%4];"
                 : "=r"(r0), "=r"(r1), "=r"(r2), "=r"(r3) : "r"(a));
}
__device__ __forceinline__ void mma16816(float* d, const uint32_t* a,
                                         const uint32_t* b) {
    asm volatile(
        "mma.sync.aligned.m16n8k16.row.col.f32.bf16.bf16.f32 "
        "{%0,%1,%2,%3},{%4,%5,%6,%7},{%8,%9},{%0,%1,%2,%3};"
        : "+f"(d[0]), "+f"(d[1]), "+f"(d[2]), "+f"(d[3])
        : "r"(a[0]), "r"(a[1]), "r"(a[2]), "r"(a[3]), "r"(b[0]), "r"(b[1]));
}
__device__ __forceinline__ void mma16816h(float* d, const uint32_t* a,
                                          const uint32_t* b) {
    asm volatile(
        "mma.sync.aligned.m16n8k16.row.col.f32.f16.f16.f32 "
        "{%0,%1,%2,%3},{%4,%5,%6,%7},{%8,%9},{%0,%1,%2,%3};"
        : "+f"(d[0]), "+f"(d[1]), "+f"(d[2]), "+f"(d[3])
        : "r"(a[0]), "r"(a[1]), "r"(a[2]), "r"(a[3]), "r"(b[0]), "r"(b[1]));
}
__device__ __forceinline__ void cp16(uint32_t dst, const void* src) {
    asm volatile("cp.async.cg.shared.global [%0],[%1],16;" :: "r"(dst), "l"(src));
}
#define CP_COMMIT() asm volatile("cp.async.commit_group;")

__device__ __forceinline__ void split2(float a, float b, uint32_t& hi, uint32_t& lo) {
    __nv_bfloat162 h = __floats2bfloat162_rn(a, b);
    hi = *(uint32_t*)&h;
    __nv_bfloat162 l = __floats2bfloat162_rn(a - __bfloat162float(h.x),
                                             b - __bfloat162float(h.y));
    lo = *(uint32_t*)&l;
}
__device__ __forceinline__ uint32_t packh2(float a, float b) {
    __half2 h = __floats2half2_rn(a, b);
    return *(uint32_t*)&h;
}

// ---------------------------------------------------------------------------
// Prep
// ---------------------------------------------------------------------------
__global__ void split_kernel(const float* __restrict__ x, int n)
{
    for (int i = blockIdx.x * blockDim.x + threadIdx.x; i < n;
         i += gridDim.x * blockDim.x)
        g_xh[i] = __float2half(x[i]);
}

// W_qkv [1024,3072] fp32 -> g_WqTh [3072,1024] fp16
__global__ void tsplit_h(const float* __restrict__ W, int K, int N)
{
    __shared__ float t[32][33];
    int n0 = blockIdx.x * 32, k0 = blockIdx.y * 32;
    int tx = threadIdx.x, ty = threadIdx.y;
#pragma unroll
    for (int r = 0; r < 32; r += 8)
        t[ty + r][tx] = W[(size_t)(k0 + ty + r) * N + n0 + tx];
    __syncthreads();
#pragma unroll
    for (int r = 0; r < 32; r += 8)
        g_WqTh[(size_t)(n0 + ty + r) * K + k0 + tx] = __float2half(t[tx][ty + r]);
}

// W_proj [1024,1024] fp32 -> g_WpT_{hi,lo} [1024,1024] bf16
__global__ void tsplit_bf(const float* __restrict__ W, int K, int N)
{
    __shared__ float t[32][33];
    int n0 = blockIdx.x * 32, k0 = blockIdx.y * 32;
    int tx = threadIdx.x, ty = threadIdx.y;
#pragma unroll
    for (int r = 0; r < 32; r += 8)
        t[ty + r][tx] = W[(size_t)(k0 + ty + r) * N + n0 + tx];
    __syncthreads();
#pragma unroll
    for (int r = 0; r < 32; r += 8) {
        float f = t[tx][ty + r];
        __nv_bfloat16 h = __float2bfloat16(f);
        size_t o = (size_t)(n0 + ty + r) * K + k0 + tx;
        g_WpT_hi[o] = h;
        g_WpT_lo[o] = __float2bfloat16(f - __bfloat162float(h));
    }
}

// ---------------------------------------------------------------------------
// Shared tile loader: ROWS x 64 elements (128B rows), ld = 1024 elements
// ---------------------------------------------------------------------------
template <int ROWS, typename T>
__device__ __forceinline__ void cp_tileR(uint32_t sdst, const T* __restrict__ g,
                                         int row0, int k0, int tid)
{
#pragma unroll
    for (int it = 0; it < ROWS / 32; it++) {
        int idx = tid + it * 256;
        int row = idx >> 3;
        int c   = idx & 7;
        cp16(sdst + swz(row * 128 + c * 16),
             g + (size_t)(row0 + row) * 1024 + k0 + c * 8);
    }
}

// ---------------------------------------------------------------------------
// QKV GEMM: fp16 SINGLE-PASS mma.sync. 256x128 CTA tile, 8 warps (4x2),
// 64x64 warp tile, K-chunk 64, 2-stage double buffer (48KB/stage).
// Writes g_Qh/g_Kh/g_Vh fp16 (+bias, Q scaled 0.125).
// ---------------------------------------------------------------------------
#define QA_BYTES (256 * 64 * 2)              // 32768
#define QB_BYTES (128 * 64 * 2)              // 16384
#define QSTAGE   (QA_BYTES + QB_BYTES)       // 49152
#define QKV_DSMEM (2 * QSTAGE)               // 98304

__global__ void __launch_bounds__(256) gemm_qkv_h(const float* __restrict__ bias)
{
    constexpr int nkc = D_ / 64;    // 16
    extern __shared__ char dsm[];
    const uint32_t sb0 = smem_u32(dsm);

    const int tid = threadIdx.x;
    const int wid = tid >> 5;
    const int lid = tid & 31;
    const int wm = wid >> 1;        // 0..3
    const int wn = wid & 1;         // 0..1
    const int m0 = blockIdx.y * 256;
    const int n0 = blockIdx.x * 128;

    const int a_row = (lid & 7) + ((lid >> 3) & 1) * 8;
    const int a_kb  = (lid >> 4) * 16;
    const int b_row = (lid & 7) + ((lid >> 4) & 1) * 8;
    const int b_kb  = ((lid >> 3) & 1) * 16;

    float acc[4][8][4];
#pragma unroll
    for (int i = 0; i < 4; i++)
#pragma unroll
        for (int j = 0; j < 8; j++)
#pragma unroll
            for (int r = 0; r < 4; r++) acc[i][j][r] = 0.f;

    {
        cp_tileR<256>(sb0 + 0,        g_xh,   m0, 0, tid);
        cp_tileR<128>(sb0 + QA_BYTES, g_WqTh, n0, 0, tid);
        CP_COMMIT();
    }

    for (int kc = 0; kc < nkc; kc++) {
        if (kc + 1 < nkc) {
            uint32_t sb = sb0 + ((kc + 1) & 1) * QSTAGE;
            const int k0 = (kc + 1) * 64;
            cp_tileR<256>(sb + 0,        g_xh,   m0, k0, tid);
            cp_tileR<128>(sb + QA_BYTES, g_WqTh, n0, k0, tid);
            CP_COMMIT();
            asm volatile("cp.async.wait_group 1;");
        } else {
            asm volatile("cp.async.wait_group 0;");
        }
        __syncthreads();

        const uint32_t sb = sb0 + (kc & 1) * QSTAGE;
        const uint32_t sA = sb;
        const uint32_t sB = sb + QA_BYTES;

#pragma unroll
        for (int ks = 0; ks < 4; ks++) {
            uint32_t ah[4][4], bh[8][2];
#pragma unroll
            for (int i = 0; i < 4; i++) {
                uint32_t off = swz((wm * 64 + i * 16 + a_row) * 128 + ks * 32 + a_kb);
                ldm4(ah[i][0], ah[i][1], ah[i][2], ah[i][3], sA + off);
            }
#pragma unroll
            for (int p = 0; p < 4; p++) {
                uint32_t off = swz((wn * 64 + p * 16 + b_row) * 128 + ks * 32 + b_kb);
                ldm4(bh[2 * p][0], bh[2 * p][1], bh[2 * p + 1][0],
                     bh[2 * p + 1][1], sB + off);
            }
#pragma unroll
            for (int i = 0; i < 4; i++)
#pragma unroll
                for (int j = 0; j < 8; j++)
                    mma16816h(acc[i][j], ah[i], bh[j]);
        }
        __syncthreads();
    }

    const int which = n0 >> 10;   // 0=Q, 1=K, 2=V (constant per CTA)
#pragma unroll
    for (int i = 0; i < 4; i++) {
#pragma unroll
        for (int j = 0; j < 8; j++) {
            const int n = n0 + wn * 64 + j * 8 + (lid & 3) * 2;
            const float b0 = __ldg(&bias[n]);
            const float b1 = __ldg(&bias[n + 1]);
#pragma unroll
            for (int rr = 0; rr < 2; rr++) {
                const int m = m0 + wm * 64 + i * 16 + (lid >> 2) + rr * 8;
                float v0 = acc[i][j][rr * 2 + 0] + b0;
                float v1 = acc[i][j][rr * 2 + 1] + b1;
                const int b = m >> 11, s = m & 2047;
                const int rem = n & 1023, h = rem >> 6, d = rem & 63;
                const size_t o = (((size_t)(b * H_ + h) << 11) + s) * DH_ + d;
                if (which == 0) { v0 *= 0.125f; v1 *= 0.125f; }
                const uint32_t hp = packh2(v0, v1);
                if (which == 0)      *(uint32_t*)(g_Qh + o) = hp;
                else if (which == 1) *(uint32_t*)(g_Kh + o) = hp;
                else                 *(uint32_t*)(g_Vh + o) = hp;
            }
        }
    }
}

// ---------------------------------------------------------------------------
// Proj GEMM: bf16 hi/lo 3-pass (round-8 structure). 256x128 CTA tile,
// 8 warps (4x2), 64x64 warp tile, K-chunk 64, 2-stage double buffer.
// ---------------------------------------------------------------------------
#define A_BYTES (256 * 64 * 2)
#define Bn_BYTES (128 * 64 * 2)
#define STAGE_BYTES (2 * A_BYTES + 2 * Bn_BYTES)   // 98304
#define GEMM_DSMEM (2 * STAGE_BYTES)               // 196608

__global__ void __launch_bounds__(256) gemm_proj_kernel(
    const float* __restrict__ bias, float* __restrict__ Cout)
{
    constexpr int N = D_;
    constexpr int nkc = D_ / 64;
    extern __shared__ char dsm[];
    const uint32_t sb0 = smem_u32(dsm);

    const int tid = threadIdx.x;
    const int wid = tid >> 5;
    const int lid = tid & 31;
    const int wm = wid >> 1;
    const int wn = wid & 1;
    const int m0 = blockIdx.y * 256;
    const int n0 = blockIdx.x * 128;

    const int a_row = (lid & 7) + ((lid >> 3) & 1) * 8;
    const int a_kb  = (lid >> 4) * 16;
    const int b_row = (lid & 7) + ((lid >> 4) & 1) * 8;
    const int b_kb  = ((lid >> 3) & 1) * 16;

    float acc[4][8][4];
#pragma unroll
    for (int i = 0; i < 4; i++)
#pragma unroll
        for (int j = 0; j < 8; j++)
#pragma unroll
            for (int r = 0; r < 4; r++) acc[i][j][r] = 0.f;

    {
        cp_tileR<256>(sb0 + 0,                       g_Ohi,    m0, 0, tid);
        cp_tileR<256>(sb0 + A_BYTES,                 g_Olo,    m0, 0, tid);
        cp_tileR<128>(sb0 + 2 * A_BYTES,             g_WpT_hi, n0, 0, tid);
        cp_tileR<128>(sb0 + 2 * A_BYTES + Bn_BYTES,  g_WpT_lo, n0, 0, tid);
        CP_COMMIT();
    }

    for (int kc = 0; kc < nkc; kc++) {
        if (kc + 1 < nkc) {
            uint32_t sb = sb0 + ((kc + 1) & 1) * STAGE_BYTES;
            const int k0 = (kc + 1) * 64;
            cp_tileR<256>(sb + 0,                      g_Ohi,    m0, k0, tid);
            cp_tileR<256>(sb + A_BYTES,                g_Olo,    m0, k0, tid);
            cp_tileR<128>(sb + 2 * A_BYTES,            g_WpT_hi, n0, k0, tid);
            cp_tileR<128>(sb + 2 * A_BYTES + Bn_BYTES, g_WpT_lo, n0, k0, tid);
            CP_COMMIT();
            asm volatile("cp.async.wait_group 1;");
        } else {
            asm volatile("cp.async.wait_group 0;");
        }
        __syncthreads();

        const uint32_t sb = sb0 + (kc & 1) * STAGE_BYTES;
        const uint32_t sAhi = sb;
        const uint32_t sAlo = sb + A_BYTES;
        const uint32_t sBhi = sb + 2 * A_BYTES;
        const uint32_t sBlo = sb + 2 * A_BYTES + Bn_BYTES;

#pragma unroll
        for (int ks = 0; ks < 4; ks++) {
            uint32_t ahi[4][4], alo[4][4], bhi[8][2], blo[8][2];
#pragma unroll
            for (int i = 0; i < 4; i++) {
                uint32_t off = swz((wm * 64 + i * 16 + a_row) * 128 + ks * 32 + a_kb);
                ldm4(ahi[i][0], ahi[i][1], ahi[i][2], ahi[i][3], sAhi + off);
                ldm4(alo[i][0], alo[i][1], alo[i][2], alo[i][3], sAlo + off);
            }
#pragma unroll
            for (int p = 0; p < 4; p++) {
                uint32_t off = swz((wn * 64 + p * 16 + b_row) * 128 + ks * 32 + b_kb);
                ldm4(bhi[2 * p][0], bhi[2 * p][1], bhi[2 * p + 1][0],
                     bhi[2 * p + 1][1], sBhi + off);
                ldm4(blo[2 * p][0], blo[2 * p][1], blo[2 * p + 1][0],
                     blo[2 * p + 1][1], sBlo + off);
            }
#pragma unroll
            for (int i = 0; i < 4; i++)
#pragma unroll
                for (int j = 0; j < 8; j++) {
                    mma16816(acc[i][j], ahi[i], bhi[j]);
                    mma16816(acc[i][j], ahi[i], blo[j]);
                    mma16816(acc[i][j], alo[i], bhi[j]);
                }
        }
        __syncthreads();
    }

#pragma unroll
    for (int i = 0; i < 4; i++) {
#pragma unroll
        for (int j = 0; j < 8; j++) {
            const int n = n0 + wn * 64 + j * 8 + (lid & 3) * 2;
            const float b0 = __ldg(&bias[n]);
            const float b1 = __ldg(&bias[n + 1]);
#pragma unroll
            for (int rr = 0; rr < 2; rr++) {
                const int m = m0 + wm * 64 + i * 16 + (lid >> 2) + rr * 8;
                *(float2*)(Cout + (size_t)m * N + n) =
                    make_float2(acc[i][j][rr * 2 + 0] + b0,
                                acc[i][j][rr * 2 + 1] + b1);
            }
        }
    }
}

// ---------------------------------------------------------------------------
// Flash attention, fp16 single-pass (round-9, unchanged).
// ---------------------------------------------------------------------------
#define FBM 128
#define FBN 64
#define FK_BYTES (FBN * 128)            // 8192
#define FSTAGE   (2 * FK_BYTES)          // 16384
#define FLASH_DSMEM (3 * FSTAGE)         // 49152

__device__ __forceinline__ void cp_ftile(uint32_t sdst,
                                         const __half* __restrict__ g,
                                         int tid)
{
#pragma unroll
    for (int it = 0; it < 2; it++) {
        int idx = tid + it * 256;
        int row = idx >> 3;
        int c   = idx & 7;
        cp16(sdst + swz(row * 128 + c * 16), g + (size_t)row * 64 + c * 8);
    }
}

__global__ void __launch_bounds__(256) flash_mma_kernel()
{
    extern __shared__ char fsm[];
    const uint32_t sStage = smem_u32(fsm);

    const int tid = threadIdx.x;
    const int wid = tid >> 5;
    const int lid = tid & 31;
    const int qt = blockIdx.x;
    const int bh = blockIdx.y;
    const int q0 = qt * FBM;
    const int nkt = 2 * qt + 2;

    const __half* Qg = g_Qh + ((size_t)bh * S_ + q0) * DH_;
    const __half* Kg = g_Kh + (size_t)bh * S_ * DH_;
    const __half* Vg = g_Vh + (size_t)bh * S_ * DH_;

#pragma unroll
    for (int it = 0; it < 4; it++) {
        int idx = tid + it * 256;
        int row = idx >> 3;
        int c   = idx & 7;
        cp16(sStage + swz(row * 128 + c * 16), Qg + (size_t)row * 64 + c * 8);
    }
    CP_COMMIT();
    asm volatile("cp.async.wait_group 0;");
    __syncthreads();

    const int a_row = (lid & 7) + ((lid >> 3) & 1) * 8;
    const int a_kb  = (lid >> 4) * 16;
    uint32_t qh[4][4];
#pragma unroll
    for (int ks = 0; ks < 4; ks++) {
        uint32_t off = swz((wid * 16 + a_row) * 128 + ks * 32 + a_kb);
        ldm4(qh[ks][0], qh[ks][1], qh[ks][2], qh[ks][3], sStage + off);
    }
    __syncthreads();

#pragma unroll
    for (int s = 0; s < 2; s++) {
        uint32_t sb = sStage + s * FSTAGE;
        const size_t koff = (size_t)s * FBN * DH_;
        cp_ftile(sb + 0,        Kg + koff, tid);
        cp_ftile(sb + FK_BYTES, Vg + koff, tid);
        CP_COMMIT();
    }

    const int b_row = (lid & 7) + ((lid >> 4) & 1) * 8;
    const int b_kb  = ((lid >> 3) & 1) * 16;
    const int v_row = (lid & 7) + ((lid >> 3) & 1) * 8;
    const int v_cb  = ((lid >> 4) & 1) * 16;

    float m_i[2] = {-1e30f, -1e30f};
    float l_i[2] = {0.f, 0.f};
    float out[8][4];
#pragma unroll
    for (int nn = 0; nn < 8; nn++)
#pragma unroll
        for (int r = 0; r < 4; r++) out[nn][r] = 0.f;

    int bufc = 0;
    int bufp = 2;
    for (int kt = 0; kt < nkt; kt++) {
        if (kt + 1 < nkt) { asm volatile("cp.async.wait_group 1;"); }
        else              { asm volatile("cp.async.wait_group 0;"); }
        __syncthreads();

        if (kt + 2 < nkt) {
            uint32_t sb2 = sStage + bufp * FSTAGE;
            const size_t koff = (size_t)(kt + 2) * FBN * DH_;
            cp_ftile(sb2 + 0,        Kg + koff, tid);
            cp_ftile(sb2 + FK_BYTES, Vg + koff, tid);
            CP_COMMIT();
        }

        const uint32_t sb = sStage + bufc * FSTAGE;
        const uint32_t sK = sb;
        const uint32_t sV = sb + FK_BYTES;

        float sc[8][4];
#pragma unroll
        for (int j = 0; j < 8; j++)
#pragma unroll
            for (int r = 0; r < 4; r++) sc[j][r] = 0.f;

#pragma unroll
        for (int jp = 0; jp < 4; jp++) {
#pragma unroll
            for (int ks = 0; ks < 4; ks++) {
                uint32_t off = swz((jp * 16 + b_row) * 128 + ks * 32 + b_kb);
                uint32_t kh[4];
                ldm4(kh[0], kh[1], kh[2], kh[3], sK + off);
                mma16816h(sc[2 * jp],     qh[ks], &kh[0]);
                mma16816h(sc[2 * jp + 1], qh[ks], &kh[2]);
            }
        }

        if (kt >= nkt - 2) {
            const int k0g = kt * FBN;
            const int rbase = q0 + wid * 16 + (lid >> 2);
#pragma unroll
            for (int j = 0; j < 8; j++) {
                const int cbase = k0g + j * 8 + 2 * (lid & 3);
#pragma unroll
                for (int rr = 0; rr < 2; rr++) {
                    const int row = rbase + rr * 8;
                    if (cbase > row)     sc[j][2 * rr]     = -1e30f;
                    if (cbase + 1 > row) sc[j][2 * rr + 1] = -1e30f;
                }
            }
        }

        float alpha[2];
#pragma unroll
        for (int rr = 0; rr < 2; rr++) {
            float tm = -1e30f;
#pragma unroll
            for (int j = 0; j < 8; j++)
                tm = fmaxf(tm, fmaxf(sc[j][2 * rr], sc[j][2 * rr + 1]));
            tm = fmaxf(tm, __shfl_xor_sync(0xffffffffu, tm, 1));
            tm = fmaxf(tm, __shfl_xor_sync(0xffffffffu, tm, 2));
            const float mn = fmaxf(m_i[rr], tm);
            alpha[rr] = __expf(m_i[rr] - mn);
            m_i[rr] = mn;
            float rs = 0.f;
#pragma unroll
            for (int j = 0; j < 8; j++) {
                float p0 = __expf(sc[j][2 * rr]     - mn);
                float p1 = __expf(sc[j][2 * rr + 1] - mn);
                sc[j][2 * rr] = p0; sc[j][2 * rr + 1] = p1;
                rs += p0 + p1;
            }
            rs += __shfl_xor_sync(0xffffffffu, rs, 1);
            rs += __shfl_xor_sync(0xffffffffu, rs, 2);
            l_i[rr] = l_i[rr] * alpha[rr] + rs;
        }
#pragma unroll
        for (int nn = 0; nn < 8; nn++) {
            out[nn][0] *= alpha[0]; out[nn][1] *= alpha[0];
            out[nn][2] *= alpha[1]; out[nn][3] *= alpha[1];
        }

#pragma unroll
        for (int kk = 0; kk < 4; kk++) {
            uint32_t ph[4];
            ph[0] = packh2(sc[2 * kk][0],     sc[2 * kk][1]);
            ph[1] = packh2(sc[2 * kk][2],     sc[2 * kk][3]);
            ph[2] = packh2(sc[2 * kk + 1][0], sc[2 * kk + 1][1]);
            ph[3] = packh2(sc[2 * kk + 1][2], sc[2 * kk + 1][3]);
#pragma unroll
            for (int np = 0; np < 4; np++) {
                uint32_t off = swz((kk * 16 + v_row) * 128 + np * 32 + v_cb);
                uint32_t vh[4];
                ldm4t(vh[0], vh[1], vh[2], vh[3], sV + off);
                mma16816h(out[2 * np],     ph, &vh[0]);
                mma16816h(out[2 * np + 1], ph, &vh[2]);
            }
        }

        bufc = (bufc == 2) ? 0 : bufc + 1;
        bufp = (bufp == 2) ? 0 : bufp + 1;
    }

    const int b = bh >> 4;
    const int h = bh & 15;
    const float inv0 = 1.0f / l_i[0];
    const float inv1 = 1.0f / l_i[1];
#pragma unroll
    for (int nn = 0; nn < 8; nn++) {
        const int col = h * 64 + nn * 8 + 2 * (lid & 3);
#pragma unroll
        for (int rr = 0; rr < 2; rr++) {
            const int row = q0 + wid * 16 + (lid >> 2) + rr * 8;
            const float inv = rr ? inv1 : inv0;
            uint32_t hp, lp;
            split2(out[nn][2 * rr] * inv, out[nn][2 * rr + 1] * inv, hp, lp);
            const size_t o = ((size_t)b * S_ + row) * D_ + col;
            *(uint32_t*)(g_Ohi + o) = hp;
            *(uint32_t*)(g_Olo + o) = lp;
        }
    }
}

// ---------------------------------------------------------------------------
// Launch
// ---------------------------------------------------------------------------
extern "C" void kernel_launch(void* const* d_in, const int* in_sizes, int n_in,
                              void* d_out, int out_size)
{
    const float* x     = (const float*)d_in[0];
    const float* Wqkv  = (const float*)d_in[1];
    const float* bqkv  = (const float*)d_in[2];
    const float* Wproj = (const float*)d_in[3];
    const float* bproj = (const float*)d_in[4];
    float* out = (float*)d_out;

    cudaFuncSetAttribute(gemm_qkv_h,
                         cudaFuncAttributeMaxDynamicSharedMemorySize, QKV_DSMEM);
    cudaFuncSetAttribute(gemm_proj_kernel,
                         cudaFuncAttributeMaxDynamicSharedMemorySize, GEMM_DSMEM);
    cudaFuncSetAttribute(flash_mma_kernel,
                         cudaFuncAttributeMaxDynamicSharedMemorySize, FLASH_DSMEM);

    split_kernel<<<4096, 256>>>(x, BS_ * D_);
    tsplit_h<<<dim3(N3D_ / 32, D_ / 32), dim3(32, 8)>>>(Wqkv, D_, N3D_);
    tsplit_bf<<<dim3(D_ / 32, D_ / 32), dim3(32, 8)>>>(Wproj, D_, D_);

    gemm_qkv_h<<<dim3(N3D_ / 128, BS_ / 256), 256, QKV_DSMEM>>>(bqkv);

    flash_mma_kernel<<<dim3(S_ / FBM, B_ * H_), 256, FLASH_DSMEM>>>();

    gemm_proj_kernel<<<dim3(D_ / 128, BS_ / 256), 256, GEMM_DSMEM>>>(bproj, out);
}

// round 11
// speedup vs baseline: 2.1324x; 1.1709x over previous
#include <cuda_runtime.h>
#include <cuda_fp16.h>
#include <cstdint>

// Problem constants
#define B_  2
#define S_  2048
#define D_  1024
#define H_  16
#define DH_ 64
#define BS_ (B_ * S_)        // 4096
#define N3D_ (3 * D_)        // 3072

// ---------------------------------------------------------------------------
// Scratch (allocation-free: __device__ globals) — all fp16 now
// ---------------------------------------------------------------------------
__device__ __align__(128) __half g_Qh[B_ * H_ * S_ * DH_];  // scaled 0.125
__device__ __align__(128) __half g_Kh[B_ * H_ * S_ * DH_];
__device__ __align__(128) __half g_Vh[B_ * H_ * S_ * DH_];
__device__ __align__(128) __half g_xh[BS_ * D_];            // x fp16
__device__ __align__(128) __half g_WqTh[N3D_ * D_];         // W_qkv^T fp16
__device__ __align__(128) __half g_WpTh[D_ * D_];           // W_proj^T fp16
__device__ __align__(128) __half g_Oh[BS_ * D_];            // attention out fp16

// ---------------------------------------------------------------------------
// Base-ISA helpers
// ---------------------------------------------------------------------------
__device__ __forceinline__ uint32_t smem_u32(const void* p) {
    uint32_t a;
    asm("{ .reg .u64 t; cvta.to.shared.u64 t, %1; cvt.u32.u64 %0, t; }"
        : "=r"(a) : "l"(p));
    return a;
}
__device__ __forceinline__ uint32_t swz(uint32_t b) { return b ^ ((b >> 3) & 0x70); }

__device__ __forceinline__ void ldm4(uint32_t& r0, uint32_t& r1, uint32_t& r2,
                                     uint32_t& r3, uint32_t a) {
    asm volatile("ldmatrix.sync.aligned.m8n8.x4.shared.b16 {%0,%1,%2,%3},[%4];"
                 : "=r"(r0), "=r"(r1), "=r"(r2), "=r"(r3) : "r"(a));
}
__device__ __forceinline__ void ldm4t(uint32_t& r0, uint32_t& r1, uint32_t& r2,
                                      uint32_t& r3, uint32_t a) {
    asm volatile("ldmatrix.sync.aligned.m8n8.x4.trans.shared.b16 {%0,%1,%2,%3},[%4];"
                 : "=r"(r0), "=r"(r1), "=r"(r2), "=r"(r3) : "r"(a));
}
__device__ __forceinline__ void mma16816h(float* d, const uint32_t* a,
                                          const uint32_t* b) {
    asm volatile(
        "mma.sync.aligned.m16n8k16.row.col.f32.f16.f16.f32 "
        "{%0,%1,%2,%3},{%4,%5,%6,%7},{%8,%9},{%0,%1,%2,%3};"
        : "+f"(d[0]), "+f"(d[1]), "+f"(d[2]), "+f"(d[3])
        : "r"(a[0]), "r"(a[1]), "r"(a[2]), "r"(a[3]), "r"(b[0]), "r"(b[1]));
}
__device__ __forceinline__ void cp16(uint32_t dst, const void* src) {
    asm volatile("cp.async.cg.shared.global [%0],[%1],16;" :: "r"(dst), "l"(src));
}
#define CP_COMMIT() asm volatile("cp.async.commit_group;")

__device__ __forceinline__ uint32_t packh2(float a, float b) {
    __half2 h = __floats2half2_rn(a, b);
    return *(uint32_t*)&h;
}

// ---------------------------------------------------------------------------
// Prep
// ---------------------------------------------------------------------------
__global__ void split_kernel(const float* __restrict__ x, int n)
{
    for (int i = blockIdx.x * blockDim.x + threadIdx.x; i < n;
         i += gridDim.x * blockDim.x)
        g_xh[i] = __float2half(x[i]);
}

// W [K,N] fp32 -> dst [N,K] fp16.  MODE 0: W_qkv -> g_WqTh, 1: W_proj -> g_WpTh
template <int MODE>
__global__ void tsplit_h(const float* __restrict__ W, int K, int N)
{
    __half* dst = (MODE == 0) ? g_WqTh : g_WpTh;
    __shared__ float t[32][33];
    int n0 = blockIdx.x * 32, k0 = blockIdx.y * 32;
    int tx = threadIdx.x, ty = threadIdx.y;
#pragma unroll
    for (int r = 0; r < 32; r += 8)
        t[ty + r][tx] = W[(size_t)(k0 + ty + r) * N + n0 + tx];
    __syncthreads();
#pragma unroll
    for (int r = 0; r < 32; r += 8)
        dst[(size_t)(n0 + ty + r) * K + k0 + tx] = __float2half(t[tx][ty + r]);
}

// ---------------------------------------------------------------------------
// Shared tile loader: ROWS x 64 fp16 (128B rows), ld = 1024 elements
// ---------------------------------------------------------------------------
template <int ROWS>
__device__ __forceinline__ void cp_tileR(uint32_t sdst, const __half* __restrict__ g,
                                         int row0, int k0, int tid)
{
#pragma unroll
    for (int it = 0; it < ROWS / 32; it++) {
        int idx = tid + it * 256;
        int row = idx >> 3;
        int c   = idx & 7;
        cp16(sdst + swz(row * 128 + c * 16),
             g + (size_t)(row0 + row) * 1024 + k0 + c * 8);
    }
}

// ---------------------------------------------------------------------------
// fp16 single-pass GEMM. 256x128 CTA tile, 8 warps (4x2), 64x64 warp tile,
// K-chunk 64, 2-stage double buffer (48KB/stage).
// MODE 0: QKV (A=x, B=WqT) -> scatter g_Qh/g_Kh/g_Vh (+bias, Q scaled)
// MODE 1: proj (A=O, B=WpT) -> Cout fp32 (+bias)
// ---------------------------------------------------------------------------
#define QA_BYTES (256 * 64 * 2)              // 32768
#define QB_BYTES (128 * 64 * 2)              // 16384
#define QSTAGE   (QA_BYTES + QB_BYTES)       // 49152
#define GEMM_DSMEM (2 * QSTAGE)              // 98304

template <int MODE>
__global__ void __launch_bounds__(256) gemm_h(
    const float* __restrict__ bias, float* __restrict__ Cout)
{
    constexpr int N = (MODE == 0) ? N3D_ : D_;
    constexpr int nkc = D_ / 64;    // 16
    extern __shared__ char dsm[];
    const uint32_t sb0 = smem_u32(dsm);

    const int tid = threadIdx.x;
    const int wid = tid >> 5;
    const int lid = tid & 31;
    const int wm = wid >> 1;        // 0..3
    const int wn = wid & 1;         // 0..1
    const int m0 = blockIdx.y * 256;
    const int n0 = blockIdx.x * 128;

    const __half* A = (MODE == 0) ? g_xh : g_Oh;
    const __half* Bm = (MODE == 0) ? g_WqTh : g_WpTh;

    const int a_row = (lid & 7) + ((lid >> 3) & 1) * 8;
    const int a_kb  = (lid >> 4) * 16;
    const int b_row = (lid & 7) + ((lid >> 4) & 1) * 8;
    const int b_kb  = ((lid >> 3) & 1) * 16;

    float acc[4][8][4];
#pragma unroll
    for (int i = 0; i < 4; i++)
#pragma unroll
        for (int j = 0; j < 8; j++)
#pragma unroll
            for (int r = 0; r < 4; r++) acc[i][j][r] = 0.f;

    {
        cp_tileR<256>(sb0 + 0,        A,  m0, 0, tid);
        cp_tileR<128>(sb0 + QA_BYTES, Bm, n0, 0, tid);
        CP_COMMIT();
    }

    for (int kc = 0; kc < nkc; kc++) {
        if (kc + 1 < nkc) {
            uint32_t sb = sb0 + ((kc + 1) & 1) * QSTAGE;
            const int k0 = (kc + 1) * 64;
            cp_tileR<256>(sb + 0,        A,  m0, k0, tid);
            cp_tileR<128>(sb + QA_BYTES, Bm, n0, k0, tid);
            CP_COMMIT();
            asm volatile("cp.async.wait_group 1;");
        } else {
            asm volatile("cp.async.wait_group 0;");
        }
        __syncthreads();

        const uint32_t sb = sb0 + (kc & 1) * QSTAGE;
        const uint32_t sA = sb;
        const uint32_t sB = sb + QA_BYTES;

#pragma unroll
        for (int ks = 0; ks < 4; ks++) {
            uint32_t ah[4][4], bh[8][2];
#pragma unroll
            for (int i = 0; i < 4; i++) {
                uint32_t off = swz((wm * 64 + i * 16 + a_row) * 128 + ks * 32 + a_kb);
                ldm4(ah[i][0], ah[i][1], ah[i][2], ah[i][3], sA + off);
            }
#pragma unroll
            for (int p = 0; p < 4; p++) {
                uint32_t off = swz((wn * 64 + p * 16 + b_row) * 128 + ks * 32 + b_kb);
                ldm4(bh[2 * p][0], bh[2 * p][1], bh[2 * p + 1][0],
                     bh[2 * p + 1][1], sB + off);
            }
#pragma unroll
            for (int i = 0; i < 4; i++)
#pragma unroll
                for (int j = 0; j < 8; j++)
                    mma16816h(acc[i][j], ah[i], bh[j]);
        }
        __syncthreads();
    }

#pragma unroll
    for (int i = 0; i < 4; i++) {
#pragma unroll
        for (int j = 0; j < 8; j++) {
            const int n = n0 + wn * 64 + j * 8 + (lid & 3) * 2;
            const float b0 = __ldg(&bias[n]);
            const float b1 = __ldg(&bias[n + 1]);
#pragma unroll
            for (int rr = 0; rr < 2; rr++) {
                const int m = m0 + wm * 64 + i * 16 + (lid >> 2) + rr * 8;
                float v0 = acc[i][j][rr * 2 + 0] + b0;
                float v1 = acc[i][j][rr * 2 + 1] + b1;
                if constexpr (MODE == 0) {
                    const int b = m >> 11, s = m & 2047;
                    const int rem = n & 1023, h = rem >> 6, d = rem & 63;
                    const size_t o = (((size_t)(b * H_ + h) << 11) + s) * DH_ + d;
                    const int which = n0 >> 10;
                    if (which == 0) { v0 *= 0.125f; v1 *= 0.125f; }
                    const uint32_t hp = packh2(v0, v1);
                    if (which == 0)      *(uint32_t*)(g_Qh + o) = hp;
                    else if (which == 1) *(uint32_t*)(g_Kh + o) = hp;
                    else                 *(uint32_t*)(g_Vh + o) = hp;
                } else {
                    *(float2*)(Cout + (size_t)m * N + n) = make_float2(v0, v1);
                }
            }
        }
    }
}

// ---------------------------------------------------------------------------
// Flash attention, fp16 single-pass (round-9 core; epilogue writes fp16 O).
// BM=128, BN=64, 8 warps * 16 rows, 3-stage pipeline (16KB/stage = 48KB).
// ---------------------------------------------------------------------------
#define FBM 128
#define FBN 64
#define FK_BYTES (FBN * 128)            // 8192
#define FSTAGE   (2 * FK_BYTES)          // 16384
#define FLASH_DSMEM (3 * FSTAGE)         // 49152

__device__ __forceinline__ void cp_ftile(uint32_t sdst,
                                         const __half* __restrict__ g,
                                         int tid)
{
#pragma unroll
    for (int it = 0; it < 2; it++) {
        int idx = tid + it * 256;
        int row = idx >> 3;
        int c   = idx & 7;
        cp16(sdst + swz(row * 128 + c * 16), g + (size_t)row * 64 + c * 8);
    }
}

__global__ void __launch_bounds__(256) flash_mma_kernel()
{
    extern __shared__ char fsm[];
    const uint32_t sStage = smem_u32(fsm);

    const int tid = threadIdx.x;
    const int wid = tid >> 5;
    const int lid = tid & 31;
    const int qt = blockIdx.x;
    const int bh = blockIdx.y;
    const int q0 = qt * FBM;
    const int nkt = 2 * qt + 2;

    const __half* Qg = g_Qh + ((size_t)bh * S_ + q0) * DH_;
    const __half* Kg = g_Kh + (size_t)bh * S_ * DH_;
    const __half* Vg = g_Vh + (size_t)bh * S_ * DH_;

#pragma unroll
    for (int it = 0; it < 4; it++) {
        int idx = tid + it * 256;
        int row = idx >> 3;
        int c   = idx & 7;
        cp16(sStage + swz(row * 128 + c * 16), Qg + (size_t)row * 64 + c * 8);
    }
    CP_COMMIT();
    asm volatile("cp.async.wait_group 0;");
    __syncthreads();

    const int a_row = (lid & 7) + ((lid >> 3) & 1) * 8;
    const int a_kb  = (lid >> 4) * 16;
    uint32_t qh[4][4];
#pragma unroll
    for (int ks = 0; ks < 4; ks++) {
        uint32_t off = swz((wid * 16 + a_row) * 128 + ks * 32 + a_kb);
        ldm4(qh[ks][0], qh[ks][1], qh[ks][2], qh[ks][3], sStage + off);
    }
    __syncthreads();

#pragma unroll
    for (int s = 0; s < 2; s++) {
        uint32_t sb = sStage + s * FSTAGE;
        const size_t koff = (size_t)s * FBN * DH_;
        cp_ftile(sb + 0,        Kg + koff, tid);
        cp_ftile(sb + FK_BYTES, Vg + koff, tid);
        CP_COMMIT();
    }

    const int b_row = (lid & 7) + ((lid >> 4) & 1) * 8;
    const int b_kb  = ((lid >> 3) & 1) * 16;
    const int v_row = (lid & 7) + ((lid >> 3) & 1) * 8;
    const int v_cb  = ((lid >> 4) & 1) * 16;

    float m_i[2] = {-1e30f, -1e30f};
    float l_i[2] = {0.f, 0.f};
    float out[8][4];
#pragma unroll
    for (int nn = 0; nn < 8; nn++)
#pragma unroll
        for (int r = 0; r < 4; r++) out[nn][r] = 0.f;

    int bufc = 0;
    int bufp = 2;
    for (int kt = 0; kt < nkt; kt++) {
        if (kt + 1 < nkt) { asm volatile("cp.async.wait_group 1;"); }
        else              { asm volatile("cp.async.wait_group 0;"); }
        __syncthreads();

        if (kt + 2 < nkt) {
            uint32_t sb2 = sStage + bufp * FSTAGE;
            const size_t koff = (size_t)(kt + 2) * FBN * DH_;
            cp_ftile(sb2 + 0,        Kg + koff, tid);
            cp_ftile(sb2 + FK_BYTES, Vg + koff, tid);
            CP_COMMIT();
        }

        const uint32_t sb = sStage + bufc * FSTAGE;
        const uint32_t sK = sb;
        const uint32_t sV = sb + FK_BYTES;

        float sc[8][4];
#pragma unroll
        for (int j = 0; j < 8; j++)
#pragma unroll
            for (int r = 0; r < 4; r++) sc[j][r] = 0.f;

#pragma unroll
        for (int jp = 0; jp < 4; jp++) {
#pragma unroll
            for (int ks = 0; ks < 4; ks++) {
                uint32_t off = swz((jp * 16 + b_row) * 128 + ks * 32 + b_kb);
                uint32_t kh[4];
                ldm4(kh[0], kh[1], kh[2], kh[3], sK + off);
                mma16816h(sc[2 * jp],     qh[ks], &kh[0]);
                mma16816h(sc[2 * jp + 1], qh[ks], &kh[2]);
            }
        }

        if (kt >= nkt - 2) {
            const int k0g = kt * FBN;
            const int rbase = q0 + wid * 16 + (lid >> 2);
#pragma unroll
            for (int j = 0; j < 8; j++) {
                const int cbase = k0g + j * 8 + 2 * (lid & 3);
#pragma unroll
                for (int rr = 0; rr < 2; rr++) {
                    const int row = rbase + rr * 8;
                    if (cbase > row)     sc[j][2 * rr]     = -1e30f;
                    if (cbase + 1 > row) sc[j][2 * rr + 1] = -1e30f;
                }
            }
        }

        float alpha[2];
#pragma unroll
        for (int rr = 0; rr < 2; rr++) {
            float tm = -1e30f;
#pragma unroll
            for (int j = 0; j < 8; j++)
                tm = fmaxf(tm, fmaxf(sc[j][2 * rr], sc[j][2 * rr + 1]));
            tm = fmaxf(tm, __shfl_xor_sync(0xffffffffu, tm, 1));
            tm = fmaxf(tm, __shfl_xor_sync(0xffffffffu, tm, 2));
            const float mn = fmaxf(m_i[rr], tm);
            alpha[rr] = __expf(m_i[rr] - mn);
            m_i[rr] = mn;
            float rs = 0.f;
#pragma unroll
            for (int j = 0; j < 8; j++) {
                float p0 = __expf(sc[j][2 * rr]     - mn);
                float p1 = __expf(sc[j][2 * rr + 1] - mn);
                sc[j][2 * rr] = p0; sc[j][2 * rr + 1] = p1;
                rs += p0 + p1;
            }
            rs += __shfl_xor_sync(0xffffffffu, rs, 1);
            rs += __shfl_xor_sync(0xffffffffu, rs, 2);
            l_i[rr] = l_i[rr] * alpha[rr] + rs;
        }
#pragma unroll
        for (int nn = 0; nn < 8; nn++) {
            out[nn][0] *= alpha[0]; out[nn][1] *= alpha[0];
            out[nn][2] *= alpha[1]; out[nn][3] *= alpha[1];
        }

#pragma unroll
        for (int kk = 0; kk < 4; kk++) {
            uint32_t ph[4];
            ph[0] = packh2(sc[2 * kk][0],     sc[2 * kk][1]);
            ph[1] = packh2(sc[2 * kk][2],     sc[2 * kk][3]);
            ph[2] = packh2(sc[2 * kk + 1][0], sc[2 * kk + 1][1]);
            ph[3] = packh2(sc[2 * kk + 1][2], sc[2 * kk + 1][3]);
#pragma unroll
            for (int np = 0; np < 4; np++) {
                uint32_t off = swz((kk * 16 + v_row) * 128 + np * 32 + v_cb);
                uint32_t vh[4];
                ldm4t(vh[0], vh[1], vh[2], vh[3], sV + off);
                mma16816h(out[2 * np],     ph, &vh[0]);
                mma16816h(out[2 * np + 1], ph, &vh[2]);
            }
        }

        bufc = (bufc == 2) ? 0 : bufc + 1;
        bufp = (bufp == 2) ? 0 : bufp + 1;
    }

    // epilogue: O = out / l -> fp16 (single array)
    const int b = bh >> 4;
    const int h = bh & 15;
    const float inv0 = 1.0f / l_i[0];
    const float inv1 = 1.0f / l_i[1];
#pragma unroll
    for (int nn = 0; nn < 8; nn++) {
        const int col = h * 64 + nn * 8 + 2 * (lid & 3);
#pragma unroll
        for (int rr = 0; rr < 2; rr++) {
            const int row = q0 + wid * 16 + (lid >> 2) + rr * 8;
            const float inv = rr ? inv1 : inv0;
            const size_t o = ((size_t)b * S_ + row) * D_ + col;
            *(uint32_t*)(g_Oh + o) =
                packh2(out[nn][2 * rr] * inv, out[nn][2 * rr + 1] * inv);
        }
    }
}

// ---------------------------------------------------------------------------
// Launch
// ---------------------------------------------------------------------------
extern "C" void kernel_launch(void* const* d_in, const int* in_sizes, int n_in,
                              void* d_out, int out_size)
{
    const float* x     = (const float*)d_in[0];
    const float* Wqkv  = (const float*)d_in[1];
    const float* bqkv  = (const float*)d_in[2];
    const float* Wproj = (const float*)d_in[3];
    const float* bproj = (const float*)d_in[4];
    float* out = (float*)d_out;

    cudaFuncSetAttribute(gemm_h<0>,
                         cudaFuncAttributeMaxDynamicSharedMemorySize, GEMM_DSMEM);
    cudaFuncSetAttribute(gemm_h<1>,
                         cudaFuncAttributeMaxDynamicSharedMemorySize, GEMM_DSMEM);
    cudaFuncSetAttribute(flash_mma_kernel,
                         cudaFuncAttributeMaxDynamicSharedMemorySize, FLASH_DSMEM);

    split_kernel<<<4096, 256>>>(x, BS_ * D_);
    tsplit_h<0><<<dim3(N3D_ / 32, D_ / 32), dim3(32, 8)>>>(Wqkv, D_, N3D_);
    tsplit_h<1><<<dim3(D_ / 32, D_ / 32), dim3(32, 8)>>>(Wproj, D_, D_);

    gemm_h<0><<<dim3(N3D_ / 128, BS_ / 256), 256, GEMM_DSMEM>>>(bqkv, nullptr);

    flash_mma_kernel<<<dim3(S_ / FBM, B_ * H_), 256, FLASH_DSMEM>>>();

    gemm_h<1><<<dim3(D_ / 128, BS_ / 256), 256, GEMM_DSMEM>>>(bproj, out);
}

// round 12
// speedup vs baseline: 2.2316x; 1.0465x over previous
#include <cuda_runtime.h>
#include <cuda_fp16.h>
#include <cstdint>

// Problem constants
#define B_  2
#define S_  2048
#define D_  1024
#define H_  16
#define DH_ 64
#define BS_ (B_ * S_)        // 4096
#define N3D_ (3 * D_)        // 3072

// ---------------------------------------------------------------------------
// Scratch (allocation-free: __device__ globals) — all fp16
// ---------------------------------------------------------------------------
__device__ __align__(128) __half g_Qh[B_ * H_ * S_ * DH_];  // scaled 0.125
__device__ __align__(128) __half g_Kh[B_ * H_ * S_ * DH_];
__device__ __align__(128) __half g_Vh[B_ * H_ * S_ * DH_];
__device__ __align__(128) __half g_xh[BS_ * D_];
__device__ __align__(128) __half g_WqTh[N3D_ * D_];
__device__ __align__(128) __half g_WpTh[D_ * D_];
__device__ __align__(128) __half g_Oh[BS_ * D_];

// ---------------------------------------------------------------------------
// Base-ISA helpers
// ---------------------------------------------------------------------------
__device__ __forceinline__ uint32_t smem_u32(const void* p) {
    uint32_t a;
    asm("{ .reg .u64 t; cvta.to.shared.u64 t, %1; cvt.u32.u64 %0, t; }"
        : "=r"(a) : "l"(p));
    return a;
}
__device__ __forceinline__ uint32_t swz(uint32_t b) { return b ^ ((b >> 3) & 0x70); }

__device__ __forceinline__ void ldm4(uint32_t& r0, uint32_t& r1, uint32_t& r2,
                                     uint32_t& r3, uint32_t a) {
    asm volatile("ldmatrix.sync.aligned.m8n8.x4.shared.b16 {%0,%1,%2,%3},[%4];"
                 : "=r"(r0), "=r"(r1), "=r"(r2), "=r"(r3) : "r"(a));
}
__device__ __forceinline__ void ldm4t(uint32_t& r0, uint32_t& r1, uint32_t& r2,
                                      uint32_t& r3, uint32_t a) {
    asm volatile("ldmatrix.sync.aligned.m8n8.x4.trans.shared.b16 {%0,%1,%2,%3},[%4];"
                 : "=r"(r0), "=r"(r1), "=r"(r2), "=r"(r3) : "r"(a));
}
__device__ __forceinline__ void mma16816h(float* d, const uint32_t* a,
                                          const uint32_t* b) {
    asm volatile(
        "mma.sync.aligned.m16n8k16.row.col.f32.f16.f16.f32 "
        "{%0,%1,%2,%3},{%4,%5,%6,%7},{%8,%9},{%0,%1,%2,%3};"
        : "+f"(d[0]), "+f"(d[1]), "+f"(d[2]), "+f"(d[3])
        : "r"(a[0]), "r"(a[1]), "r"(a[2]), "r"(a[3]), "r"(b[0]), "r"(b[1]));
}
__device__ __forceinline__ void cp16(uint32_t dst, const void* src) {
    asm volatile("cp.async.cg.shared.global [%0],[%1],16;" :: "r"(dst), "l"(src));
}
#define CP_COMMIT() asm volatile("cp.async.commit_group;")

__device__ __forceinline__ uint32_t packh2(float a, float b) {
    __half2 h = __floats2half2_rn(a, b);
    return *(uint32_t*)&h;
}

// ---------------------------------------------------------------------------
// Prep
// ---------------------------------------------------------------------------
__global__ void split_kernel(const float* __restrict__ x, int n)
{
    for (int i = blockIdx.x * blockDim.x + threadIdx.x; i < n;
         i += gridDim.x * blockDim.x)
        g_xh[i] = __float2half(x[i]);
}

template <int MODE>  // 0: W_qkv -> g_WqTh, 1: W_proj -> g_WpTh
__global__ void tsplit_h(const float* __restrict__ W, int K, int N)
{
    __half* dst = (MODE == 0) ? g_WqTh : g_WpTh;
    __shared__ float t[32][33];
    int n0 = blockIdx.x * 32, k0 = blockIdx.y * 32;
    int tx = threadIdx.x, ty = threadIdx.y;
#pragma unroll
    for (int r = 0; r < 32; r += 8)
        t[ty + r][tx] = W[(size_t)(k0 + ty + r) * N + n0 + tx];
    __syncthreads();
#pragma unroll
    for (int r = 0; r < 32; r += 8)
        dst[(size_t)(n0 + ty + r) * K + k0 + tx] = __float2half(t[tx][ty + r]);
}

// ---------------------------------------------------------------------------
// Tile loader (512 threads): ROWS x 64 fp16 (128B rows), ld = 1024 elements
// ---------------------------------------------------------------------------
template <int ROWS>
__device__ __forceinline__ void cp_tile512(uint32_t sdst,
                                           const __half* __restrict__ g,
                                           int row0, int k0, int tid)
{
#pragma unroll
    for (int it = 0; it < ROWS / 64; it++) {
        int idx = tid + it * 512;
        int row = idx >> 3;
        int c   = idx & 7;
        cp16(sdst + swz(row * 128 + c * 16),
             g + (size_t)(row0 + row) * 1024 + k0 + c * 8);
    }
}

// ---------------------------------------------------------------------------
// fp16 single-pass GEMM. 256x128 CTA tile, 16 warps (8x2), 32x64 warp tile,
// K-chunk 64, 2-stage double buffer (48KB/stage).
// MODE 0: QKV -> scatter g_Qh/g_Kh/g_Vh (+bias, Q scaled)
// MODE 1: proj -> Cout fp32 (+bias)
// ---------------------------------------------------------------------------
#define QA_BYTES (256 * 64 * 2)              // 32768
#define QB_BYTES (128 * 64 * 2)              // 16384
#define QSTAGE   (QA_BYTES + QB_BYTES)       // 49152
#define GEMM_DSMEM (2 * QSTAGE)              // 98304

template <int MODE>
__global__ void __launch_bounds__(512) gemm_h(
    const float* __restrict__ bias, float* __restrict__ Cout)
{
    constexpr int N = (MODE == 0) ? N3D_ : D_;
    constexpr int nkc = D_ / 64;    // 16
    extern __shared__ char dsm[];
    const uint32_t sb0 = smem_u32(dsm);

    const int tid = threadIdx.x;
    const int wid = tid >> 5;
    const int lid = tid & 31;
    const int wm = wid >> 1;        // 0..7 (32-row band)
    const int wn = wid & 1;         // 0..1 (64-col band)
    const int m0 = blockIdx.y * 256;
    const int n0 = blockIdx.x * 128;

    const __half* A  = (MODE == 0) ? g_xh : g_Oh;
    const __half* Bm = (MODE == 0) ? g_WqTh : g_WpTh;

    const int a_row = (lid & 7) + ((lid >> 3) & 1) * 8;
    const int a_kb  = (lid >> 4) * 16;
    const int b_row = (lid & 7) + ((lid >> 4) & 1) * 8;
    const int b_kb  = ((lid >> 3) & 1) * 16;

    float acc[2][8][4];
#pragma unroll
    for (int i = 0; i < 2; i++)
#pragma unroll
        for (int j = 0; j < 8; j++)
#pragma unroll
            for (int r = 0; r < 4; r++) acc[i][j][r] = 0.f;

    {
        cp_tile512<256>(sb0 + 0,        A,  m0, 0, tid);
        cp_tile512<128>(sb0 + QA_BYTES, Bm, n0, 0, tid);
        CP_COMMIT();
    }

    for (int kc = 0; kc < nkc; kc++) {
        if (kc + 1 < nkc) {
            uint32_t sb = sb0 + ((kc + 1) & 1) * QSTAGE;
            const int k0 = (kc + 1) * 64;
            cp_tile512<256>(sb + 0,        A,  m0, k0, tid);
            cp_tile512<128>(sb + QA_BYTES, Bm, n0, k0, tid);
            CP_COMMIT();
            asm volatile("cp.async.wait_group 1;");
        } else {
            asm volatile("cp.async.wait_group 0;");
        }
        __syncthreads();

        const uint32_t sb = sb0 + (kc & 1) * QSTAGE;
        const uint32_t sA = sb;
        const uint32_t sB = sb + QA_BYTES;

#pragma unroll
        for (int ks = 0; ks < 4; ks++) {
            uint32_t ah[2][4], bh[8][2];
#pragma unroll
            for (int i = 0; i < 2; i++) {
                uint32_t off = swz((wm * 32 + i * 16 + a_row) * 128 + ks * 32 + a_kb);
                ldm4(ah[i][0], ah[i][1], ah[i][2], ah[i][3], sA + off);
            }
#pragma unroll
            for (int p = 0; p < 4; p++) {
                uint32_t off = swz((wn * 64 + p * 16 + b_row) * 128 + ks * 32 + b_kb);
                ldm4(bh[2 * p][0], bh[2 * p][1], bh[2 * p + 1][0],
                     bh[2 * p + 1][1], sB + off);
            }
#pragma unroll
            for (int i = 0; i < 2; i++)
#pragma unroll
                for (int j = 0; j < 8; j++)
                    mma16816h(acc[i][j], ah[i], bh[j]);
        }
        __syncthreads();
    }

#pragma unroll
    for (int i = 0; i < 2; i++) {
#pragma unroll
        for (int j = 0; j < 8; j++) {
            const int n = n0 + wn * 64 + j * 8 + (lid & 3) * 2;
            const float b0 = __ldg(&bias[n]);
            const float b1 = __ldg(&bias[n + 1]);
#pragma unroll
            for (int rr = 0; rr < 2; rr++) {
                const int m = m0 + wm * 32 + i * 16 + (lid >> 2) + rr * 8;
                float v0 = acc[i][j][rr * 2 + 0] + b0;
                float v1 = acc[i][j][rr * 2 + 1] + b1;
                if constexpr (MODE == 0) {
                    const int b = m >> 11, s = m & 2047;
                    const int rem = n & 1023, h = rem >> 6, d = rem & 63;
                    const size_t o = (((size_t)(b * H_ + h) << 11) + s) * DH_ + d;
                    const int which = n0 >> 10;
                    if (which == 0) { v0 *= 0.125f; v1 *= 0.125f; }
                    const uint32_t hp = packh2(v0, v1);
                    if (which == 0)      *(uint32_t*)(g_Qh + o) = hp;
                    else if (which == 1) *(uint32_t*)(g_Kh + o) = hp;
                    else                 *(uint32_t*)(g_Vh + o) = hp;
                } else {
                    *(float2*)(Cout + (size_t)m * N + n) = make_float2(v0, v1);
                }
            }
        }
    }
}

// ---------------------------------------------------------------------------
// Flash attention, fp16 single-pass (unchanged from round 11).
// ---------------------------------------------------------------------------
#define FBM 128
#define FBN 64
#define FK_BYTES (FBN * 128)            // 8192
#define FSTAGE   (2 * FK_BYTES)          // 16384
#define FLASH_DSMEM (3 * FSTAGE)         // 49152

__device__ __forceinline__ void cp_ftile(uint32_t sdst,
                                         const __half* __restrict__ g,
                                         int tid)
{
#pragma unroll
    for (int it = 0; it < 2; it++) {
        int idx = tid + it * 256;
        int row = idx >> 3;
        int c   = idx & 7;
        cp16(sdst + swz(row * 128 + c * 16), g + (size_t)row * 64 + c * 8);
    }
}

__global__ void __launch_bounds__(256) flash_mma_kernel()
{
    extern __shared__ char fsm[];
    const uint32_t sStage = smem_u32(fsm);

    const int tid = threadIdx.x;
    const int wid = tid >> 5;
    const int lid = tid & 31;
    const int qt = blockIdx.x;
    const int bh = blockIdx.y;
    const int q0 = qt * FBM;
    const int nkt = 2 * qt + 2;

    const __half* Qg = g_Qh + ((size_t)bh * S_ + q0) * DH_;
    const __half* Kg = g_Kh + (size_t)bh * S_ * DH_;
    const __half* Vg = g_Vh + (size_t)bh * S_ * DH_;

#pragma unroll
    for (int it = 0; it < 4; it++) {
        int idx = tid + it * 256;
        int row = idx >> 3;
        int c   = idx & 7;
        cp16(sStage + swz(row * 128 + c * 16), Qg + (size_t)row * 64 + c * 8);
    }
    CP_COMMIT();
    asm volatile("cp.async.wait_group 0;");
    __syncthreads();

    const int a_row = (lid & 7) + ((lid >> 3) & 1) * 8;
    const int a_kb  = (lid >> 4) * 16;
    uint32_t qh[4][4];
#pragma unroll
    for (int ks = 0; ks < 4; ks++) {
        uint32_t off = swz((wid * 16 + a_row) * 128 + ks * 32 + a_kb);
        ldm4(qh[ks][0], qh[ks][1], qh[ks][2], qh[ks][3], sStage + off);
    }
    __syncthreads();

#pragma unroll
    for (int s = 0; s < 2; s++) {
        uint32_t sb = sStage + s * FSTAGE;
        const size_t koff = (size_t)s * FBN * DH_;
        cp_ftile(sb + 0,        Kg + koff, tid);
        cp_ftile(sb + FK_BYTES, Vg + koff, tid);
        CP_COMMIT();
    }

    const int b_row = (lid & 7) + ((lid >> 4) & 1) * 8;
    const int b_kb  = ((lid >> 3) & 1) * 16;
    const int v_row = (lid & 7) + ((lid >> 3) & 1) * 8;
    const int v_cb  = ((lid >> 4) & 1) * 16;

    float m_i[2] = {-1e30f, -1e30f};
    float l_i[2] = {0.f, 0.f};
    float out[8][4];
#pragma unroll
    for (int nn = 0; nn < 8; nn++)
#pragma unroll
        for (int r = 0; r < 4; r++) out[nn][r] = 0.f;

    int bufc = 0;
    int bufp = 2;
    for (int kt = 0; kt < nkt; kt++) {
        if (kt + 1 < nkt) { asm volatile("cp.async.wait_group 1;"); }
        else              { asm volatile("cp.async.wait_group 0;"); }
        __syncthreads();

        if (kt + 2 < nkt) {
            uint32_t sb2 = sStage + bufp * FSTAGE;
            const size_t koff = (size_t)(kt + 2) * FBN * DH_;
            cp_ftile(sb2 + 0,        Kg + koff, tid);
            cp_ftile(sb2 + FK_BYTES, Vg + koff, tid);
            CP_COMMIT();
        }

        const uint32_t sb = sStage + bufc * FSTAGE;
        const uint32_t sK = sb;
        const uint32_t sV = sb + FK_BYTES;

        float sc[8][4];
#pragma unroll
        for (int j = 0; j < 8; j++)
#pragma unroll
            for (int r = 0; r < 4; r++) sc[j][r] = 0.f;

#pragma unroll
        for (int jp = 0; jp < 4; jp++) {
#pragma unroll
            for (int ks = 0; ks < 4; ks++) {
                uint32_t off = swz((jp * 16 + b_row) * 128 + ks * 32 + b_kb);
                uint32_t kh[4];
                ldm4(kh[0], kh[1], kh[2], kh[3], sK + off);
                mma16816h(sc[2 * jp],     qh[ks], &kh[0]);
                mma16816h(sc[2 * jp + 1], qh[ks], &kh[2]);
            }
        }

        if (kt >= nkt - 2) {
            const int k0g = kt * FBN;
            const int rbase = q0 + wid * 16 + (lid >> 2);
#pragma unroll
            for (int j = 0; j < 8; j++) {
                const int cbase = k0g + j * 8 + 2 * (lid & 3);
#pragma unroll
                for (int rr = 0; rr < 2; rr++) {
                    const int row = rbase + rr * 8;
                    if (cbase > row)     sc[j][2 * rr]     = -1e30f;
                    if (cbase + 1 > row) sc[j][2 * rr + 1] = -1e30f;
                }
            }
        }

        float alpha[2];
#pragma unroll
        for (int rr = 0; rr < 2; rr++) {
            float tm = -1e30f;
#pragma unroll
            for (int j = 0; j < 8; j++)
                tm = fmaxf(tm, fmaxf(sc[j][2 * rr], sc[j][2 * rr + 1]));
            tm = fmaxf(tm, __shfl_xor_sync(0xffffffffu, tm, 1));
            tm = fmaxf(tm, __shfl_xor_sync(0xffffffffu, tm, 2));
            const float mn = fmaxf(m_i[rr], tm);
            alpha[rr] = __expf(m_i[rr] - mn);
            m_i[rr] = mn;
            float rs = 0.f;
#pragma unroll
            for (int j = 0; j < 8; j++) {
                float p0 = __expf(sc[j][2 * rr]     - mn);
                float p1 = __expf(sc[j][2 * rr + 1] - mn);
                sc[j][2 * rr] = p0; sc[j][2 * rr + 1] = p1;
                rs += p0 + p1;
            }
            rs += __shfl_xor_sync(0xffffffffu, rs, 1);
            rs += __shfl_xor_sync(0xffffffffu, rs, 2);
            l_i[rr] = l_i[rr] * alpha[rr] + rs;
        }
#pragma unroll
        for (int nn = 0; nn < 8; nn++) {
            out[nn][0] *= alpha[0]; out[nn][1] *= alpha[0];
            out[nn][2] *= alpha[1]; out[nn][3] *= alpha[1];
        }

#pragma unroll
        for (int kk = 0; kk < 4; kk++) {
            uint32_t ph[4];
            ph[0] = packh2(sc[2 * kk][0],     sc[2 * kk][1]);
            ph[1] = packh2(sc[2 * kk][2],     sc[2 * kk][3]);
            ph[2] = packh2(sc[2 * kk + 1][0], sc[2 * kk + 1][1]);
            ph[3] = packh2(sc[2 * kk + 1][2], sc[2 * kk + 1][3]);
#pragma unroll
            for (int np = 0; np < 4; np++) {
                uint32_t off = swz((kk * 16 + v_row) * 128 + np * 32 + v_cb);
                uint32_t vh[4];
                ldm4t(vh[0], vh[1], vh[2], vh[3], sV + off);
                mma16816h(out[2 * np],     ph, &vh[0]);
                mma16816h(out[2 * np + 1], ph, &vh[2]);
            }
        }

        bufc = (bufc == 2) ? 0 : bufc + 1;
        bufp = (bufp == 2) ? 0 : bufp + 1;
    }

    const int b = bh >> 4;
    const int h = bh & 15;
    const float inv0 = 1.0f / l_i[0];
    const float inv1 = 1.0f / l_i[1];
#pragma unroll
    for (int nn = 0; nn < 8; nn++) {
        const int col = h * 64 + nn * 8 + 2 * (lid & 3);
#pragma unroll
        for (int rr = 0; rr < 2; rr++) {
            const int row = q0 + wid * 16 + (lid >> 2) + rr * 8;
            const float inv = rr ? inv1 : inv0;
            const size_t o = ((size_t)b * S_ + row) * D_ + col;
            *(uint32_t*)(g_Oh + o) =
                packh2(out[nn][2 * rr] * inv, out[nn][2 * rr + 1] * inv);
        }
    }
}

// ---------------------------------------------------------------------------
// Launch
// ---------------------------------------------------------------------------
extern "C" void kernel_launch(void* const* d_in, const int* in_sizes, int n_in,
                              void* d_out, int out_size)
{
    const float* x     = (const float*)d_in[0];
    const float* Wqkv  = (const float*)d_in[1];
    const float* bqkv  = (const float*)d_in[2];
    const float* Wproj = (const float*)d_in[3];
    const float* bproj = (const float*)d_in[4];
    float* out = (float*)d_out;

    cudaFuncSetAttribute(gemm_h<0>,
                         cudaFuncAttributeMaxDynamicSharedMemorySize, GEMM_DSMEM);
    cudaFuncSetAttribute(gemm_h<1>,
                         cudaFuncAttributeMaxDynamicSharedMemorySize, GEMM_DSMEM);
    cudaFuncSetAttribute(flash_mma_kernel,
                         cudaFuncAttributeMaxDynamicSharedMemorySize, FLASH_DSMEM);

    split_kernel<<<4096, 256>>>(x, BS_ * D_);
    tsplit_h<0><<<dim3(N3D_ / 32, D_ / 32), dim3(32, 8)>>>(Wqkv, D_, N3D_);
    tsplit_h<1><<<dim3(D_ / 32, D_ / 32), dim3(32, 8)>>>(Wproj, D_, D_);

    gemm_h<0><<<dim3(N3D_ / 128, BS_ / 256), 512, GEMM_DSMEM>>>(bqkv, nullptr);

    flash_mma_kernel<<<dim3(S_ / FBM, B_ * H_), 256, FLASH_DSMEM>>>();

    gemm_h<1><<<dim3(D_ / 128, BS_ / 256), 512, GEMM_DSMEM>>>(bproj, out);
}

// round 13
// speedup vs baseline: 2.4062x; 1.0782x over previous
#include <cuda_runtime.h>
#include <cuda_fp16.h>
#include <cstdint>

// Problem constants
#define B_  2
#define S_  2048
#define D_  1024
#define H_  16
#define DH_ 64
#define BS_ (B_ * S_)        // 4096
#define N3D_ (3 * D_)        // 3072

// ---------------------------------------------------------------------------
// Scratch (allocation-free: __device__ globals) — all fp16
// ---------------------------------------------------------------------------
__device__ __align__(128) __half g_Qh[B_ * H_ * S_ * DH_];  // scaled 0.125
__device__ __align__(128) __half g_Kh[B_ * H_ * S_ * DH_];
__device__ __align__(128) __half g_Vh[B_ * H_ * S_ * DH_];
__device__ __align__(128) __half g_xh[BS_ * D_];
__device__ __align__(128) __half g_WqTh[N3D_ * D_];
__device__ __align__(128) __half g_WpTh[D_ * D_];
__device__ __align__(128) __half g_Oh[BS_ * D_];

// ---------------------------------------------------------------------------
// Base-ISA helpers
// ---------------------------------------------------------------------------
__device__ __forceinline__ uint32_t smem_u32(const void* p) {
    uint32_t a;
    asm("{ .reg .u64 t; cvta.to.shared.u64 t, %1; cvt.u32.u64 %0, t; }"
        : "=r"(a) : "l"(p));
    return a;
}
__device__ __forceinline__ uint32_t swz(uint32_t b) { return b ^ ((b >> 3) & 0x70); }

__device__ __forceinline__ void ldm4(uint32_t& r0, uint32_t& r1, uint32_t& r2,
                                     uint32_t& r3, uint32_t a) {
    asm volatile("ldmatrix.sync.aligned.m8n8.x4.shared.b16 {%0,%1,%2,%3},[%4];"
                 : "=r"(r0), "=r"(r1), "=r"(r2), "=r"(r3) : "r"(a));
}
__device__ __forceinline__ void ldm4t(uint32_t& r0, uint32_t& r1, uint32_t& r2,
                                      uint32_t& r3, uint32_t a) {
    asm volatile("ldmatrix.sync.aligned.m8n8.x4.trans.shared.b16 {%0,%1,%2,%3},[%4];"
                 : "=r"(r0), "=r"(r1), "=r"(r2), "=r"(r3) : "r"(a));
}
__device__ __forceinline__ void mma16816h(float* d, const uint32_t* a,
                                          const uint32_t* b) {
    asm volatile(
        "mma.sync.aligned.m16n8k16.row.col.f32.f16.f16.f32 "
        "{%0,%1,%2,%3},{%4,%5,%6,%7},{%8,%9},{%0,%1,%2,%3};"
        : "+f"(d[0]), "+f"(d[1]), "+f"(d[2]), "+f"(d[3])
        : "r"(a[0]), "r"(a[1]), "r"(a[2]), "r"(a[3]), "r"(b[0]), "r"(b[1]));
}
__device__ __forceinline__ void cp16(uint32_t dst, const void* src) {
    asm volatile("cp.async.cg.shared.global [%0],[%1],16;" :: "r"(dst), "l"(src));
}
#define CP_COMMIT() asm volatile("cp.async.commit_group;")

__device__ __forceinline__ uint32_t packh2(float a, float b) {
    __half2 h = __floats2half2_rn(a, b);
    return *(uint32_t*)&h;
}

// ---------------------------------------------------------------------------
// Prep
// ---------------------------------------------------------------------------
__global__ void split_kernel(const float* __restrict__ x, int n4)
{
    // n4 = n/4; vectorized fp32x4 -> fp16x4
    for (int i = blockIdx.x * blockDim.x + threadIdx.x; i < n4;
         i += gridDim.x * blockDim.x) {
        float4 f = ((const float4*)x)[i];
        uint2 o;
        o.x = packh2(f.x, f.y);
        o.y = packh2(f.z, f.w);
        ((uint2*)g_xh)[i] = o;
    }
}

template <int MODE>  // 0: W_qkv -> g_WqTh, 1: W_proj -> g_WpTh
__global__ void tsplit_h(const float* __restrict__ W, int K, int N)
{
    __half* dst = (MODE == 0) ? g_WqTh : g_WpTh;
    __shared__ float t[32][33];
    int n0 = blockIdx.x * 32, k0 = blockIdx.y * 32;
    int tx = threadIdx.x, ty = threadIdx.y;
#pragma unroll
    for (int r = 0; r < 32; r += 8)
        t[ty + r][tx] = W[(size_t)(k0 + ty + r) * N + n0 + tx];
    __syncthreads();
#pragma unroll
    for (int r = 0; r < 32; r += 8)
        dst[(size_t)(n0 + ty + r) * K + k0 + tx] = __float2half(t[tx][ty + r]);
}

// ---------------------------------------------------------------------------
// Tile loader (512 threads): ROWS x 64 fp16 (128B rows), ld = 1024 elements
// ---------------------------------------------------------------------------
template <int ROWS>
__device__ __forceinline__ void cp_tile512(uint32_t sdst,
                                           const __half* __restrict__ g,
                                           int row0, int k0, int tid)
{
#pragma unroll
    for (int it = 0; it < ROWS / 64; it++) {
        int idx = tid + it * 512;
        int row = idx >> 3;
        int c   = idx & 7;
        cp16(sdst + swz(row * 128 + c * 16),
             g + (size_t)(row0 + row) * 1024 + k0 + c * 8);
    }
}

// ---------------------------------------------------------------------------
// fp16 single-pass GEMM (round-12 best). 256x128 CTA tile, 16 warps (8x2),
// 32x64 warp tile, K-chunk 64, 2-stage double buffer.
// ---------------------------------------------------------------------------
#define QA_BYTES (256 * 64 * 2)              // 32768
#define QB_BYTES (128 * 64 * 2)              // 16384
#define QSTAGE   (QA_BYTES + QB_BYTES)       // 49152
#define GEMM_DSMEM (2 * QSTAGE)              // 98304

template <int MODE>
__global__ void __launch_bounds__(512) gemm_h(
    const float* __restrict__ bias, float* __restrict__ Cout)
{
    constexpr int N = (MODE == 0) ? N3D_ : D_;
    constexpr int nkc = D_ / 64;
    extern __shared__ char dsm[];
    const uint32_t sb0 = smem_u32(dsm);

    const int tid = threadIdx.x;
    const int wid = tid >> 5;
    const int lid = tid & 31;
    const int wm = wid >> 1;
    const int wn = wid & 1;
    const int m0 = blockIdx.y * 256;
    const int n0 = blockIdx.x * 128;

    const __half* A  = (MODE == 0) ? g_xh : g_Oh;
    const __half* Bm = (MODE == 0) ? g_WqTh : g_WpTh;

    const int a_row = (lid & 7) + ((lid >> 3) & 1) * 8;
    const int a_kb  = (lid >> 4) * 16;
    const int b_row = (lid & 7) + ((lid >> 4) & 1) * 8;
    const int b_kb  = ((lid >> 3) & 1) * 16;

    float acc[2][8][4];
#pragma unroll
    for (int i = 0; i < 2; i++)
#pragma unroll
        for (int j = 0; j < 8; j++)
#pragma unroll
            for (int r = 0; r < 4; r++) acc[i][j][r] = 0.f;

    {
        cp_tile512<256>(sb0 + 0,        A,  m0, 0, tid);
        cp_tile512<128>(sb0 + QA_BYTES, Bm, n0, 0, tid);
        CP_COMMIT();
    }

    for (int kc = 0; kc < nkc; kc++) {
        if (kc + 1 < nkc) {
            uint32_t sb = sb0 + ((kc + 1) & 1) * QSTAGE;
            const int k0 = (kc + 1) * 64;
            cp_tile512<256>(sb + 0,        A,  m0, k0, tid);
            cp_tile512<128>(sb + QA_BYTES, Bm, n0, k0, tid);
            CP_COMMIT();
            asm volatile("cp.async.wait_group 1;");
        } else {
            asm volatile("cp.async.wait_group 0;");
        }
        __syncthreads();

        const uint32_t sb = sb0 + (kc & 1) * QSTAGE;
        const uint32_t sA = sb;
        const uint32_t sB = sb + QA_BYTES;

#pragma unroll
        for (int ks = 0; ks < 4; ks++) {
            uint32_t ah[2][4], bh[8][2];
#pragma unroll
            for (int i = 0; i < 2; i++) {
                uint32_t off = swz((wm * 32 + i * 16 + a_row) * 128 + ks * 32 + a_kb);
                ldm4(ah[i][0], ah[i][1], ah[i][2], ah[i][3], sA + off);
            }
#pragma unroll
            for (int p = 0; p < 4; p++) {
                uint32_t off = swz((wn * 64 + p * 16 + b_row) * 128 + ks * 32 + b_kb);
                ldm4(bh[2 * p][0], bh[2 * p][1], bh[2 * p + 1][0],
                     bh[2 * p + 1][1], sB + off);
            }
#pragma unroll
            for (int i = 0; i < 2; i++)
#pragma unroll
                for (int j = 0; j < 8; j++)
                    mma16816h(acc[i][j], ah[i], bh[j]);
        }
        __syncthreads();
    }

#pragma unroll
    for (int i = 0; i < 2; i++) {
#pragma unroll
        for (int j = 0; j < 8; j++) {
            const int n = n0 + wn * 64 + j * 8 + (lid & 3) * 2;
            const float b0 = __ldg(&bias[n]);
            const float b1 = __ldg(&bias[n + 1]);
#pragma unroll
            for (int rr = 0; rr < 2; rr++) {
                const int m = m0 + wm * 32 + i * 16 + (lid >> 2) + rr * 8;
                float v0 = acc[i][j][rr * 2 + 0] + b0;
                float v1 = acc[i][j][rr * 2 + 1] + b1;
                if constexpr (MODE == 0) {
                    const int b = m >> 11, s = m & 2047;
                    const int rem = n & 1023, h = rem >> 6, d = rem & 63;
                    const size_t o = (((size_t)(b * H_ + h) << 11) + s) * DH_ + d;
                    const int which = n0 >> 10;
                    if (which == 0) { v0 *= 0.125f; v1 *= 0.125f; }
                    const uint32_t hp = packh2(v0, v1);
                    if (which == 0)      *(uint32_t*)(g_Qh + o) = hp;
                    else if (which == 1) *(uint32_t*)(g_Kh + o) = hp;
                    else                 *(uint32_t*)(g_Vh + o) = hp;
                } else {
                    *(float2*)(Cout + (size_t)m * N + n) = make_float2(v0, v1);
                }
            }
        }
    }
}

// ---------------------------------------------------------------------------
// Flash attention, fp16 single-pass, BN=128 key tiles.
// BM=128, 8 warps * 16 rows, 3-stage pipeline (32KB/stage = 96KB),
// ONE sync per 128 keys. Q staged through stage 0.
// ---------------------------------------------------------------------------
#define FBM 128
#define FBN 128
#define FK_BYTES (FBN * 128)            // 16384 (128 rows x 128B)
#define FSTAGE   (2 * FK_BYTES)          // 32768 (K + V)
#define FLASH_DSMEM (3 * FSTAGE)         // 98304

__device__ __forceinline__ void cp_ftile(uint32_t sdst,
                                         const __half* __restrict__ g,
                                         int tid)
{
    // 128 rows x 128B
#pragma unroll
    for (int it = 0; it < 4; it++) {
        int idx = tid + it * 256;
        int row = idx >> 3;
        int c   = idx & 7;
        cp16(sdst + swz(row * 128 + c * 16), g + (size_t)row * 64 + c * 8);
    }
}

__global__ void __launch_bounds__(256) flash_mma_kernel()
{
    extern __shared__ char fsm[];
    const uint32_t sStage = smem_u32(fsm);

    const int tid = threadIdx.x;
    const int wid = tid >> 5;
    const int lid = tid & 31;
    const int qt = blockIdx.x;
    const int bh = blockIdx.y;
    const int q0 = qt * FBM;
    const int nkt = qt + 1;          // 128-key tiles

    const __half* Qg = g_Qh + ((size_t)bh * S_ + q0) * DH_;
    const __half* Kg = g_Kh + (size_t)bh * S_ * DH_;
    const __half* Vg = g_Vh + (size_t)bh * S_ * DH_;

    // ---- stage Q (16KB) through stage-0 buffer ----
#pragma unroll
    for (int it = 0; it < 4; it++) {
        int idx = tid + it * 256;
        int row = idx >> 3;
        int c   = idx & 7;
        cp16(sStage + swz(row * 128 + c * 16), Qg + (size_t)row * 64 + c * 8);
    }
    CP_COMMIT();
    asm volatile("cp.async.wait_group 0;");
    __syncthreads();

    const int a_row = (lid & 7) + ((lid >> 3) & 1) * 8;
    const int a_kb  = (lid >> 4) * 16;
    uint32_t qh[4][4];
#pragma unroll
    for (int ks = 0; ks < 4; ks++) {
        uint32_t off = swz((wid * 16 + a_row) * 128 + ks * 32 + a_kb);
        ldm4(qh[ks][0], qh[ks][1], qh[ks][2], qh[ks][3], sStage + off);
    }
    __syncthreads();   // Q frags extracted; buffers reusable for K/V

    // prefetch kt=0 -> buf0, kt=1 -> buf1 (rows 128..255 always in-bounds;
    // when nkt==1 the second prefetch is simply unused)
#pragma unroll
    for (int s = 0; s < 2; s++) {
        uint32_t sb = sStage + s * FSTAGE;
        const size_t koff = (size_t)s * FBN * DH_;
        cp_ftile(sb + 0,        Kg + koff, tid);
        cp_ftile(sb + FK_BYTES, Vg + koff, tid);
        CP_COMMIT();
    }

    const int b_row = (lid & 7) + ((lid >> 4) & 1) * 8;
    const int b_kb  = ((lid >> 3) & 1) * 16;
    const int v_row = (lid & 7) + ((lid >> 3) & 1) * 8;
    const int v_cb  = ((lid >> 4) & 1) * 16;

    float m_i[2] = {-1e30f, -1e30f};
    float l_i[2] = {0.f, 0.f};
    float out[8][4];
#pragma unroll
    for (int nn = 0; nn < 8; nn++)
#pragma unroll
        for (int r = 0; r < 4; r++) out[nn][r] = 0.f;

    int bufc = 0;   // kt % 3
    int bufp = 2;   // (kt+2) % 3
    for (int kt = 0; kt < nkt; kt++) {
        if (kt + 1 < nkt) { asm volatile("cp.async.wait_group 1;"); }
        else              { asm volatile("cp.async.wait_group 0;"); }
        __syncthreads();

        if (kt + 2 < nkt) {
            uint32_t sb2 = sStage + bufp * FSTAGE;
            const size_t koff = (size_t)(kt + 2) * FBN * DH_;
            cp_ftile(sb2 + 0,        Kg + koff, tid);
            cp_ftile(sb2 + FK_BYTES, Vg + koff, tid);
            CP_COMMIT();
        }

        const uint32_t sb = sStage + bufc * FSTAGE;
        const uint32_t sK = sb;
        const uint32_t sV = sb + FK_BYTES;

        float sc[16][4];
#pragma unroll
        for (int j = 0; j < 16; j++)
#pragma unroll
            for (int r = 0; r < 4; r++) sc[j][r] = 0.f;

        // QK^T over 128 keys
#pragma unroll
        for (int jp = 0; jp < 8; jp++) {
#pragma unroll
            for (int ks = 0; ks < 4; ks++) {
                uint32_t off = swz((jp * 16 + b_row) * 128 + ks * 32 + b_kb);
                uint32_t kh[4];
                ldm4(kh[0], kh[1], kh[2], kh[3], sK + off);
                mma16816h(sc[2 * jp],     qh[ks], &kh[0]);
                mma16816h(sc[2 * jp + 1], qh[ks], &kh[2]);
            }
        }

        // causal mask: last tile only (tile cols q0..q0+127)
        if (kt == nkt - 1) {
            const int k0g = kt * FBN;
            const int rbase = q0 + wid * 16 + (lid >> 2);
#pragma unroll
            for (int j = 0; j < 16; j++) {
                const int cbase = k0g + j * 8 + 2 * (lid & 3);
#pragma unroll
                for (int rr = 0; rr < 2; rr++) {
                    const int row = rbase + rr * 8;
                    if (cbase > row)     sc[j][2 * rr]     = -1e30f;
                    if (cbase + 1 > row) sc[j][2 * rr + 1] = -1e30f;
                }
            }
        }

        float alpha[2];
#pragma unroll
        for (int rr = 0; rr < 2; rr++) {
            float tm = -1e30f;
#pragma unroll
            for (int j = 0; j < 16; j++)
                tm = fmaxf(tm, fmaxf(sc[j][2 * rr], sc[j][2 * rr + 1]));
            tm = fmaxf(tm, __shfl_xor_sync(0xffffffffu, tm, 1));
            tm = fmaxf(tm, __shfl_xor_sync(0xffffffffu, tm, 2));
            const float mn = fmaxf(m_i[rr], tm);
            alpha[rr] = __expf(m_i[rr] - mn);
            m_i[rr] = mn;
            float rs = 0.f;
#pragma unroll
            for (int j = 0; j < 16; j++) {
                float p0 = __expf(sc[j][2 * rr]     - mn);
                float p1 = __expf(sc[j][2 * rr + 1] - mn);
                sc[j][2 * rr] = p0; sc[j][2 * rr + 1] = p1;
                rs += p0 + p1;
            }
            rs += __shfl_xor_sync(0xffffffffu, rs, 1);
            rs += __shfl_xor_sync(0xffffffffu, rs, 2);
            l_i[rr] = l_i[rr] * alpha[rr] + rs;
        }
#pragma unroll
        for (int nn = 0; nn < 8; nn++) {
            out[nn][0] *= alpha[0]; out[nn][1] *= alpha[0];
            out[nn][2] *= alpha[1]; out[nn][3] *= alpha[1];
        }

        // PV over 128 keys (8 k-steps of 16)
#pragma unroll
        for (int kk = 0; kk < 8; kk++) {
            uint32_t ph[4];
            ph[0] = packh2(sc[2 * kk][0],     sc[2 * kk][1]);
            ph[1] = packh2(sc[2 * kk][2],     sc[2 * kk][3]);
            ph[2] = packh2(sc[2 * kk + 1][0], sc[2 * kk + 1][1]);
            ph[3] = packh2(sc[2 * kk + 1][2], sc[2 * kk + 1][3]);
#pragma unroll
            for (int np = 0; np < 4; np++) {
                uint32_t off = swz((kk * 16 + v_row) * 128 + np * 32 + v_cb);
                uint32_t vh[4];
                ldm4t(vh[0], vh[1], vh[2], vh[3], sV + off);
                mma16816h(out[2 * np],     ph, &vh[0]);
                mma16816h(out[2 * np + 1], ph, &vh[2]);
            }
        }

        bufc = (bufc == 2) ? 0 : bufc + 1;
        bufp = (bufp == 2) ? 0 : bufp + 1;
    }

    // epilogue: O = out / l -> fp16
    const int b = bh >> 4;
    const int h = bh & 15;
    const float inv0 = 1.0f / l_i[0];
    const float inv1 = 1.0f / l_i[1];
#pragma unroll
    for (int nn = 0; nn < 8; nn++) {
        const int col = h * 64 + nn * 8 + 2 * (lid & 3);
#pragma unroll
        for (int rr = 0; rr < 2; rr++) {
            const int row = q0 + wid * 16 + (lid >> 2) + rr * 8;
            const float inv = rr ? inv1 : inv0;
            const size_t o = ((size_t)b * S_ + row) * D_ + col;
            *(uint32_t*)(g_Oh + o) =
                packh2(out[nn][2 * rr] * inv, out[nn][2 * rr + 1] * inv);
        }
    }
}

// ---------------------------------------------------------------------------
// Launch
// ---------------------------------------------------------------------------
extern "C" void kernel_launch(void* const* d_in, const int* in_sizes, int n_in,
                              void* d_out, int out_size)
{
    const float* x     = (const float*)d_in[0];
    const float* Wqkv  = (const float*)d_in[1];
    const float* bqkv  = (const float*)d_in[2];
    const float* Wproj = (const float*)d_in[3];
    const float* bproj = (const float*)d_in[4];
    float* out = (float*)d_out;

    cudaFuncSetAttribute(gemm_h<0>,
                         cudaFuncAttributeMaxDynamicSharedMemorySize, GEMM_DSMEM);
    cudaFuncSetAttribute(gemm_h<1>,
                         cudaFuncAttributeMaxDynamicSharedMemorySize, GEMM_DSMEM);
    cudaFuncSetAttribute(flash_mma_kernel,
                         cudaFuncAttributeMaxDynamicSharedMemorySize, FLASH_DSMEM);

    split_kernel<<<2048, 256>>>(x, BS_ * D_ / 4);
    tsplit_h<0><<<dim3(N3D_ / 32, D_ / 32), dim3(32, 8)>>>(Wqkv, D_, N3D_);
    tsplit_h<1><<<dim3(D_ / 32, D_ / 32), dim3(32, 8)>>>(Wproj, D_, D_);

    gemm_h<0><<<dim3(N3D_ / 128, BS_ / 256), 512, GEMM_DSMEM>>>(bqkv, nullptr);

    flash_mma_kernel<<<dim3(S_ / FBM, B_ * H_), 256, FLASH_DSMEM>>>();

    gemm_h<1><<<dim3(D_ / 128, BS_ / 256), 512, GEMM_DSMEM>>>(bproj, out);
}

// round 14
// speedup vs baseline: 2.5198x; 1.0472x over previous
#include <cuda_runtime.h>
#include <cuda_fp16.h>
#include <cstdint>

// Problem constants
#define B_  2
#define S_  2048
#define D_  1024
#define H_  16
#define DH_ 64
#define BS_ (B_ * S_)        // 4096
#define N3D_ (3 * D_)        // 3072

// ---------------------------------------------------------------------------
// Scratch (allocation-free: __device__ globals) — all fp16
// ---------------------------------------------------------------------------
__device__ __align__(128) __half g_Qh[B_ * H_ * S_ * DH_];  // scaled 0.125
__device__ __align__(128) __half g_Kh[B_ * H_ * S_ * DH_];
__device__ __align__(128) __half g_Vh[B_ * H_ * S_ * DH_];
__device__ __align__(128) __half g_xh[BS_ * D_];
__device__ __align__(128) __half g_WqTh[N3D_ * D_];
__device__ __align__(128) __half g_WpTh[D_ * D_];
__device__ __align__(128) __half g_Oh[BS_ * D_];

// ---------------------------------------------------------------------------
// Base-ISA helpers
// ---------------------------------------------------------------------------
__device__ __forceinline__ uint32_t smem_u32(const void* p) {
    uint32_t a;
    asm("{ .reg .u64 t; cvta.to.shared.u64 t, %1; cvt.u32.u64 %0, t; }"
        : "=r"(a) : "l"(p));
    return a;
}
__device__ __forceinline__ uint32_t swz(uint32_t b) { return b ^ ((b >> 3) & 0x70); }

__device__ __forceinline__ void ldm4(uint32_t& r0, uint32_t& r1, uint32_t& r2,
                                     uint32_t& r3, uint32_t a) {
    asm volatile("ldmatrix.sync.aligned.m8n8.x4.shared.b16 {%0,%1,%2,%3},[%4];"
                 : "=r"(r0), "=r"(r1), "=r"(r2), "=r"(r3) : "r"(a));
}
__device__ __forceinline__ void ldm4t(uint32_t& r0, uint32_t& r1, uint32_t& r2,
                                      uint32_t& r3, uint32_t a) {
    asm volatile("ldmatrix.sync.aligned.m8n8.x4.trans.shared.b16 {%0,%1,%2,%3},[%4];"
                 : "=r"(r0), "=r"(r1), "=r"(r2), "=r"(r3) : "r"(a));
}
__device__ __forceinline__ void mma16816h(float* d, const uint32_t* a,
                                          const uint32_t* b) {
    asm volatile(
        "mma.sync.aligned.m16n8k16.row.col.f32.f16.f16.f32 "
        "{%0,%1,%2,%3},{%4,%5,%6,%7},{%8,%9},{%0,%1,%2,%3};"
        : "+f"(d[0]), "+f"(d[1]), "+f"(d[2]), "+f"(d[3])
        : "r"(a[0]), "r"(a[1]), "r"(a[2]), "r"(a[3]), "r"(b[0]), "r"(b[1]));
}
__device__ __forceinline__ void cp16(uint32_t dst, const void* src) {
    asm volatile("cp.async.cg.shared.global [%0],[%1],16;" :: "r"(dst), "l"(src));
}
#define CP_COMMIT() asm volatile("cp.async.commit_group;")

__device__ __forceinline__ uint32_t packh2(float a, float b) {
    __half2 h = __floats2half2_rn(a, b);
    return *(uint32_t*)&h;
}

// ---------------------------------------------------------------------------
// Fused prep: blocks [0,2048) split x; [2048,5120) transpose Wqkv;
// [5120,6144) transpose Wproj.  All 256-thread blocks.
// ---------------------------------------------------------------------------
__global__ void __launch_bounds__(256) prep_kernel(
    const float* __restrict__ x,
    const float* __restrict__ Wqkv,
    const float* __restrict__ Wproj)
{
    const int bid = blockIdx.x;
    const int tid = threadIdx.x;

    if (bid < 2048) {
        // x fp32 -> fp16, vectorized: n4 = BS_*D_/4 = 1M
        const int n4 = BS_ * D_ / 4;
        for (int i = bid * 256 + tid; i < n4; i += 2048 * 256) {
            float4 f = ((const float4*)x)[i];
            uint2 o;
            o.x = packh2(f.x, f.y);
            o.y = packh2(f.z, f.w);
            ((uint2*)g_xh)[i] = o;
        }
        return;
    }

    // transpose phases: 32x32 tiles, (tx, ty) = (tid&31, tid>>5), 8 rows/thread
    __shared__ float t[32][33];
    const int tx = tid & 31;
    const int ty = tid >> 5;

    const float* W;
    __half* dst;
    int K = D_, N;
    int tile;
    if (bid < 5120) {           // Wqkv: 96 x 32 tiles (N=3072, K=1024)
        W = Wqkv; dst = g_WqTh; N = N3D_;
        tile = bid - 2048;      // 0..3071
    } else {                    // Wproj: 32 x 32 tiles
        W = Wproj; dst = g_WpTh; N = D_;
        tile = bid - 5120;      // 0..1023
    }
    const int ntx = N / 32;
    const int n0 = (tile % ntx) * 32;
    const int k0 = (tile / ntx) * 32;

#pragma unroll
    for (int r = 0; r < 32; r += 8)
        t[ty + r][tx] = W[(size_t)(k0 + ty + r) * N + n0 + tx];
    __syncthreads();
#pragma unroll
    for (int r = 0; r < 32; r += 8)
        dst[(size_t)(n0 + ty + r) * K + k0 + tx] = __float2half(t[tx][ty + r]);
}

// ---------------------------------------------------------------------------
// Tile loader (512 threads): ROWS x 64 fp16 (128B swizzled rows), ld = 1024
// ---------------------------------------------------------------------------
template <int ROWS>
__device__ __forceinline__ void cp_tile512(uint32_t sdst,
                                           const __half* __restrict__ g,
                                           int row0, int k0, int tid)
{
#pragma unroll
    for (int it = 0; it < ROWS / 64; it++) {
        int idx = tid + it * 512;
        int row = idx >> 3;
        int c   = idx & 7;
        cp16(sdst + swz(row * 128 + c * 16),
             g + (size_t)(row0 + row) * 1024 + k0 + c * 8);
    }
}

// ---------------------------------------------------------------------------
// fp16 single-pass GEMM. 256x128 CTA tile, 16 warps (8x2), 32x64 warp tile,
// K-chunk 128 (two 64-col sub-tiles per stage), 2-stage double buffer.
// Stage layout: [A_k0 32KB][A_k1 32KB][B_k0 16KB][B_k1 16KB] = 96KB.
// MODE 0: QKV -> scatter g_Qh/g_Kh/g_Vh (+bias, Q scaled)
// MODE 1: proj -> Cout fp32 (+bias)
// ---------------------------------------------------------------------------
#define SUBA (256 * 64 * 2)                  // 32768
#define SUBB (128 * 64 * 2)                  // 16384
#define QSTAGE (2 * SUBA + 2 * SUBB)         // 98304
#define GEMM_DSMEM (2 * QSTAGE)              // 196608

__device__ __forceinline__ void load_stage(uint32_t sb, const __half* A,
                                           const __half* Bm, int m0, int n0,
                                           int k0, int tid)
{
    cp_tile512<256>(sb + 0 * SUBA,        A,  m0, k0,      tid);
    cp_tile512<256>(sb + 1 * SUBA,        A,  m0, k0 + 64, tid);
    cp_tile512<128>(sb + 2 * SUBA,        Bm, n0, k0,      tid);
    cp_tile512<128>(sb + 2 * SUBA + SUBB, Bm, n0, k0 + 64, tid);
    CP_COMMIT();
}

template <int MODE>
__global__ void __launch_bounds__(512) gemm_h(
    const float* __restrict__ bias, float* __restrict__ Cout)
{
    constexpr int N = (MODE == 0) ? N3D_ : D_;
    constexpr int nkc = D_ / 128;   // 8
    extern __shared__ char dsm[];
    const uint32_t sb0 = smem_u32(dsm);

    const int tid = threadIdx.x;
    const int wid = tid >> 5;
    const int lid = tid & 31;
    const int wm = wid >> 1;        // 0..7
    const int wn = wid & 1;         // 0..1
    const int m0 = blockIdx.y * 256;
    const int n0 = blockIdx.x * 128;

    const __half* A  = (MODE == 0) ? g_xh : g_Oh;
    const __half* Bm = (MODE == 0) ? g_WqTh : g_WpTh;

    const int a_row = (lid & 7) + ((lid >> 3) & 1) * 8;
    const int a_kb  = (lid >> 4) * 16;
    const int b_row = (lid & 7) + ((lid >> 4) & 1) * 8;
    const int b_kb  = ((lid >> 3) & 1) * 16;

    float acc[2][8][4];
#pragma unroll
    for (int i = 0; i < 2; i++)
#pragma unroll
        for (int j = 0; j < 8; j++)
#pragma unroll
            for (int r = 0; r < 4; r++) acc[i][j][r] = 0.f;

    load_stage(sb0, A, Bm, m0, n0, 0, tid);

    for (int kc = 0; kc < nkc; kc++) {
        if (kc + 1 < nkc) {
            load_stage(sb0 + ((kc + 1) & 1) * QSTAGE, A, Bm, m0, n0,
                       (kc + 1) * 128, tid);
            asm volatile("cp.async.wait_group 1;");
        } else {
            asm volatile("cp.async.wait_group 0;");
        }
        __syncthreads();

        const uint32_t sb = sb0 + (kc & 1) * QSTAGE;

#pragma unroll
        for (int ks = 0; ks < 8; ks++) {
            const uint32_t sA = sb + (ks >> 2) * SUBA;
            const uint32_t sB = sb + 2 * SUBA + (ks >> 2) * SUBB;
            const int ksl = ks & 3;
            uint32_t ah[2][4], bh[8][2];
#pragma unroll
            for (int i = 0; i < 2; i++) {
                uint32_t off = swz((wm * 32 + i * 16 + a_row) * 128 + ksl * 32 + a_kb);
                ldm4(ah[i][0], ah[i][1], ah[i][2], ah[i][3], sA + off);
            }
#pragma unroll
            for (int p = 0; p < 4; p++) {
                uint32_t off = swz((wn * 64 + p * 16 + b_row) * 128 + ksl * 32 + b_kb);
                ldm4(bh[2 * p][0], bh[2 * p][1], bh[2 * p + 1][0],
                     bh[2 * p + 1][1], sB + off);
            }
#pragma unroll
            for (int i = 0; i < 2; i++)
#pragma unroll
                for (int j = 0; j < 8; j++)
                    mma16816h(acc[i][j], ah[i], bh[j]);
        }
        __syncthreads();
    }

#pragma unroll
    for (int i = 0; i < 2; i++) {
#pragma unroll
        for (int j = 0; j < 8; j++) {
            const int n = n0 + wn * 64 + j * 8 + (lid & 3) * 2;
            const float b0 = __ldg(&bias[n]);
            const float b1 = __ldg(&bias[n + 1]);
#pragma unroll
            for (int rr = 0; rr < 2; rr++) {
                const int m = m0 + wm * 32 + i * 16 + (lid >> 2) + rr * 8;
                float v0 = acc[i][j][rr * 2 + 0] + b0;
                float v1 = acc[i][j][rr * 2 + 1] + b1;
                if constexpr (MODE == 0) {
                    const int b = m >> 11, s = m & 2047;
                    const int rem = n & 1023, h = rem >> 6, d = rem & 63;
                    const size_t o = (((size_t)(b * H_ + h) << 11) + s) * DH_ + d;
                    const int which = n0 >> 10;
                    if (which == 0) { v0 *= 0.125f; v1 *= 0.125f; }
                    const uint32_t hp = packh2(v0, v1);
                    if (which == 0)      *(uint32_t*)(g_Qh + o) = hp;
                    else if (which == 1) *(uint32_t*)(g_Kh + o) = hp;
                    else                 *(uint32_t*)(g_Vh + o) = hp;
                } else {
                    *(float2*)(Cout + (size_t)m * N + n) = make_float2(v0, v1);
                }
            }
        }
    }
}

// ---------------------------------------------------------------------------
// Flash attention, fp16 single-pass, BN=128 key tiles (round-13 best),
// heavy-first q-tile order (LPT).
// ---------------------------------------------------------------------------
#define FBM 128
#define FBN 128
#define FK_BYTES (FBN * 128)            // 16384
#define FSTAGE   (2 * FK_BYTES)          // 32768
#define FLASH_DSMEM (3 * FSTAGE)         // 98304

__device__ __forceinline__ void cp_ftile(uint32_t sdst,
                                         const __half* __restrict__ g,
                                         int tid)
{
#pragma unroll
    for (int it = 0; it < 4; it++) {
        int idx = tid + it * 256;
        int row = idx >> 3;
        int c   = idx & 7;
        cp16(sdst + swz(row * 128 + c * 16), g + (size_t)row * 64 + c * 8);
    }
}

__global__ void __launch_bounds__(256) flash_mma_kernel()
{
    extern __shared__ char fsm[];
    const uint32_t sStage = smem_u32(fsm);

    const int tid = threadIdx.x;
    const int wid = tid >> 5;
    const int lid = tid & 31;
    const int qt = gridDim.x - 1 - blockIdx.x;   // heavy tiles first (LPT)
    const int bh = blockIdx.y;
    const int q0 = qt * FBM;
    const int nkt = qt + 1;

    const __half* Qg = g_Qh + ((size_t)bh * S_ + q0) * DH_;
    const __half* Kg = g_Kh + (size_t)bh * S_ * DH_;
    const __half* Vg = g_Vh + (size_t)bh * S_ * DH_;

    // ---- stage Q (16KB) through stage-0 buffer ----
#pragma unroll
    for (int it = 0; it < 4; it++) {
        int idx = tid + it * 256;
        int row = idx >> 3;
        int c   = idx & 7;
        cp16(sStage + swz(row * 128 + c * 16), Qg + (size_t)row * 64 + c * 8);
    }
    CP_COMMIT();
    asm volatile("cp.async.wait_group 0;");
    __syncthreads();

    const int a_row = (lid & 7) + ((lid >> 3) & 1) * 8;
    const int a_kb  = (lid >> 4) * 16;
    uint32_t qh[4][4];
#pragma unroll
    for (int ks = 0; ks < 4; ks++) {
        uint32_t off = swz((wid * 16 + a_row) * 128 + ks * 32 + a_kb);
        ldm4(qh[ks][0], qh[ks][1], qh[ks][2], qh[ks][3], sStage + off);
    }
    __syncthreads();

    // prefetch kt=0 -> buf0, kt=1 -> buf1 (rows always in-bounds; unused if nkt==1)
#pragma unroll
    for (int s = 0; s < 2; s++) {
        uint32_t sb = sStage + s * FSTAGE;
        const size_t koff = (size_t)s * FBN * DH_;
        cp_ftile(sb + 0,        Kg + koff, tid);
        cp_ftile(sb + FK_BYTES, Vg + koff, tid);
        CP_COMMIT();
    }

    const int b_row = (lid & 7) + ((lid >> 4) & 1) * 8;
    const int b_kb  = ((lid >> 3) & 1) * 16;
    const int v_row = (lid & 7) + ((lid >> 3) & 1) * 8;
    const int v_cb  = ((lid >> 4) & 1) * 16;

    float m_i[2] = {-1e30f, -1e30f};
    float l_i[2] = {0.f, 0.f};
    float out[8][4];
#pragma unroll
    for (int nn = 0; nn < 8; nn++)
#pragma unroll
        for (int r = 0; r < 4; r++) out[nn][r] = 0.f;

    int bufc = 0;
    int bufp = 2;
    for (int kt = 0; kt < nkt; kt++) {
        if (kt + 1 < nkt) { asm volatile("cp.async.wait_group 1;"); }
        else              { asm volatile("cp.async.wait_group 0;"); }
        __syncthreads();

        if (kt + 2 < nkt) {
            uint32_t sb2 = sStage + bufp * FSTAGE;
            const size_t koff = (size_t)(kt + 2) * FBN * DH_;
            cp_ftile(sb2 + 0,        Kg + koff, tid);
            cp_ftile(sb2 + FK_BYTES, Vg + koff, tid);
            CP_COMMIT();
        }

        const uint32_t sb = sStage + bufc * FSTAGE;
        const uint32_t sK = sb;
        const uint32_t sV = sb + FK_BYTES;

        float sc[16][4];
#pragma unroll
        for (int j = 0; j < 16; j++)
#pragma unroll
            for (int r = 0; r < 4; r++) sc[j][r] = 0.f;

#pragma unroll
        for (int jp = 0; jp < 8; jp++) {
#pragma unroll
            for (int ks = 0; ks < 4; ks++) {
                uint32_t off = swz((jp * 16 + b_row) * 128 + ks * 32 + b_kb);
                uint32_t kh[4];
                ldm4(kh[0], kh[1], kh[2], kh[3], sK + off);
                mma16816h(sc[2 * jp],     qh[ks], &kh[0]);
                mma16816h(sc[2 * jp + 1], qh[ks], &kh[2]);
            }
        }

        if (kt == nkt - 1) {
            const int k0g = kt * FBN;
            const int rbase = q0 + wid * 16 + (lid >> 2);
#pragma unroll
            for (int j = 0; j < 16; j++) {
                const int cbase = k0g + j * 8 + 2 * (lid & 3);
#pragma unroll
                for (int rr = 0; rr < 2; rr++) {
                    const int row = rbase + rr * 8;
                    if (cbase > row)     sc[j][2 * rr]     = -1e30f;
                    if (cbase + 1 > row) sc[j][2 * rr + 1] = -1e30f;
                }
            }
        }

        float alpha[2];
#pragma unroll
        for (int rr = 0; rr < 2; rr++) {
            float tm = -1e30f;
#pragma unroll
            for (int j = 0; j < 16; j++)
                tm = fmaxf(tm, fmaxf(sc[j][2 * rr], sc[j][2 * rr + 1]));
            tm = fmaxf(tm, __shfl_xor_sync(0xffffffffu, tm, 1));
            tm = fmaxf(tm, __shfl_xor_sync(0xffffffffu, tm, 2));
            const float mn = fmaxf(m_i[rr], tm);
            alpha[rr] = __expf(m_i[rr] - mn);
            m_i[rr] = mn;
            float rs = 0.f;
#pragma unroll
            for (int j = 0; j < 16; j++) {
                float p0 = __expf(sc[j][2 * rr]     - mn);
                float p1 = __expf(sc[j][2 * rr + 1] - mn);
                sc[j][2 * rr] = p0; sc[j][2 * rr + 1] = p1;
                rs += p0 + p1;
            }
            rs += __shfl_xor_sync(0xffffffffu, rs, 1);
            rs += __shfl_xor_sync(0xffffffffu, rs, 2);
            l_i[rr] = l_i[rr] * alpha[rr] + rs;
        }
#pragma unroll
        for (int nn = 0; nn < 8; nn++) {
            out[nn][0] *= alpha[0]; out[nn][1] *= alpha[0];
            out[nn][2] *= alpha[1]; out[nn][3] *= alpha[1];
        }

#pragma unroll
        for (int kk = 0; kk < 8; kk++) {
            uint32_t ph[4];
            ph[0] = packh2(sc[2 * kk][0],     sc[2 * kk][1]);
            ph[1] = packh2(sc[2 * kk][2],     sc[2 * kk][3]);
            ph[2] = packh2(sc[2 * kk + 1][0], sc[2 * kk + 1][1]);
            ph[3] = packh2(sc[2 * kk + 1][2], sc[2 * kk + 1][3]);
#pragma unroll
            for (int np = 0; np < 4; np++) {
                uint32_t off = swz((kk * 16 + v_row) * 128 + np * 32 + v_cb);
                uint32_t vh[4];
                ldm4t(vh[0], vh[1], vh[2], vh[3], sV + off);
                mma16816h(out[2 * np],     ph, &vh[0]);
                mma16816h(out[2 * np + 1], ph, &vh[2]);
            }
        }

        bufc = (bufc == 2) ? 0 : bufc + 1;
        bufp = (bufp == 2) ? 0 : bufp + 1;
    }

    const int b = bh >> 4;
    const int h = bh & 15;
    const float inv0 = 1.0f / l_i[0];
    const float inv1 = 1.0f / l_i[1];
#pragma unroll
    for (int nn = 0; nn < 8; nn++) {
        const int col = h * 64 + nn * 8 + 2 * (lid & 3);
#pragma unroll
        for (int rr = 0; rr < 2; rr++) {
            const int row = q0 + wid * 16 + (lid >> 2) + rr * 8;
            const float inv = rr ? inv1 : inv0;
            const size_t o = ((size_t)b * S_ + row) * D_ + col;
            *(uint32_t*)(g_Oh + o) =
                packh2(out[nn][2 * rr] * inv, out[nn][2 * rr + 1] * inv);
        }
    }
}

// ---------------------------------------------------------------------------
// Launch
// ---------------------------------------------------------------------------
extern "C" void kernel_launch(void* const* d_in, const int* in_sizes, int n_in,
                              void* d_out, int out_size)
{
    const float* x     = (const float*)d_in[0];
    const float* Wqkv  = (const float*)d_in[1];
    const float* bqkv  = (const float*)d_in[2];
    const float* Wproj = (const float*)d_in[3];
    const float* bproj = (const float*)d_in[4];
    float* out = (float*)d_out;

    cudaFuncSetAttribute(gemm_h<0>,
                         cudaFuncAttributeMaxDynamicSharedMemorySize, GEMM_DSMEM);
    cudaFuncSetAttribute(gemm_h<1>,
                         cudaFuncAttributeMaxDynamicSharedMemorySize, GEMM_DSMEM);
    cudaFuncSetAttribute(flash_mma_kernel,
                         cudaFuncAttributeMaxDynamicSharedMemorySize, FLASH_DSMEM);

    prep_kernel<<<6144, 256>>>(x, Wqkv, Wproj);

    gemm_h<0><<<dim3(N3D_ / 128, BS_ / 256), 512, GEMM_DSMEM>>>(bqkv, nullptr);

    flash_mma_kernel<<<dim3(S_ / FBM, B_ * H_), 256, FLASH_DSMEM>>>();

    gemm_h<1><<<dim3(D_ / 128, BS_ / 256), 512, GEMM_DSMEM>>>(bproj, out);
}

// round 15
// speedup vs baseline: 2.5746x; 1.0217x over previous
#include <cuda_runtime.h>
#include <cuda_fp16.h>
#include <cstdint>

// Problem constants
#define B_  2
#define S_  2048
#define D_  1024
#define H_  16
#define DH_ 64
#define BS_ (B_ * S_)        // 4096
#define N3D_ (3 * D_)        // 3072

// ---------------------------------------------------------------------------
// Scratch (allocation-free: __device__ globals) — all fp16
// ---------------------------------------------------------------------------
__device__ __align__(128) __half g_Qh[B_ * H_ * S_ * DH_];  // scaled 0.125
__device__ __align__(128) __half g_Kh[B_ * H_ * S_ * DH_];
__device__ __align__(128) __half g_Vh[B_ * H_ * S_ * DH_];
__device__ __align__(128) __half g_xh[BS_ * D_];
__device__ __align__(128) __half g_WqTh[N3D_ * D_];
__device__ __align__(128) __half g_WpTh[D_ * D_];
__device__ __align__(128) __half g_Oh[BS_ * D_];

// ---------------------------------------------------------------------------
// Base-ISA helpers
// ---------------------------------------------------------------------------
__device__ __forceinline__ uint32_t smem_u32(const void* p) {
    uint32_t a;
    asm("{ .reg .u64 t; cvta.to.shared.u64 t, %1; cvt.u32.u64 %0, t; }"
        : "=r"(a) : "l"(p));
    return a;
}
__device__ __forceinline__ uint32_t swz(uint32_t b) { return b ^ ((b >> 3) & 0x70); }

__device__ __forceinline__ void ldm4(uint32_t& r0, uint32_t& r1, uint32_t& r2,
                                     uint32_t& r3, uint32_t a) {
    asm volatile("ldmatrix.sync.aligned.m8n8.x4.shared.b16 {%0,%1,%2,%3},[%4];"
                 : "=r"(r0), "=r"(r1), "=r"(r2), "=r"(r3) : "r"(a));
}
__device__ __forceinline__ void ldm4t(uint32_t& r0, uint32_t& r1, uint32_t& r2,
                                      uint32_t& r3, uint32_t a) {
    asm volatile("ldmatrix.sync.aligned.m8n8.x4.trans.shared.b16 {%0,%1,%2,%3},[%4];"
                 : "=r"(r0), "=r"(r1), "=r"(r2), "=r"(r3) : "r"(a));
}
__device__ __forceinline__ void mma16816h(float* d, const uint32_t* a,
                                          const uint32_t* b) {
    asm volatile(
        "mma.sync.aligned.m16n8k16.row.col.f32.f16.f16.f32 "
        "{%0,%1,%2,%3},{%4,%5,%6,%7},{%8,%9},{%0,%1,%2,%3};"
        : "+f"(d[0]), "+f"(d[1]), "+f"(d[2]), "+f"(d[3])
        : "r"(a[0]), "r"(a[1]), "r"(a[2]), "r"(a[3]), "r"(b[0]), "r"(b[1]));
}
__device__ __forceinline__ void cp16(uint32_t dst, const void* src) {
    asm volatile("cp.async.cg.shared.global [%0],[%1],16;" :: "r"(dst), "l"(src));
}
#define CP_COMMIT() asm volatile("cp.async.commit_group;")

__device__ __forceinline__ uint32_t packh2(float a, float b) {
    __half2 h = __floats2half2_rn(a, b);
    return *(uint32_t*)&h;
}

// ---------------------------------------------------------------------------
// Fused prep (round-14): blocks [0,2048) split x; [2048,5120) Wqkv^T;
// [5120,6144) Wproj^T.
// ---------------------------------------------------------------------------
__global__ void __launch_bounds__(256) prep_kernel(
    const float* __restrict__ x,
    const float* __restrict__ Wqkv,
    const float* __restrict__ Wproj)
{
    const int bid = blockIdx.x;
    const int tid = threadIdx.x;

    if (bid < 2048) {
        const int n4 = BS_ * D_ / 4;
        for (int i = bid * 256 + tid; i < n4; i += 2048 * 256) {
            float4 f = ((const float4*)x)[i];
            uint2 o;
            o.x = packh2(f.x, f.y);
            o.y = packh2(f.z, f.w);
            ((uint2*)g_xh)[i] = o;
        }
        return;
    }

    __shared__ float t[32][33];
    const int tx = tid & 31;
    const int ty = tid >> 5;

    const float* W;
    __half* dst;
    int K = D_, N;
    int tile;
    if (bid < 5120) {
        W = Wqkv; dst = g_WqTh; N = N3D_;
        tile = bid - 2048;
    } else {
        W = Wproj; dst = g_WpTh; N = D_;
        tile = bid - 5120;
    }
    const int ntx = N / 32;
    const int n0 = (tile % ntx) * 32;
    const int k0 = (tile / ntx) * 32;

#pragma unroll
    for (int r = 0; r < 32; r += 8)
        t[ty + r][tx] = W[(size_t)(k0 + ty + r) * N + n0 + tx];
    __syncthreads();
#pragma unroll
    for (int r = 0; r < 32; r += 8)
        dst[(size_t)(n0 + ty + r) * K + k0 + tx] = __float2half(t[tx][ty + r]);
}

// ---------------------------------------------------------------------------
// Tile loader (256 threads): 128 rows x 64 fp16 (128B swizzled rows), ld=1024
// ---------------------------------------------------------------------------
__device__ __forceinline__ void cp_tile128(uint32_t sdst,
                                           const __half* __restrict__ g,
                                           int row0, int k0, int tid)
{
#pragma unroll
    for (int it = 0; it < 4; it++) {
        int idx = tid + it * 256;
        int row = idx >> 3;
        int c   = idx & 7;
        cp16(sdst + swz(row * 128 + c * 16),
             g + (size_t)(row0 + row) * 1024 + k0 + c * 8);
    }
}

// ---------------------------------------------------------------------------
// fp16 single-pass GEMM. 128x128 CTA tile, 8 warps (4x2), 32x64 warp tile,
// K-chunk 64, 2-stage double buffer (32KB/stage, 64KB total) -> 2 CTAs/SM.
// MODE 0: QKV -> scatter g_Qh/g_Kh/g_Vh (+bias, Q scaled)
// MODE 1: proj -> Cout fp32 (+bias)
// ---------------------------------------------------------------------------
#define GA_BYTES (128 * 64 * 2)              // 16384
#define GSTAGE   (2 * GA_BYTES)              // 32768 (A + B)
#define GEMM_DSMEM (2 * GSTAGE)              // 65536

template <int MODE>
__global__ void __launch_bounds__(256, 2) gemm_h(
    const float* __restrict__ bias, float* __restrict__ Cout)
{
    constexpr int N = (MODE == 0) ? N3D_ : D_;
    constexpr int nkc = D_ / 64;    // 16
    extern __shared__ char dsm[];
    const uint32_t sb0 = smem_u32(dsm);

    const int tid = threadIdx.x;
    const int wid = tid >> 5;
    const int lid = tid & 31;
    const int wm = wid >> 1;        // 0..3 (32-row band)
    const int wn = wid & 1;         // 0..1 (64-col band)
    const int m0 = blockIdx.y * 128;
    const int n0 = blockIdx.x * 128;

    const __half* A  = (MODE == 0) ? g_xh : g_Oh;
    const __half* Bm = (MODE == 0) ? g_WqTh : g_WpTh;

    const int a_row = (lid & 7) + ((lid >> 3) & 1) * 8;
    const int a_kb  = (lid >> 4) * 16;
    const int b_row = (lid & 7) + ((lid >> 4) & 1) * 8;
    const int b_kb  = ((lid >> 3) & 1) * 16;

    float acc[2][8][4];
#pragma unroll
    for (int i = 0; i < 2; i++)
#pragma unroll
        for (int j = 0; j < 8; j++)
#pragma unroll
            for (int r = 0; r < 4; r++) acc[i][j][r] = 0.f;

    {
        cp_tile128(sb0 + 0,        A,  m0, 0, tid);
        cp_tile128(sb0 + GA_BYTES, Bm, n0, 0, tid);
        CP_COMMIT();
    }

    for (int kc = 0; kc < nkc; kc++) {
        if (kc + 1 < nkc) {
            uint32_t sb = sb0 + ((kc + 1) & 1) * GSTAGE;
            const int k0 = (kc + 1) * 64;
            cp_tile128(sb + 0,        A,  m0, k0, tid);
            cp_tile128(sb + GA_BYTES, Bm, n0, k0, tid);
            CP_COMMIT();
            asm volatile("cp.async.wait_group 1;");
        } else {
            asm volatile("cp.async.wait_group 0;");
        }
        __syncthreads();

        const uint32_t sb = sb0 + (kc & 1) * GSTAGE;
        const uint32_t sA = sb;
        const uint32_t sB = sb + GA_BYTES;

#pragma unroll
        for (int ks = 0; ks < 4; ks++) {
            uint32_t ah[2][4], bh[8][2];
#pragma unroll
            for (int i = 0; i < 2; i++) {
                uint32_t off = swz((wm * 32 + i * 16 + a_row) * 128 + ks * 32 + a_kb);
                ldm4(ah[i][0], ah[i][1], ah[i][2], ah[i][3], sA + off);
            }
#pragma unroll
            for (int p = 0; p < 4; p++) {
                uint32_t off = swz((wn * 64 + p * 16 + b_row) * 128 + ks * 32 + b_kb);
                ldm4(bh[2 * p][0], bh[2 * p][1], bh[2 * p + 1][0],
                     bh[2 * p + 1][1], sB + off);
            }
#pragma unroll
            for (int i = 0; i < 2; i++)
#pragma unroll
                for (int j = 0; j < 8; j++)
                    mma16816h(acc[i][j], ah[i], bh[j]);
        }
        __syncthreads();
    }

#pragma unroll
    for (int i = 0; i < 2; i++) {
#pragma unroll
        for (int j = 0; j < 8; j++) {
            const int n = n0 + wn * 64 + j * 8 + (lid & 3) * 2;
            const float b0 = __ldg(&bias[n]);
            const float b1 = __ldg(&bias[n + 1]);
#pragma unroll
            for (int rr = 0; rr < 2; rr++) {
                const int m = m0 + wm * 32 + i * 16 + (lid >> 2) + rr * 8;
                float v0 = acc[i][j][rr * 2 + 0] + b0;
                float v1 = acc[i][j][rr * 2 + 1] + b1;
                if constexpr (MODE == 0) {
                    const int b = m >> 11, s = m & 2047;
                    const int rem = n & 1023, h = rem >> 6, d = rem & 63;
                    const size_t o = (((size_t)(b * H_ + h) << 11) + s) * DH_ + d;
                    const int which = n0 >> 10;
                    if (which == 0) { v0 *= 0.125f; v1 *= 0.125f; }
                    const uint32_t hp = packh2(v0, v1);
                    if (which == 0)      *(uint32_t*)(g_Qh + o) = hp;
                    else if (which == 1) *(uint32_t*)(g_Kh + o) = hp;
                    else                 *(uint32_t*)(g_Vh + o) = hp;
                } else {
                    *(float2*)(Cout + (size_t)m * N + n) = make_float2(v0, v1);
                }
            }
        }
    }
}

// ---------------------------------------------------------------------------
// Flash attention, fp16 single-pass, BN=128 key tiles, LPT order (round-14).
// ---------------------------------------------------------------------------
#define FBM 128
#define FBN 128
#define FK_BYTES (FBN * 128)            // 16384
#define FSTAGE   (2 * FK_BYTES)          // 32768
#define FLASH_DSMEM (3 * FSTAGE)         // 98304

__device__ __forceinline__ void cp_ftile(uint32_t sdst,
                                         const __half* __restrict__ g,
                                         int tid)
{
#pragma unroll
    for (int it = 0; it < 4; it++) {
        int idx = tid + it * 256;
        int row = idx >> 3;
        int c   = idx & 7;
        cp16(sdst + swz(row * 128 + c * 16), g + (size_t)row * 64 + c * 8);
    }
}

__global__ void __launch_bounds__(256) flash_mma_kernel()
{
    extern __shared__ char fsm[];
    const uint32_t sStage = smem_u32(fsm);

    const int tid = threadIdx.x;
    const int wid = tid >> 5;
    const int lid = tid & 31;
    const int qt = gridDim.x - 1 - blockIdx.x;   // heavy tiles first (LPT)
    const int bh = blockIdx.y;
    const int q0 = qt * FBM;
    const int nkt = qt + 1;

    const __half* Qg = g_Qh + ((size_t)bh * S_ + q0) * DH_;
    const __half* Kg = g_Kh + (size_t)bh * S_ * DH_;
    const __half* Vg = g_Vh + (size_t)bh * S_ * DH_;

#pragma unroll
    for (int it = 0; it < 4; it++) {
        int idx = tid + it * 256;
        int row = idx >> 3;
        int c   = idx & 7;
        cp16(sStage + swz(row * 128 + c * 16), Qg + (size_t)row * 64 + c * 8);
    }
    CP_COMMIT();
    asm volatile("cp.async.wait_group 0;");
    __syncthreads();

    const int a_row = (lid & 7) + ((lid >> 3) & 1) * 8;
    const int a_kb  = (lid >> 4) * 16;
    uint32_t qh[4][4];
#pragma unroll
    for (int ks = 0; ks < 4; ks++) {
        uint32_t off = swz((wid * 16 + a_row) * 128 + ks * 32 + a_kb);
        ldm4(qh[ks][0], qh[ks][1], qh[ks][2], qh[ks][3], sStage + off);
    }
    __syncthreads();

#pragma unroll
    for (int s = 0; s < 2; s++) {
        uint32_t sb = sStage + s * FSTAGE;
        const size_t koff = (size_t)s * FBN * DH_;
        cp_ftile(sb + 0,        Kg + koff, tid);
        cp_ftile(sb + FK_BYTES, Vg + koff, tid);
        CP_COMMIT();
    }

    const int b_row = (lid & 7) + ((lid >> 4) & 1) * 8;
    const int b_kb  = ((lid >> 3) & 1) * 16;
    const int v_row = (lid & 7) + ((lid >> 3) & 1) * 8;
    const int v_cb  = ((lid >> 4) & 1) * 16;

    float m_i[2] = {-1e30f, -1e30f};
    float l_i[2] = {0.f, 0.f};
    float out[8][4];
#pragma unroll
    for (int nn = 0; nn < 8; nn++)
#pragma unroll
        for (int r = 0; r < 4; r++) out[nn][r] = 0.f;

    int bufc = 0;
    int bufp = 2;
    for (int kt = 0; kt < nkt; kt++) {
        if (kt + 1 < nkt) { asm volatile("cp.async.wait_group 1;"); }
        else              { asm volatile("cp.async.wait_group 0;"); }
        __syncthreads();

        if (kt + 2 < nkt) {
            uint32_t sb2 = sStage + bufp * FSTAGE;
            const size_t koff = (size_t)(kt + 2) * FBN * DH_;
            cp_ftile(sb2 + 0,        Kg + koff, tid);
            cp_ftile(sb2 + FK_BYTES, Vg + koff, tid);
            CP_COMMIT();
        }

        const uint32_t sb = sStage + bufc * FSTAGE;
        const uint32_t sK = sb;
        const uint32_t sV = sb + FK_BYTES;

        float sc[16][4];
#pragma unroll
        for (int j = 0; j < 16; j++)
#pragma unroll
            for (int r = 0; r < 4; r++) sc[j][r] = 0.f;

#pragma unroll
        for (int jp = 0; jp < 8; jp++) {
#pragma unroll
            for (int ks = 0; ks < 4; ks++) {
                uint32_t off = swz((jp * 16 + b_row) * 128 + ks * 32 + b_kb);
                uint32_t kh[4];
                ldm4(kh[0], kh[1], kh[2], kh[3], sK + off);
                mma16816h(sc[2 * jp],     qh[ks], &kh[0]);
                mma16816h(sc[2 * jp + 1], qh[ks], &kh[2]);
            }
        }

        if (kt == nkt - 1) {
            const int k0g = kt * FBN;
            const int rbase = q0 + wid * 16 + (lid >> 2);
#pragma unroll
            for (int j = 0; j < 16; j++) {
                const int cbase = k0g + j * 8 + 2 * (lid & 3);
#pragma unroll
                for (int rr = 0; rr < 2; rr++) {
                    const int row = rbase + rr * 8;
                    if (cbase > row)     sc[j][2 * rr]     = -1e30f;
                    if (cbase + 1 > row) sc[j][2 * rr + 1] = -1e30f;
                }
            }
        }

        float alpha[2];
#pragma unroll
        for (int rr = 0; rr < 2; rr++) {
            float tm = -1e30f;
#pragma unroll
            for (int j = 0; j < 16; j++)
                tm = fmaxf(tm, fmaxf(sc[j][2 * rr], sc[j][2 * rr + 1]));
            tm = fmaxf(tm, __shfl_xor_sync(0xffffffffu, tm, 1));
            tm = fmaxf(tm, __shfl_xor_sync(0xffffffffu, tm, 2));
            const float mn = fmaxf(m_i[rr], tm);
            alpha[rr] = __expf(m_i[rr] - mn);
            m_i[rr] = mn;
            float rs = 0.f;
#pragma unroll
            for (int j = 0; j < 16; j++) {
                float p0 = __expf(sc[j][2 * rr]     - mn);
                float p1 = __expf(sc[j][2 * rr + 1] - mn);
                sc[j][2 * rr] = p0; sc[j][2 * rr + 1] = p1;
                rs += p0 + p1;
            }
            rs += __shfl_xor_sync(0xffffffffu, rs, 1);
            rs += __shfl_xor_sync(0xffffffffu, rs, 2);
            l_i[rr] = l_i[rr] * alpha[rr] + rs;
        }
#pragma unroll
        for (int nn = 0; nn < 8; nn++) {
            out[nn][0] *= alpha[0]; out[nn][1] *= alpha[0];
            out[nn][2] *= alpha[1]; out[nn][3] *= alpha[1];
        }

#pragma unroll
        for (int kk = 0; kk < 8; kk++) {
            uint32_t ph[4];
            ph[0] = packh2(sc[2 * kk][0],     sc[2 * kk][1]);
            ph[1] = packh2(sc[2 * kk][2],     sc[2 * kk][3]);
            ph[2] = packh2(sc[2 * kk + 1][0], sc[2 * kk + 1][1]);
            ph[3] = packh2(sc[2 * kk + 1][2], sc[2 * kk + 1][3]);
#pragma unroll
            for (int np = 0; np < 4; np++) {
                uint32_t off = swz((kk * 16 + v_row) * 128 + np * 32 + v_cb);
                uint32_t vh[4];
                ldm4t(vh[0], vh[1], vh[2], vh[3], sV + off);
                mma16816h(out[2 * np],     ph, &vh[0]);
                mma16816h(out[2 * np + 1], ph, &vh[2]);
            }
        }

        bufc = (bufc == 2) ? 0 : bufc + 1;
        bufp = (bufp == 2) ? 0 : bufp + 1;
    }

    const int b = bh >> 4;
    const int h = bh & 15;
    const float inv0 = 1.0f / l_i[0];
    const float inv1 = 1.0f / l_i[1];
#pragma unroll
    for (int nn = 0; nn < 8; nn++) {
        const int col = h * 64 + nn * 8 + 2 * (lid & 3);
#pragma unroll
        for (int rr = 0; rr < 2; rr++) {
            const int row = q0 + wid * 16 + (lid >> 2) + rr * 8;
            const float inv = rr ? inv1 : inv0;
            const size_t o = ((size_t)b * S_ + row) * D_ + col;
            *(uint32_t*)(g_Oh + o) =
                packh2(out[nn][2 * rr] * inv, out[nn][2 * rr + 1] * inv);
        }
    }
}

// ---------------------------------------------------------------------------
// Launch
// ---------------------------------------------------------------------------
extern "C" void kernel_launch(void* const* d_in, const int* in_sizes, int n_in,
                              void* d_out, int out_size)
{
    const float* x     = (const float*)d_in[0];
    const float* Wqkv  = (const float*)d_in[1];
    const float* bqkv  = (const float*)d_in[2];
    const float* Wproj = (const float*)d_in[3];
    const float* bproj = (const float*)d_in[4];
    float* out = (float*)d_out;

    cudaFuncSetAttribute(gemm_h<0>,
                         cudaFuncAttributeMaxDynamicSharedMemorySize, GEMM_DSMEM);
    cudaFuncSetAttribute(gemm_h<1>,
                         cudaFuncAttributeMaxDynamicSharedMemorySize, GEMM_DSMEM);
    cudaFuncSetAttribute(flash_mma_kernel,
                         cudaFuncAttributeMaxDynamicSharedMemorySize, FLASH_DSMEM);

    prep_kernel<<<6144, 256>>>(x, Wqkv, Wproj);

    gemm_h<0><<<dim3(N3D_ / 128, BS_ / 128), 256, GEMM_DSMEM>>>(bqkv, nullptr);

    flash_mma_kernel<<<dim3(S_ / FBM, B_ * H_), 256, FLASH_DSMEM>>>();

    gemm_h<1><<<dim3(D_ / 128, BS_ / 128), 256, GEMM_DSMEM>>>(bproj, out);
}